// round 10
// baseline (speedup 1.0000x reference)
#include <cuda_runtime.h>
#include <cuda_fp16.h>
#include <math.h>
#include <stdint.h>

// ---------------- problem constants ----------------
#define D_NODE 100
#define D_HID  300
#define NB     128
#define NT     512
#define NNODE  256
#define NLQ    256
#define ROWS_BT (NB*NT)     // 65536
#define ROWS_BN (NB*NNODE)  // 32768

#define KN_PAD 112
#define KH_PAD 304
#define HPAD   608          // hidden padded: [fwd 304 | bwd 304]
#define NCOLS  1824         // reordered gate cols

#define OUT_PATH   (NB*D_HID)
#define OUT_NODEF  ((long)ROWS_BN*D_HID)
#define OUT_TAIL_START (OUT_PATH + OUT_NODEF)

// ---------------- device scratch ----------------
__device__ __half g_nodes_h[(size_t)ROWS_BN * KN_PAD];
__device__ __half g_ctx_h[(size_t)NB * NLQ * KH_PAD];
__device__ __half g_T_h[(size_t)ROWS_BT * KN_PAD];
__device__ __half g_Wc_h[NCOLS * KN_PAD];
__device__ float  g_c_r[NCOLS];
__device__ float  g_bhn[HPAD];
__device__ __half g_Wnode_h[300 * KN_PAD];
__device__ __half g_Wout_h[300 * HPAD];
__device__ __half g_hidden_h[(size_t)ROWS_BT * HPAD];
__device__ __half g_hid_h[(size_t)ROWS_BT * KH_PAD];
__device__ float  g_alpha2[NB * 2 * NT];

// ---------------- PTX helpers ----------------
__device__ __forceinline__ uint32_t smem_to_u32(const void* p) {
    uint32_t a;
    asm("{ .reg .u64 t; cvta.to.shared.u64 t, %1; cvt.u32.u64 %0, t; }" : "=r"(a) : "l"(p));
    return a;
}
__device__ __forceinline__ void mma_f16(float* d, const uint32_t* a, const uint32_t* b) {
    asm volatile(
        "mma.sync.aligned.m16n8k16.row.col.f32.f16.f16.f32 "
        "{%0,%1,%2,%3}, {%4,%5,%6,%7}, {%8,%9}, {%0,%1,%2,%3};"
        : "+f"(d[0]), "+f"(d[1]), "+f"(d[2]), "+f"(d[3])
        : "r"(a[0]), "r"(a[1]), "r"(a[2]), "r"(a[3]), "r"(b[0]), "r"(b[1]));
}
__device__ __forceinline__ void cp_async16(uint32_t dst, const void* src, int src_size) {
    asm volatile("cp.async.cg.shared.global [%0], [%1], 16, %2;"
        :: "r"(dst), "l"(src), "r"(src_size) : "memory");
}
#define CP_COMMIT() asm volatile("cp.async.commit_group;" ::: "memory")
#define CP_WAIT(n)  asm volatile("cp.async.wait_group %0;" :: "n"(n) : "memory")

__device__ __forceinline__ float fexp2(float x) {
    float y; asm("ex2.approx.f32 %0, %1;" : "=f"(y) : "f"(x)); return y;
}
__device__ __forceinline__ float frcp(float x) {
    float y; asm("rcp.approx.f32 %0, %1;" : "=f"(y) : "f"(x)); return y;
}
#define LOG2E 1.4426950408889634f
__device__ __forceinline__ float fsigmoid(float x) { return frcp(1.f + fexp2(-LOG2E * x)); }
__device__ __forceinline__ float ftanh(float x)    { return 2.f * frcp(1.f + fexp2(-2.f * LOG2E * x)) - 1.f; }

// ================= generic fp16 mma GEMM (per-warp N-tail skip) =================
#define BM 128
#define BN 128
#define ASTR 40

template <bool OUT_HALF>
__global__ void __launch_bounds__(256, 2)
gemm_f16(const __half* __restrict__ A, long aBatch,
         const __half* __restrict__ W, long wBatch,
         void* __restrict__ Cv, long cBatch,
         int M, int N, int Npad, int K,
         const float* __restrict__ bias, int act_tanh)
{
    __shared__ __half sA[2][BM * ASTR];
    __shared__ __half sB[2][BN * ASTR];

    const int bz = blockIdx.z;
    A += (long)bz * aBatch; W += (long)bz * wBatch;

    const int tid  = threadIdx.x;
    const int warp = tid >> 5, lane = tid & 31;
    const int wm = warp & 3, wn = warp >> 2;
    const int g = lane >> 2, t = lane & 3;

    const int m0 = blockIdx.y * BM;
    const int n0 = blockIdx.x * BN;
    const int CH = (K + 31) >> 5;

    // per-warp valid tn count: skip mma for columns >= N (their acc stays 0)
    const int tnMax = min(8, max(0, (N - n0 - wn * 64 + 7) >> 3));

    const uint32_t sA32 = smem_to_u32(sA);
    const uint32_t sB32 = smem_to_u32(sB);

    float acc[2][8][4];
#pragma unroll
    for (int i = 0; i < 2; ++i)
#pragma unroll
        for (int j = 0; j < 8; ++j)
#pragma unroll
            for (int q = 0; q < 4; ++q) acc[i][j][q] = 0.f;

    auto issue = [&](int c) {
        const int s = c & 1;
        const int kb = c << 5;
        const uint32_t aB = sA32 + (uint32_t)s * (BM * ASTR * 2);
        const uint32_t bB = sB32 + (uint32_t)s * (BN * ASTR * 2);
#pragma unroll
        for (int i = 0; i < 2; ++i) {
            const int seg = tid + i * 256;
            const int row = seg >> 2, q = seg & 3;
            const int k = kb + q * 8;
            const int va = (k + 8 <= K);
            cp_async16(aB + (uint32_t)(row * (ASTR * 2) + q * 16),
                       va ? (const void*)(A + (long)(m0 + row) * K + k) : (const void*)A,
                       va ? 16 : 0);
            const int vb = va && (n0 + row < N);
            cp_async16(bB + (uint32_t)(row * (ASTR * 2) + q * 16),
                       vb ? (const void*)(W + (long)(n0 + row) * K + k) : (const void*)W,
                       vb ? 16 : 0);
        }
        CP_COMMIT();
    };

    issue(0);
    for (int c = 0; c < CH; ++c) {
        if (c + 1 < CH) { issue(c + 1); CP_WAIT(1); }
        else            { CP_WAIT(0); }
        __syncthreads();

        const __half* a_ = sA[c & 1];
        const __half* b_ = sB[c & 1];

        if (tnMax > 0) {
#pragma unroll
            for (int kk = 0; kk < 2; ++kk) {
                const int col = kk * 16 + 2 * t;
                uint32_t af[2][4], bf[8][2];
#pragma unroll
                for (int tm = 0; tm < 2; ++tm) {
                    const int r = wm * 32 + tm * 16 + g;
                    af[tm][0] = *(const uint32_t*)(a_ + r * ASTR + col);
                    af[tm][1] = *(const uint32_t*)(a_ + (r + 8) * ASTR + col);
                    af[tm][2] = *(const uint32_t*)(a_ + r * ASTR + col + 8);
                    af[tm][3] = *(const uint32_t*)(a_ + (r + 8) * ASTR + col + 8);
                }
#pragma unroll 8
                for (int tn = 0; tn < tnMax; ++tn) {
                    const int n = wn * 64 + tn * 8 + g;
                    bf[tn][0] = *(const uint32_t*)(b_ + n * ASTR + col);
                    bf[tn][1] = *(const uint32_t*)(b_ + n * ASTR + col + 8);
                }
#pragma unroll 8
                for (int tn = 0; tn < tnMax; ++tn)
#pragma unroll
                    for (int tm = 0; tm < 2; ++tm)
                        mma_f16(acc[tm][tn], af[tm], bf[tn]);
            }
        }
        __syncthreads();
    }

#pragma unroll
    for (int tm = 0; tm < 2; ++tm) {
        const int row = m0 + wm * 32 + tm * 16 + g;
#pragma unroll 8
        for (int tn = 0; tn < tnMax; ++tn) {
            const int n = n0 + wn * 64 + tn * 8 + 2 * t;
            if (OUT_HALF ? (n < Npad) : (n < N)) {
                float v0 = 0.f, v1 = 0.f, v2 = 0.f, v3 = 0.f;
                if (n < N) {
                    float b0 = 0.f, b1 = 0.f;
                    if (bias) { b0 = bias[n]; b1 = bias[n + 1]; }
                    v0 = acc[tm][tn][0] + b0;
                    v1 = acc[tm][tn][1] + b1;
                    v2 = acc[tm][tn][2] + b0;
                    v3 = acc[tm][tn][3] + b1;
                    if (act_tanh) { v0 = ftanh(v0); v1 = ftanh(v1); v2 = ftanh(v2); v3 = ftanh(v3); }
                }
                if constexpr (OUT_HALF) {
                    __half* C = (__half*)Cv + (long)bz * cBatch;
                    *(__half2*)(C + (size_t)row * Npad + n)       = __floats2half2_rn(v0, v1);
                    *(__half2*)(C + (size_t)(row + 8) * Npad + n) = __floats2half2_rn(v2, v3);
                } else {
                    float* C = (float*)Cv + (long)bz * cBatch;
                    *(float2*)(C + (size_t)row * N + n)       = make_float2(v0, v1);
                    *(float2*)(C + (size_t)(row + 8) * N + n) = make_float2(v2, v3);
                }
            }
        }
    }
}

// ================= gi-GEMM with fused GRU gates epilogue =================
#define GSTR 120
#define GA_HALVES (128 * GSTR)
#define GB_HALVES (96 * GSTR)
#define GATES_SMEM ((GA_HALVES + 2 * GB_HALVES) * 2)
#define GNT 19

__global__ void __launch_bounds__(256, 2) gemm_gates()
{
    extern __shared__ __half gsm[];
    __half* sA = gsm;
    __half* sB = gsm + GA_HALVES;

    const int tid  = threadIdx.x;
    const int warp = tid >> 5, lane = tid & 31;
    const int wm = warp & 3, wn = warp >> 2;
    const int g = lane >> 2, t = lane & 3;
    const int m0 = blockIdx.x * 128;

    const uint32_t sA32 = smem_to_u32(sA);
    const uint32_t sB32 = smem_to_u32(sB);

    auto issueB = [&](int nt) {
        const uint32_t bB = sB32 + (uint32_t)((nt & 1) * GB_HALVES * 2);
#pragma unroll
        for (int i = 0; i < 6; ++i) {
            const int seg = tid + i * 256;
            if (seg < 1344) {
                const int row = seg / 14, q = seg % 14;
                cp_async16(bB + (uint32_t)(row * (GSTR * 2) + q * 16),
                           g_Wc_h + (size_t)(nt * 96 + row) * KN_PAD + q * 8, 16);
            }
        }
        CP_COMMIT();
    };

#pragma unroll
    for (int i = 0; i < 7; ++i) {
        const int seg = tid + i * 256;
        const int row = seg / 14, q = seg % 14;
        cp_async16(sA32 + (uint32_t)(row * (GSTR * 2) + q * 16),
                   g_T_h + (size_t)(m0 + row) * KN_PAD + q * 8, 16);
    }
    {
        const uint32_t bB = sB32;
#pragma unroll
        for (int i = 0; i < 6; ++i) {
            const int seg = tid + i * 256;
            if (seg < 1344) {
                const int row = seg / 14, q = seg % 14;
                cp_async16(bB + (uint32_t)(row * (GSTR * 2) + q * 16),
                           g_Wc_h + (size_t)row * KN_PAD + q * 8, 16);
            }
        }
        CP_COMMIT();
    }
    issueB(1);

#pragma unroll 1
    for (int nt = 0; nt < GNT; ++nt) {
        CP_WAIT(1);
        __syncthreads();

        const __half* a_ = sA;
        const __half* b_ = sB + (nt & 1) * GB_HALVES;

        float acc[2][6][4];
#pragma unroll
        for (int i = 0; i < 2; ++i)
#pragma unroll
            for (int j = 0; j < 6; ++j)
#pragma unroll
                for (int q = 0; q < 4; ++q) acc[i][j][q] = 0.f;

#pragma unroll
        for (int kk = 0; kk < 7; ++kk) {
            const int col = kk * 16 + 2 * t;
            uint32_t af[2][4], bf[6][2];
#pragma unroll
            for (int tm = 0; tm < 2; ++tm) {
                const int r = wm * 32 + tm * 16 + g;
                af[tm][0] = *(const uint32_t*)(a_ + r * GSTR + col);
                af[tm][1] = *(const uint32_t*)(a_ + (r + 8) * GSTR + col);
                af[tm][2] = *(const uint32_t*)(a_ + r * GSTR + col + 8);
                af[tm][3] = *(const uint32_t*)(a_ + (r + 8) * GSTR + col + 8);
            }
#pragma unroll
            for (int tn = 0; tn < 6; ++tn) {
                const int n = wn * 48 + tn * 8 + g;
                bf[tn][0] = *(const uint32_t*)(b_ + n * GSTR + col);
                bf[tn][1] = *(const uint32_t*)(b_ + n * GSTR + col + 8);
            }
#pragma unroll
            for (int tm = 0; tm < 2; ++tm)
#pragma unroll
                for (int tn = 0; tn < 6; ++tn)
                    mma_f16(acc[tm][tn], af[tm], bf[tn]);
        }
        __syncthreads();
        if (nt + 2 < GNT) issueB(nt + 2);
        else              CP_COMMIT();

        const int n0 = nt * 96;
#pragma unroll
        for (int G = 0; G < 2; ++G) {
            const int colbase = n0 + wn * 48 + G * 24;
            const int d = (colbase >= 912);
            const int grp = (colbase - d * 912) / 24;
            const int j0 = grp * 8 + 2 * t;
            const float bh0 = g_bhn[d * 304 + j0];
            const float bh1 = g_bhn[d * 304 + j0 + 1];
            const float cr0 = g_c_r[colbase + 2 * t];
            const float cr1 = g_c_r[colbase + 2 * t + 1];
            const float cz0 = g_c_r[colbase + 8 + 2 * t];
            const float cz1 = g_c_r[colbase + 8 + 2 * t + 1];
            const float cn0 = g_c_r[colbase + 16 + 2 * t];
            const float cn1 = g_c_r[colbase + 16 + 2 * t + 1];
            const bool valid = (j0 < 300);
#pragma unroll
            for (int tm = 0; tm < 2; ++tm) {
#pragma unroll
                for (int rr = 0; rr < 2; ++rr) {
                    const int bt = m0 + wm * 32 + tm * 16 + g + rr * 8;
                    float h0 = 0.f, h1 = 0.f;
                    if (valid) {
                        const int q0 = rr * 2;
                        const float r0 = fsigmoid(acc[tm][3 * G + 0][q0]     + cr0);
                        const float r1 = fsigmoid(acc[tm][3 * G + 0][q0 + 1] + cr1);
                        const float z0 = fsigmoid(acc[tm][3 * G + 1][q0]     + cz0);
                        const float z1 = fsigmoid(acc[tm][3 * G + 1][q0 + 1] + cz1);
                        const float n0_ = acc[tm][3 * G + 2][q0]     + cn0;
                        const float n1_ = acc[tm][3 * G + 2][q0 + 1] + cn1;
                        h0 = (1.f - z0) * ftanh(n0_ + r0 * bh0);
                        h1 = (1.f - z1) * ftanh(n1_ + r1 * bh1);
                    }
                    *(__half2*)(g_hidden_h + (size_t)bt * HPAD + d * 304 + j0) =
                        __floats2half2_rn(h0, h1);
                }
            }
        }
        // no trailing __syncthreads: next iteration's CP_WAIT + __syncthreads
        // provides both the visibility and the anti-overwrite ordering.
    }
}

// ================= fused scores GEMM + softmax + alpha =================
#define SC_STR 520
#define ATTN_PIPE_HALVES (2 * (128 + 128) * ASTR)
#define ATTN_SC_HALVES   (128 * SC_STR)
#define ATTN_SMEM ((ATTN_PIPE_HALVES + ATTN_SC_HALVES) * 2 + 8 * NT * 4)

__global__ void __launch_bounds__(256, 1) attn_kernel()
{
    extern __shared__ __half asm_[];
    __half* sPipe = asm_;
    __half* ssc   = asm_ + ATTN_PIPE_HALVES;
    float*  part  = (float*)(asm_ + ATTN_PIPE_HALVES + ATTN_SC_HALVES);

    const int b  = blockIdx.x;
    const int lb = blockIdx.y;
    const __half* A = g_ctx_h + (size_t)(b * NLQ + lb * 128) * KH_PAD;
    const __half* B = g_hid_h + (size_t)b * NT * KH_PAD;

    const int tid  = threadIdx.x;
    const int warp = tid >> 5, lane = tid & 31;
    const int wm = warp & 3, wn = warp >> 2;
    const int g = lane >> 2, t = lane & 3;

    const uint32_t p32 = smem_to_u32(sPipe);
    const int CH = (KH_PAD + 31) >> 5;

#pragma unroll 1
    for (int nt = 0; nt < 4; ++nt) {
        const __half* Bt = B + (size_t)(nt * 128) * KH_PAD;

        auto issue = [&](int c) {
            const int s = c & 1;
            const int kb = c << 5;
            const uint32_t aB = p32 + (uint32_t)s * ((128 + 128) * ASTR * 2);
            const uint32_t bB = aB + (uint32_t)(128 * ASTR * 2);
#pragma unroll
            for (int i = 0; i < 2; ++i) {
                const int seg = tid + i * 256;
                const int row = seg >> 2, q = seg & 3;
                const int k = kb + q * 8;
                const int va = (k + 8 <= KH_PAD);
                cp_async16(aB + (uint32_t)(row * (ASTR * 2) + q * 16),
                           va ? (const void*)(A + (size_t)row * KH_PAD + k) : (const void*)A,
                           va ? 16 : 0);
                cp_async16(bB + (uint32_t)(row * (ASTR * 2) + q * 16),
                           va ? (const void*)(Bt + (size_t)row * KH_PAD + k) : (const void*)Bt,
                           va ? 16 : 0);
            }
            CP_COMMIT();
        };

        float acc[2][8][4];
#pragma unroll
        for (int i = 0; i < 2; ++i)
#pragma unroll
            for (int j = 0; j < 8; ++j)
#pragma unroll
                for (int q = 0; q < 4; ++q) acc[i][j][q] = 0.f;

        issue(0);
        for (int c = 0; c < CH; ++c) {
            if (c + 1 < CH) { issue(c + 1); CP_WAIT(1); }
            else            { CP_WAIT(0); }
            __syncthreads();

            const __half* a_ = sPipe + (size_t)(c & 1) * ((128 + 128) * ASTR);
            const __half* b_ = a_ + 128 * ASTR;

#pragma unroll
            for (int kk = 0; kk < 2; ++kk) {
                const int col = kk * 16 + 2 * t;
                uint32_t af[2][4], bf[8][2];
#pragma unroll
                for (int tm = 0; tm < 2; ++tm) {
                    const int r = wm * 32 + tm * 16 + g;
                    af[tm][0] = *(const uint32_t*)(a_ + r * ASTR + col);
                    af[tm][1] = *(const uint32_t*)(a_ + (r + 8) * ASTR + col);
                    af[tm][2] = *(const uint32_t*)(a_ + r * ASTR + col + 8);
                    af[tm][3] = *(const uint32_t*)(a_ + (r + 8) * ASTR + col + 8);
                }
#pragma unroll
                for (int tn = 0; tn < 8; ++tn) {
                    const int n = wn * 64 + tn * 8 + g;
                    bf[tn][0] = *(const uint32_t*)(b_ + n * ASTR + col);
                    bf[tn][1] = *(const uint32_t*)(b_ + n * ASTR + col + 8);
                }
#pragma unroll
                for (int tm = 0; tm < 2; ++tm)
#pragma unroll
                    for (int tn = 0; tn < 8; ++tn)
                        mma_f16(acc[tm][tn], af[tm], bf[tn]);
            }
            __syncthreads();
        }

#pragma unroll
        for (int tm = 0; tm < 2; ++tm) {
            const int row = wm * 32 + tm * 16 + g;
#pragma unroll
            for (int tn = 0; tn < 8; ++tn) {
                const int n = nt * 128 + wn * 64 + tn * 8 + 2 * t;
                *(__half2*)(ssc + (size_t)row * SC_STR + n) =
                    __floats2half2_rn(acc[tm][tn][0], acc[tm][tn][1]);
                *(__half2*)(ssc + (size_t)(row + 8) * SC_STR + n) =
                    __floats2half2_rn(acc[tm][tn][2], acc[tm][tn][3]);
            }
        }
        __syncthreads();
    }

    float pacc[16];
#pragma unroll
    for (int q = 0; q < 16; ++q) pacc[q] = 0.f;

#pragma unroll 1
    for (int i = 0; i < 16; ++i) {
        const int l = warp * 16 + i;
        const __half2* row2 = (const __half2*)(ssc + (size_t)l * SC_STR);
        float v[16], m = -1e30f;
#pragma unroll
        for (int q = 0; q < 8; ++q) {
            float2 f = __half22float2(row2[lane + 32 * q]);
            v[2 * q] = f.x; v[2 * q + 1] = f.y;
            m = fmaxf(m, fmaxf(f.x, f.y));
        }
#pragma unroll
        for (int o = 16; o; o >>= 1) m = fmaxf(m, __shfl_xor_sync(0xffffffffu, m, o));
        float e[16], s = 0.f;
#pragma unroll
        for (int q = 0; q < 16; ++q) { e[q] = fexp2(LOG2E * (v[q] - m)); s += e[q]; }
#pragma unroll
        for (int o = 16; o; o >>= 1) s += __shfl_xor_sync(0xffffffffu, s, o);
        const float rinv = frcp(s);
#pragma unroll
        for (int q = 0; q < 16; ++q) pacc[q] += e[q] * rinv;
    }
#pragma unroll
    for (int q = 0; q < 8; ++q) {
        const int c = 2 * (lane + 32 * q);
        part[warp * NT + c]     = pacc[2 * q];
        part[warp * NT + c + 1] = pacc[2 * q + 1];
    }
    __syncthreads();

#pragma unroll
    for (int h = 0; h < 2; ++h) {
        const int c = tid + h * 256;
        float s = 0.f;
#pragma unroll
        for (int w2 = 0; w2 < 8; ++w2) s += part[w2 * NT + c];
        g_alpha2[(b * 2 + lb) * NT + c] = s;
    }
}

// ---------------- unified fp32 -> fp16 conversions ----------------
#define CVT_N0 ((long)ROWS_BN * KN_PAD)
#define CVT_N1 ((long)NB * NLQ * KH_PAD)
#define CVT_N2 ((long)300 * KN_PAD)
#define CVT_N3 ((long)300 * HPAD)
#define CVT_TOTAL (CVT_N0 + CVT_N1 + CVT_N2 + CVT_N3)

__global__ void convert_all(const float* __restrict__ nodes,
                            const float* __restrict__ ctx,
                            const float* __restrict__ Wnode,
                            const float* __restrict__ Wout)
{
    for (long i = blockIdx.x * (long)blockDim.x + threadIdx.x; i < CVT_TOTAL;
         i += (long)gridDim.x * blockDim.x) {
        if (i < CVT_N0) {
            const long r = i / KN_PAD, k = i - r * KN_PAD;
            g_nodes_h[i] = __float2half((k < D_NODE) ? nodes[r * D_NODE + k] : 0.f);
        } else if (i < CVT_N0 + CVT_N1) {
            const long j = i - CVT_N0;
            const long r = j / KH_PAD, k = j - r * KH_PAD;
            g_ctx_h[j] = __float2half((k < D_HID) ? ctx[r * D_HID + k] : 0.f);
        } else if (i < CVT_N0 + CVT_N1 + CVT_N2) {
            const long j = i - CVT_N0 - CVT_N1;
            const long r = j / KN_PAD, k = j - r * KN_PAD;
            g_Wnode_h[j] = __float2half((k < D_NODE) ? Wnode[r * D_NODE + k] : 0.f);
        } else {
            const long j = i - CVT_N0 - CVT_N1 - CVT_N2;
            const long n = j / HPAD, k = j - n * HPAD;
            float v = 0.f;
            if (k < 300)                  v = Wout[n * 600 + k];
            else if (k >= 304 && k < 604) v = Wout[n * 600 + (k - 4)];
            g_Wout_h[j] = __float2half(v);
        }
    }
}

// ---------------- weight combine -> reordered Wc_h / c_r / bhn ----------------
#define CBJ 16
#define COMBINE_SMEM ((30000 + CBJ * 300) * 4)

__global__ void __launch_bounds__(256)
combine_kernel(const float* __restrict__ Wf, const float* __restrict__ bif,
               const float* __restrict__ bhf,
               const float* __restrict__ Wb, const float* __restrict__ bib,
               const float* __restrict__ bhb,
               const float* __restrict__ Wmean, const float* __restrict__ bmean)
{
    extern __shared__ float csm[];
    float* sW   = csm;
    float* srow = csm + 30000;

    const int j0 = blockIdx.x * CBJ;
    const int tid = threadIdx.x;

    for (int i = tid; i < 30000; i += 256) sW[i] = Wmean[i];
    for (int i = tid; i < CBJ * 300; i += 256) {
        const int jj = i / 300, dcol = i % 300;
        const int cnew = j0 + jj;
        const int d = (cnew >= 912);
        const int rem = cnew - d * 912;
        const int grp = rem / 24, gate = (rem % 24) >> 3, pos = rem & 7;
        const int h = grp * 8 + pos;
        float v = 0.f;
        if (h < 300) {
            const int src = gate * 300 + h;
            v = d ? Wb[src * 300 + dcol] : Wf[src * 300 + dcol];
        }
        srow[i] = v;
    }
    __syncthreads();

    for (int idx = tid; idx < CBJ * KN_PAD; idx += 256) {
        const int jj = idx / KN_PAD, k = idx % KN_PAD;
        const int cnew = j0 + jj;
        float s = 0.f;
        if (k < 100) {
            const float* wr = srow + jj * 300;
#pragma unroll 4
            for (int dd = 0; dd < 300; ++dd) s = fmaf(wr[dd], sW[dd * 100 + k], s);
        }
        g_Wc_h[(size_t)cnew * KN_PAD + k] = __float2half(s);
    }
    if (tid < CBJ) {
        const int cnew = j0 + tid;
        const int d = (cnew >= 912);
        const int rem = cnew - d * 912;
        const int grp = rem / 24, gate = (rem % 24) >> 3, pos = rem & 7;
        const int h = grp * 8 + pos;
        float s = 0.f;
        if (h < 300) {
            const int src = gate * 300 + h;
            const float* bih = d ? bib : bif;
            const float* bhh = d ? bhb : bhf;
            s = bih[src];
            const float* wr = srow + tid * 300;
            for (int dd = 0; dd < 300; ++dd) s = fmaf(wr[dd], bmean[dd], s);
            if (gate < 2) s += bhh[src];
            if (gate == 2) g_bhn[d * 304 + h] = bhh[600 + h];
        } else {
            if (gate == 2) g_bhn[d * 304 + h] = 0.f;
        }
        g_c_r[cnew] = s;
    }
}

// ---------------- per-triple averaged node vectors ----------------
__global__ void __launch_bounds__(224) tri_avg(const int* __restrict__ tri)
{
    const int r = threadIdx.x / 28, c = threadIdx.x % 28;
    const int bt = blockIdx.x * 8 + r;
    const int b = bt >> 9;
    const int hN = tri[bt * 3 + 0];
    const int tN = tri[bt * 3 + 2];
    const uint2 vh = ((const uint2*)(g_nodes_h + (size_t)(b * NNODE + hN) * KN_PAD))[c];
    const uint2 vt = ((const uint2*)(g_nodes_h + (size_t)(b * NNODE + tN) * KN_PAD))[c];
    const float2 hx = __half22float2(*(const __half2*)&vh.x);
    const float2 hy = __half22float2(*(const __half2*)&vh.y);
    const float2 tx = __half22float2(*(const __half2*)&vt.x);
    const float2 ty = __half22float2(*(const __half2*)&vt.y);
    __half2 o0 = __floats2half2_rn(0.5f * (hx.x + tx.x), 0.5f * (hx.y + tx.y));
    __half2 o1 = __floats2half2_rn(0.5f * (hy.x + ty.x), 0.5f * (hy.y + ty.y));
    uint2 o;
    o.x = *(uint32_t*)&o0;
    o.y = *(uint32_t*)&o1;
    ((uint2*)(g_T_h + (size_t)bt * KN_PAD))[c] = o;
}

// ---------------- rep = alpha @ hid_ ; layernorm (coalesced) ----------------
__global__ void __launch_bounds__(320) rep_ln_kernel(const float* __restrict__ gamma,
                                                     const float* __restrict__ beta,
                                                     float* __restrict__ out)
{
    const int b = blockIdx.x;
    __shared__ float sal[NT];
    __shared__ float redc[10][304];      // per-warp partial rep
    __shared__ float red[2][10];
    const int tid = threadIdx.x;
    const int w = tid >> 5, lane = tid & 31;

    for (int t = tid; t < NT; t += 320)
        sal[t] = g_alpha2[(b * 2) * NT + t] + g_alpha2[(b * 2 + 1) * NT + t];
    __syncthreads();

    // warp-per-row accumulation: lane owns cols lane+32q (coalesced fp16 loads)
    float acc10[10];
#pragma unroll
    for (int q = 0; q < 10; ++q) acc10[q] = 0.f;
    const __half* H = g_hid_h + (size_t)b * NT * KH_PAD;
    for (int t = w; t < NT; t += 10) {
        const float a = sal[t];
        const __half* row = H + (size_t)t * KH_PAD;
#pragma unroll
        for (int q = 0; q < 10; ++q) {
            const int c = lane + 32 * q;
            if (c < 300) acc10[q] = fmaf(a, __half2float(row[c]), acc10[q]);
        }
    }
#pragma unroll
    for (int q = 0; q < 10; ++q) {
        const int c = lane + 32 * q;
        if (c < 304) redc[w][c] = acc10[q];
    }
    __syncthreads();

    float acc = 0.f;
    if (tid < D_HID) {
#pragma unroll
        for (int w2 = 0; w2 < 10; ++w2) acc += redc[w2][tid];
    }
    float v1 = (tid < D_HID) ? acc : 0.f;
    float v2 = (tid < D_HID) ? acc * acc : 0.f;
#pragma unroll
    for (int o = 16; o; o >>= 1) {
        v1 += __shfl_xor_sync(0xffffffffu, v1, o);
        v2 += __shfl_xor_sync(0xffffffffu, v2, o);
    }
    if (lane == 0) { red[0][w] = v1; red[1][w] = v2; }
    __syncthreads();
    if (tid == 0) {
        float s1 = 0.f, s2 = 0.f;
        for (int w2 = 0; w2 < 10; ++w2) { s1 += red[0][w2]; s2 += red[1][w2]; }
        red[0][0] = s1 / (float)D_HID;
        red[1][0] = s2 / (float)D_HID;
    }
    __syncthreads();
    if (tid < D_HID) {
        float mu = red[0][0];
        float var = red[1][0] - mu * mu;
        out[b * D_HID + tid] = (acc - mu) * rsqrtf(var + 1e-5f) * gamma[tid] + beta[tid];
    }
}

__global__ void zero_tail_kernel(float* __restrict__ out, long start, long end)
{
    long i = start + (long)blockIdx.x * blockDim.x + threadIdx.x;
    if (i < end) out[i] = 0.f;
}

// ---------------- launch ----------------
extern "C" void kernel_launch(void* const* d_in, const int* in_sizes, int n_in,
                              void* d_out, int out_size)
{
    const int o = (in_sizes[3] == 1) ? 1 : 0;

    const float* nodes  = (const float*)d_in[0];
    const float* ctx    = (const float*)d_in[1];
    const int*   tri    = (const int*)d_in[2];
    const float* W_mean = (const float*)d_in[3 + o];
    const float* b_mean = (const float*)d_in[4 + o];
    const float* W_ih_f = (const float*)d_in[5 + o];
    const float* b_ih_f = (const float*)d_in[6 + o];
    const float* b_hh_f = (const float*)d_in[7 + o];
    const float* W_ih_b = (const float*)d_in[8 + o];
    const float* b_ih_b = (const float*)d_in[9 + o];
    const float* b_hh_b = (const float*)d_in[10 + o];
    const float* W_out  = (const float*)d_in[11 + o];
    const float* b_out  = (const float*)d_in[12 + o];
    const float* W_node = (const float*)d_in[13 + o];
    const float* b_node = (const float*)d_in[14 + o];
    const float* gamma  = (const float*)d_in[15 + o];
    const float* beta   = (const float*)d_in[16 + o];
    float* out = (float*)d_out;

    __half *pNodesH, *pWnodeH, *pWoutH, *pHiddenH, *pHidH;
    cudaGetSymbolAddress((void**)&pNodesH,  g_nodes_h);
    cudaGetSymbolAddress((void**)&pWnodeH,  g_Wnode_h);
    cudaGetSymbolAddress((void**)&pWoutH,   g_Wout_h);
    cudaGetSymbolAddress((void**)&pHiddenH, g_hidden_h);
    cudaGetSymbolAddress((void**)&pHidH,    g_hid_h);

    cudaFuncSetAttribute(combine_kernel, cudaFuncAttributeMaxDynamicSharedMemorySize, COMBINE_SMEM);
    cudaFuncSetAttribute(gemm_gates,     cudaFuncAttributeMaxDynamicSharedMemorySize, GATES_SMEM);
    cudaFuncSetAttribute(attn_kernel,    cudaFuncAttributeMaxDynamicSharedMemorySize, ATTN_SMEM);

    convert_all<<<8192, 256>>>(nodes, ctx, W_node, W_out);

    combine_kernel<<<NCOLS / CBJ, 256, COMBINE_SMEM>>>(
        W_ih_f, b_ih_f, b_hh_f, W_ih_b, b_ih_b, b_hh_b, W_mean, b_mean);

    tri_avg<<<ROWS_BT / 8, 224>>>(tri);

    gemm_gates<<<ROWS_BT / 128, 256, GATES_SMEM>>>();

    {
        dim3 grid((D_HID + BN - 1) / BN, ROWS_BN / BM, 1);
        gemm_f16<false><<<grid, 256>>>(pNodesH, 0, pWnodeH, 0, out + OUT_PATH, 0,
                                       ROWS_BN, D_HID, D_HID, KN_PAD, b_node, 0);
    }
    {
        dim3 grid((KH_PAD + BN - 1) / BN, ROWS_BT / BM, 1);
        gemm_f16<true><<<grid, 256>>>(pHiddenH, 0, pWoutH, 0, pHidH, 0,
                                      ROWS_BT, D_HID, KH_PAD, HPAD, b_out, 1);
    }
    attn_kernel<<<dim3(NB, 2), 256, ATTN_SMEM>>>();

    rep_ln_kernel<<<NB, 320>>>(gamma, beta, out);

    {
        long start = OUT_TAIL_START;
        long end = (long)out_size;
        if (end > start) {
            long n = end - start;
            int blocks = (int)((n + 255) / 256);
            zero_tail_kernel<<<blocks, 256>>>(out, start, end);
        }
    }
}

// round 11
// speedup vs baseline: 2.1818x; 2.1818x over previous
#include <cuda_runtime.h>
#include <cuda_fp16.h>
#include <math.h>
#include <stdint.h>

// ---------------- problem constants ----------------
#define D_NODE 100
#define D_HID  300
#define NB     128
#define NT     512
#define NNODE  256
#define NLQ    256
#define ROWS_BT (NB*NT)     // 65536
#define ROWS_BN (NB*NNODE)  // 32768

#define KN_PAD 112
#define KH_PAD 304
#define HPAD   608          // hidden padded: [fwd 304 | bwd 304]
#define NCOLS  1824         // reordered gate cols

#define OUT_PATH   (NB*D_HID)
#define OUT_NODEF  ((long)ROWS_BN*D_HID)
#define OUT_TAIL_START (OUT_PATH + OUT_NODEF)

// ---------------- device scratch ----------------
__device__ __half g_nodes_h[(size_t)ROWS_BN * KN_PAD];
__device__ __half g_ctx_h[(size_t)NB * NLQ * KH_PAD];
__device__ __half g_T_h[(size_t)ROWS_BT * KN_PAD];
__device__ __half g_Wc_h[NCOLS * KN_PAD];
__device__ float  g_c_r[NCOLS];
__device__ float  g_bhn[HPAD];
__device__ __half g_Wnode_h[300 * KN_PAD];
__device__ __half g_Wout_h[300 * HPAD];
__device__ __half g_hidden_h[(size_t)ROWS_BT * HPAD];
__device__ __half g_hid_h[(size_t)ROWS_BT * KH_PAD];
__device__ float  g_alpha2[NB * 2 * NT];

// ---------------- PTX helpers ----------------
__device__ __forceinline__ uint32_t smem_to_u32(const void* p) {
    uint32_t a;
    asm("{ .reg .u64 t; cvta.to.shared.u64 t, %1; cvt.u32.u64 %0, t; }" : "=r"(a) : "l"(p));
    return a;
}
__device__ __forceinline__ void mma_f16(float* d, const uint32_t* a, const uint32_t* b) {
    asm volatile(
        "mma.sync.aligned.m16n8k16.row.col.f32.f16.f16.f32 "
        "{%0,%1,%2,%3}, {%4,%5,%6,%7}, {%8,%9}, {%0,%1,%2,%3};"
        : "+f"(d[0]), "+f"(d[1]), "+f"(d[2]), "+f"(d[3])
        : "r"(a[0]), "r"(a[1]), "r"(a[2]), "r"(a[3]), "r"(b[0]), "r"(b[1]));
}
__device__ __forceinline__ void cp_async16(uint32_t dst, const void* src, int src_size) {
    asm volatile("cp.async.cg.shared.global [%0], [%1], 16, %2;"
        :: "r"(dst), "l"(src), "r"(src_size) : "memory");
}
#define CP_COMMIT() asm volatile("cp.async.commit_group;" ::: "memory")
#define CP_WAIT(n)  asm volatile("cp.async.wait_group %0;" :: "n"(n) : "memory")

__device__ __forceinline__ float fexp2(float x) {
    float y; asm("ex2.approx.f32 %0, %1;" : "=f"(y) : "f"(x)); return y;
}
__device__ __forceinline__ float frcp(float x) {
    float y; asm("rcp.approx.f32 %0, %1;" : "=f"(y) : "f"(x)); return y;
}
#define LOG2E 1.4426950408889634f
__device__ __forceinline__ float fsigmoid(float x) { return frcp(1.f + fexp2(-LOG2E * x)); }
__device__ __forceinline__ float ftanh(float x)    { return 2.f * frcp(1.f + fexp2(-2.f * LOG2E * x)) - 1.f; }

// ================= generic fp16 mma GEMM (R9 body: compile-time bounds) =================
#define BM 128
#define BN 128
#define ASTR 40

template <bool OUT_HALF>
__global__ void __launch_bounds__(256, 2)
gemm_f16(const __half* __restrict__ A, long aBatch,
         const __half* __restrict__ W, long wBatch,
         void* __restrict__ Cv, long cBatch,
         int M, int N, int Npad, int K,
         const float* __restrict__ bias, int act_tanh)
{
    __shared__ __half sA[2][BM * ASTR];
    __shared__ __half sB[2][BN * ASTR];

    const int bz = blockIdx.z;
    A += (long)bz * aBatch; W += (long)bz * wBatch;

    const int tid  = threadIdx.x;
    const int warp = tid >> 5, lane = tid & 31;
    const int wm = warp & 3, wn = warp >> 2;
    const int g = lane >> 2, t = lane & 3;

    const int m0 = blockIdx.y * BM;
    const int n0 = blockIdx.x * BN;
    const int CH = (K + 31) >> 5;

    const uint32_t sA32 = smem_to_u32(sA);
    const uint32_t sB32 = smem_to_u32(sB);

    float acc[2][8][4];
#pragma unroll
    for (int i = 0; i < 2; ++i)
#pragma unroll
        for (int j = 0; j < 8; ++j)
#pragma unroll
            for (int q = 0; q < 4; ++q) acc[i][j][q] = 0.f;

    auto issue = [&](int c) {
        const int s = c & 1;
        const int kb = c << 5;
        const uint32_t aB = sA32 + (uint32_t)s * (BM * ASTR * 2);
        const uint32_t bB = sB32 + (uint32_t)s * (BN * ASTR * 2);
#pragma unroll
        for (int i = 0; i < 2; ++i) {
            const int seg = tid + i * 256;
            const int row = seg >> 2, q = seg & 3;
            const int k = kb + q * 8;
            const int va = (k + 8 <= K);
            cp_async16(aB + (uint32_t)(row * (ASTR * 2) + q * 16),
                       va ? (const void*)(A + (long)(m0 + row) * K + k) : (const void*)A,
                       va ? 16 : 0);
            const int vb = va && (n0 + row < N);
            cp_async16(bB + (uint32_t)(row * (ASTR * 2) + q * 16),
                       vb ? (const void*)(W + (long)(n0 + row) * K + k) : (const void*)W,
                       vb ? 16 : 0);
        }
        CP_COMMIT();
    };

    issue(0);
    for (int c = 0; c < CH; ++c) {
        if (c + 1 < CH) { issue(c + 1); CP_WAIT(1); }
        else            { CP_WAIT(0); }
        __syncthreads();

        const __half* a_ = sA[c & 1];
        const __half* b_ = sB[c & 1];

#pragma unroll
        for (int kk = 0; kk < 2; ++kk) {
            const int col = kk * 16 + 2 * t;
            uint32_t af[2][4], bf[8][2];
#pragma unroll
            for (int tm = 0; tm < 2; ++tm) {
                const int r = wm * 32 + tm * 16 + g;
                af[tm][0] = *(const uint32_t*)(a_ + r * ASTR + col);
                af[tm][1] = *(const uint32_t*)(a_ + (r + 8) * ASTR + col);
                af[tm][2] = *(const uint32_t*)(a_ + r * ASTR + col + 8);
                af[tm][3] = *(const uint32_t*)(a_ + (r + 8) * ASTR + col + 8);
            }
#pragma unroll
            for (int tn = 0; tn < 8; ++tn) {
                const int n = wn * 64 + tn * 8 + g;
                bf[tn][0] = *(const uint32_t*)(b_ + n * ASTR + col);
                bf[tn][1] = *(const uint32_t*)(b_ + n * ASTR + col + 8);
            }
#pragma unroll
            for (int tm = 0; tm < 2; ++tm)
#pragma unroll
                for (int tn = 0; tn < 8; ++tn)
                    mma_f16(acc[tm][tn], af[tm], bf[tn]);
        }
        __syncthreads();
    }

#pragma unroll
    for (int tm = 0; tm < 2; ++tm) {
        const int row = m0 + wm * 32 + tm * 16 + g;
#pragma unroll
        for (int tn = 0; tn < 8; ++tn) {
            const int n = n0 + wn * 64 + tn * 8 + 2 * t;
            if (OUT_HALF ? (n < Npad) : (n < N)) {
                float v0 = 0.f, v1 = 0.f, v2 = 0.f, v3 = 0.f;
                if (n < N) {
                    float b0 = 0.f, b1 = 0.f;
                    if (bias) { b0 = bias[n]; b1 = bias[n + 1]; }
                    v0 = acc[tm][tn][0] + b0;
                    v1 = acc[tm][tn][1] + b1;
                    v2 = acc[tm][tn][2] + b0;
                    v3 = acc[tm][tn][3] + b1;
                    if (act_tanh) { v0 = ftanh(v0); v1 = ftanh(v1); v2 = ftanh(v2); v3 = ftanh(v3); }
                }
                if constexpr (OUT_HALF) {
                    __half* C = (__half*)Cv + (long)bz * cBatch;
                    *(__half2*)(C + (size_t)row * Npad + n)       = __floats2half2_rn(v0, v1);
                    *(__half2*)(C + (size_t)(row + 8) * Npad + n) = __floats2half2_rn(v2, v3);
                } else {
                    float* C = (float*)Cv + (long)bz * cBatch;
                    *(float2*)(C + (size_t)row * N + n)       = make_float2(v0, v1);
                    *(float2*)(C + (size_t)(row + 8) * N + n) = make_float2(v2, v3);
                }
            }
        }
    }
}

// ================= gi-GEMM with fused GRU gates epilogue =================
#define GSTR 120
#define GA_HALVES (128 * GSTR)
#define GB_HALVES (96 * GSTR)
#define GATES_SMEM ((GA_HALVES + 2 * GB_HALVES) * 2)
#define GNT 19

__global__ void __launch_bounds__(256, 2) gemm_gates()
{
    extern __shared__ __half gsm[];
    __half* sA = gsm;
    __half* sB = gsm + GA_HALVES;

    const int tid  = threadIdx.x;
    const int warp = tid >> 5, lane = tid & 31;
    const int wm = warp & 3, wn = warp >> 2;
    const int g = lane >> 2, t = lane & 3;
    const int m0 = blockIdx.x * 128;

    const uint32_t sA32 = smem_to_u32(sA);
    const uint32_t sB32 = smem_to_u32(sB);

    auto issueB = [&](int nt) {
        const uint32_t bB = sB32 + (uint32_t)((nt & 1) * GB_HALVES * 2);
#pragma unroll
        for (int i = 0; i < 6; ++i) {
            const int seg = tid + i * 256;
            if (seg < 1344) {
                const int row = seg / 14, q = seg % 14;
                cp_async16(bB + (uint32_t)(row * (GSTR * 2) + q * 16),
                           g_Wc_h + (size_t)(nt * 96 + row) * KN_PAD + q * 8, 16);
            }
        }
        CP_COMMIT();
    };

#pragma unroll
    for (int i = 0; i < 7; ++i) {
        const int seg = tid + i * 256;
        const int row = seg / 14, q = seg % 14;
        cp_async16(sA32 + (uint32_t)(row * (GSTR * 2) + q * 16),
                   g_T_h + (size_t)(m0 + row) * KN_PAD + q * 8, 16);
    }
    {
        const uint32_t bB = sB32;
#pragma unroll
        for (int i = 0; i < 6; ++i) {
            const int seg = tid + i * 256;
            if (seg < 1344) {
                const int row = seg / 14, q = seg % 14;
                cp_async16(bB + (uint32_t)(row * (GSTR * 2) + q * 16),
                           g_Wc_h + (size_t)row * KN_PAD + q * 8, 16);
            }
        }
        CP_COMMIT();
    }
    issueB(1);

#pragma unroll 1
    for (int nt = 0; nt < GNT; ++nt) {
        CP_WAIT(1);
        __syncthreads();

        const __half* a_ = sA;
        const __half* b_ = sB + (nt & 1) * GB_HALVES;

        float acc[2][6][4];
#pragma unroll
        for (int i = 0; i < 2; ++i)
#pragma unroll
            for (int j = 0; j < 6; ++j)
#pragma unroll
                for (int q = 0; q < 4; ++q) acc[i][j][q] = 0.f;

#pragma unroll
        for (int kk = 0; kk < 7; ++kk) {
            const int col = kk * 16 + 2 * t;
            uint32_t af[2][4], bf[6][2];
#pragma unroll
            for (int tm = 0; tm < 2; ++tm) {
                const int r = wm * 32 + tm * 16 + g;
                af[tm][0] = *(const uint32_t*)(a_ + r * GSTR + col);
                af[tm][1] = *(const uint32_t*)(a_ + (r + 8) * GSTR + col);
                af[tm][2] = *(const uint32_t*)(a_ + r * GSTR + col + 8);
                af[tm][3] = *(const uint32_t*)(a_ + (r + 8) * GSTR + col + 8);
            }
#pragma unroll
            for (int tn = 0; tn < 6; ++tn) {
                const int n = wn * 48 + tn * 8 + g;
                bf[tn][0] = *(const uint32_t*)(b_ + n * GSTR + col);
                bf[tn][1] = *(const uint32_t*)(b_ + n * GSTR + col + 8);
            }
#pragma unroll
            for (int tm = 0; tm < 2; ++tm)
#pragma unroll
                for (int tn = 0; tn < 6; ++tn)
                    mma_f16(acc[tm][tn], af[tm], bf[tn]);
        }
        __syncthreads();
        if (nt + 2 < GNT) issueB(nt + 2);
        else              CP_COMMIT();

        const int n0 = nt * 96;
#pragma unroll
        for (int G = 0; G < 2; ++G) {
            const int colbase = n0 + wn * 48 + G * 24;
            const int d = (colbase >= 912);
            const int grp = (colbase - d * 912) / 24;
            const int j0 = grp * 8 + 2 * t;
            const float bh0 = g_bhn[d * 304 + j0];
            const float bh1 = g_bhn[d * 304 + j0 + 1];
            const float cr0 = g_c_r[colbase + 2 * t];
            const float cr1 = g_c_r[colbase + 2 * t + 1];
            const float cz0 = g_c_r[colbase + 8 + 2 * t];
            const float cz1 = g_c_r[colbase + 8 + 2 * t + 1];
            const float cn0 = g_c_r[colbase + 16 + 2 * t];
            const float cn1 = g_c_r[colbase + 16 + 2 * t + 1];
            const bool valid = (j0 < 300);
#pragma unroll
            for (int tm = 0; tm < 2; ++tm) {
#pragma unroll
                for (int rr = 0; rr < 2; ++rr) {
                    const int bt = m0 + wm * 32 + tm * 16 + g + rr * 8;
                    float h0 = 0.f, h1 = 0.f;
                    if (valid) {
                        const int q0 = rr * 2;
                        const float r0 = fsigmoid(acc[tm][3 * G + 0][q0]     + cr0);
                        const float r1 = fsigmoid(acc[tm][3 * G + 0][q0 + 1] + cr1);
                        const float z0 = fsigmoid(acc[tm][3 * G + 1][q0]     + cz0);
                        const float z1 = fsigmoid(acc[tm][3 * G + 1][q0 + 1] + cz1);
                        const float n0_ = acc[tm][3 * G + 2][q0]     + cn0;
                        const float n1_ = acc[tm][3 * G + 2][q0 + 1] + cn1;
                        h0 = (1.f - z0) * ftanh(n0_ + r0 * bh0);
                        h1 = (1.f - z1) * ftanh(n1_ + r1 * bh1);
                    }
                    *(__half2*)(g_hidden_h + (size_t)bt * HPAD + d * 304 + j0) =
                        __floats2half2_rn(h0, h1);
                }
            }
        }
        // no trailing __syncthreads: next iteration's CP_WAIT + __syncthreads
        // provides both orderings (neutral-verified in R10's ncu).
    }
}

// ================= fused scores GEMM + softmax + alpha =================
#define SC_STR 520
#define ATTN_PIPE_HALVES (2 * (128 + 128) * ASTR)
#define ATTN_SC_HALVES   (128 * SC_STR)
#define ATTN_SMEM ((ATTN_PIPE_HALVES + ATTN_SC_HALVES) * 2 + 8 * NT * 4)

__global__ void __launch_bounds__(256, 1) attn_kernel()
{
    extern __shared__ __half asm_[];
    __half* sPipe = asm_;
    __half* ssc   = asm_ + ATTN_PIPE_HALVES;
    float*  part  = (float*)(asm_ + ATTN_PIPE_HALVES + ATTN_SC_HALVES);

    const int b  = blockIdx.x;
    const int lb = blockIdx.y;
    const __half* A = g_ctx_h + (size_t)(b * NLQ + lb * 128) * KH_PAD;
    const __half* B = g_hid_h + (size_t)b * NT * KH_PAD;

    const int tid  = threadIdx.x;
    const int warp = tid >> 5, lane = tid & 31;
    const int wm = warp & 3, wn = warp >> 2;
    const int g = lane >> 2, t = lane & 3;

    const uint32_t p32 = smem_to_u32(sPipe);
    const int CH = (KH_PAD + 31) >> 5;

#pragma unroll 1
    for (int nt = 0; nt < 4; ++nt) {
        const __half* Bt = B + (size_t)(nt * 128) * KH_PAD;

        auto issue = [&](int c) {
            const int s = c & 1;
            const int kb = c << 5;
            const uint32_t aB = p32 + (uint32_t)s * ((128 + 128) * ASTR * 2);
            const uint32_t bB = aB + (uint32_t)(128 * ASTR * 2);
#pragma unroll
            for (int i = 0; i < 2; ++i) {
                const int seg = tid + i * 256;
                const int row = seg >> 2, q = seg & 3;
                const int k = kb + q * 8;
                const int va = (k + 8 <= KH_PAD);
                cp_async16(aB + (uint32_t)(row * (ASTR * 2) + q * 16),
                           va ? (const void*)(A + (size_t)row * KH_PAD + k) : (const void*)A,
                           va ? 16 : 0);
                cp_async16(bB + (uint32_t)(row * (ASTR * 2) + q * 16),
                           va ? (const void*)(Bt + (size_t)row * KH_PAD + k) : (const void*)Bt,
                           va ? 16 : 0);
            }
            CP_COMMIT();
        };

        float acc[2][8][4];
#pragma unroll
        for (int i = 0; i < 2; ++i)
#pragma unroll
            for (int j = 0; j < 8; ++j)
#pragma unroll
                for (int q = 0; q < 4; ++q) acc[i][j][q] = 0.f;

        issue(0);
        for (int c = 0; c < CH; ++c) {
            if (c + 1 < CH) { issue(c + 1); CP_WAIT(1); }
            else            { CP_WAIT(0); }
            __syncthreads();

            const __half* a_ = sPipe + (size_t)(c & 1) * ((128 + 128) * ASTR);
            const __half* b_ = a_ + 128 * ASTR;

#pragma unroll
            for (int kk = 0; kk < 2; ++kk) {
                const int col = kk * 16 + 2 * t;
                uint32_t af[2][4], bf[8][2];
#pragma unroll
                for (int tm = 0; tm < 2; ++tm) {
                    const int r = wm * 32 + tm * 16 + g;
                    af[tm][0] = *(const uint32_t*)(a_ + r * ASTR + col);
                    af[tm][1] = *(const uint32_t*)(a_ + (r + 8) * ASTR + col);
                    af[tm][2] = *(const uint32_t*)(a_ + r * ASTR + col + 8);
                    af[tm][3] = *(const uint32_t*)(a_ + (r + 8) * ASTR + col + 8);
                }
#pragma unroll
                for (int tn = 0; tn < 8; ++tn) {
                    const int n = wn * 64 + tn * 8 + g;
                    bf[tn][0] = *(const uint32_t*)(b_ + n * ASTR + col);
                    bf[tn][1] = *(const uint32_t*)(b_ + n * ASTR + col + 8);
                }
#pragma unroll
                for (int tm = 0; tm < 2; ++tm)
#pragma unroll
                    for (int tn = 0; tn < 8; ++tn)
                        mma_f16(acc[tm][tn], af[tm], bf[tn]);
            }
            __syncthreads();
        }

#pragma unroll
        for (int tm = 0; tm < 2; ++tm) {
            const int row = wm * 32 + tm * 16 + g;
#pragma unroll
            for (int tn = 0; tn < 8; ++tn) {
                const int n = nt * 128 + wn * 64 + tn * 8 + 2 * t;
                *(__half2*)(ssc + (size_t)row * SC_STR + n) =
                    __floats2half2_rn(acc[tm][tn][0], acc[tm][tn][1]);
                *(__half2*)(ssc + (size_t)(row + 8) * SC_STR + n) =
                    __floats2half2_rn(acc[tm][tn][2], acc[tm][tn][3]);
            }
        }
        __syncthreads();
    }

    float pacc[16];
#pragma unroll
    for (int q = 0; q < 16; ++q) pacc[q] = 0.f;

#pragma unroll 1
    for (int i = 0; i < 16; ++i) {
        const int l = warp * 16 + i;
        const __half2* row2 = (const __half2*)(ssc + (size_t)l * SC_STR);
        float v[16], m = -1e30f;
#pragma unroll
        for (int q = 0; q < 8; ++q) {
            float2 f = __half22float2(row2[lane + 32 * q]);
            v[2 * q] = f.x; v[2 * q + 1] = f.y;
            m = fmaxf(m, fmaxf(f.x, f.y));
        }
#pragma unroll
        for (int o = 16; o; o >>= 1) m = fmaxf(m, __shfl_xor_sync(0xffffffffu, m, o));
        float e[16], s = 0.f;
#pragma unroll
        for (int q = 0; q < 16; ++q) { e[q] = fexp2(LOG2E * (v[q] - m)); s += e[q]; }
#pragma unroll
        for (int o = 16; o; o >>= 1) s += __shfl_xor_sync(0xffffffffu, s, o);
        const float rinv = frcp(s);
#pragma unroll
        for (int q = 0; q < 16; ++q) pacc[q] += e[q] * rinv;
    }
#pragma unroll
    for (int q = 0; q < 8; ++q) {
        const int c = 2 * (lane + 32 * q);
        part[warp * NT + c]     = pacc[2 * q];
        part[warp * NT + c + 1] = pacc[2 * q + 1];
    }
    __syncthreads();

#pragma unroll
    for (int h = 0; h < 2; ++h) {
        const int c = tid + h * 256;
        float s = 0.f;
#pragma unroll
        for (int w2 = 0; w2 < 8; ++w2) s += part[w2 * NT + c];
        g_alpha2[(b * 2 + lb) * NT + c] = s;
    }
}

// ---------------- unified fp32 -> fp16 conversions ----------------
#define CVT_N0 ((long)ROWS_BN * KN_PAD)
#define CVT_N1 ((long)NB * NLQ * KH_PAD)
#define CVT_N2 ((long)300 * KN_PAD)
#define CVT_N3 ((long)300 * HPAD)
#define CVT_TOTAL (CVT_N0 + CVT_N1 + CVT_N2 + CVT_N3)

__global__ void convert_all(const float* __restrict__ nodes,
                            const float* __restrict__ ctx,
                            const float* __restrict__ Wnode,
                            const float* __restrict__ Wout)
{
    for (long i = blockIdx.x * (long)blockDim.x + threadIdx.x; i < CVT_TOTAL;
         i += (long)gridDim.x * blockDim.x) {
        if (i < CVT_N0) {
            const long r = i / KN_PAD, k = i - r * KN_PAD;
            g_nodes_h[i] = __float2half((k < D_NODE) ? nodes[r * D_NODE + k] : 0.f);
        } else if (i < CVT_N0 + CVT_N1) {
            const long j = i - CVT_N0;
            const long r = j / KH_PAD, k = j - r * KH_PAD;
            g_ctx_h[j] = __float2half((k < D_HID) ? ctx[r * D_HID + k] : 0.f);
        } else if (i < CVT_N0 + CVT_N1 + CVT_N2) {
            const long j = i - CVT_N0 - CVT_N1;
            const long r = j / KN_PAD, k = j - r * KN_PAD;
            g_Wnode_h[j] = __float2half((k < D_NODE) ? Wnode[r * D_NODE + k] : 0.f);
        } else {
            const long j = i - CVT_N0 - CVT_N1 - CVT_N2;
            const long n = j / HPAD, k = j - n * HPAD;
            float v = 0.f;
            if (k < 300)                  v = Wout[n * 600 + k];
            else if (k >= 304 && k < 604) v = Wout[n * 600 + (k - 4)];
            g_Wout_h[j] = __float2half(v);
        }
    }
}

// ---------------- weight combine -> reordered Wc_h / c_r / bhn ----------------
#define CBJ 16
#define COMBINE_SMEM ((30000 + CBJ * 300) * 4)

__global__ void __launch_bounds__(256)
combine_kernel(const float* __restrict__ Wf, const float* __restrict__ bif,
               const float* __restrict__ bhf,
               const float* __restrict__ Wb, const float* __restrict__ bib,
               const float* __restrict__ bhb,
               const float* __restrict__ Wmean, const float* __restrict__ bmean)
{
    extern __shared__ float csm[];
    float* sW   = csm;
    float* srow = csm + 30000;

    const int j0 = blockIdx.x * CBJ;
    const int tid = threadIdx.x;

    for (int i = tid; i < 30000; i += 256) sW[i] = Wmean[i];
    for (int i = tid; i < CBJ * 300; i += 256) {
        const int jj = i / 300, dcol = i % 300;
        const int cnew = j0 + jj;
        const int d = (cnew >= 912);
        const int rem = cnew - d * 912;
        const int grp = rem / 24, gate = (rem % 24) >> 3, pos = rem & 7;
        const int h = grp * 8 + pos;
        float v = 0.f;
        if (h < 300) {
            const int src = gate * 300 + h;
            v = d ? Wb[src * 300 + dcol] : Wf[src * 300 + dcol];
        }
        srow[i] = v;
    }
    __syncthreads();

    for (int idx = tid; idx < CBJ * KN_PAD; idx += 256) {
        const int jj = idx / KN_PAD, k = idx % KN_PAD;
        const int cnew = j0 + jj;
        float s = 0.f;
        if (k < 100) {
            const float* wr = srow + jj * 300;
#pragma unroll 4
            for (int dd = 0; dd < 300; ++dd) s = fmaf(wr[dd], sW[dd * 100 + k], s);
        }
        g_Wc_h[(size_t)cnew * KN_PAD + k] = __float2half(s);
    }
    if (tid < CBJ) {
        const int cnew = j0 + tid;
        const int d = (cnew >= 912);
        const int rem = cnew - d * 912;
        const int grp = rem / 24, gate = (rem % 24) >> 3, pos = rem & 7;
        const int h = grp * 8 + pos;
        float s = 0.f;
        if (h < 300) {
            const int src = gate * 300 + h;
            const float* bih = d ? bib : bif;
            const float* bhh = d ? bhb : bhf;
            s = bih[src];
            const float* wr = srow + tid * 300;
            for (int dd = 0; dd < 300; ++dd) s = fmaf(wr[dd], bmean[dd], s);
            if (gate < 2) s += bhh[src];
            if (gate == 2) g_bhn[d * 304 + h] = bhh[600 + h];
        } else {
            if (gate == 2) g_bhn[d * 304 + h] = 0.f;
        }
        g_c_r[cnew] = s;
    }
}

// ---------------- per-triple averaged node vectors ----------------
__global__ void __launch_bounds__(224) tri_avg(const int* __restrict__ tri)
{
    const int r = threadIdx.x / 28, c = threadIdx.x % 28;
    const int bt = blockIdx.x * 8 + r;
    const int b = bt >> 9;
    const int hN = tri[bt * 3 + 0];
    const int tN = tri[bt * 3 + 2];
    const uint2 vh = ((const uint2*)(g_nodes_h + (size_t)(b * NNODE + hN) * KN_PAD))[c];
    const uint2 vt = ((const uint2*)(g_nodes_h + (size_t)(b * NNODE + tN) * KN_PAD))[c];
    const float2 hx = __half22float2(*(const __half2*)&vh.x);
    const float2 hy = __half22float2(*(const __half2*)&vh.y);
    const float2 tx = __half22float2(*(const __half2*)&vt.x);
    const float2 ty = __half22float2(*(const __half2*)&vt.y);
    __half2 o0 = __floats2half2_rn(0.5f * (hx.x + tx.x), 0.5f * (hx.y + tx.y));
    __half2 o1 = __floats2half2_rn(0.5f * (hy.x + ty.x), 0.5f * (hy.y + ty.y));
    uint2 o;
    o.x = *(uint32_t*)&o0;
    o.y = *(uint32_t*)&o1;
    ((uint2*)(g_T_h + (size_t)bt * KN_PAD))[c] = o;
}

// ---------------- rep = alpha @ hid_ ; layernorm (coalesced) ----------------
__global__ void __launch_bounds__(320) rep_ln_kernel(const float* __restrict__ gamma,
                                                     const float* __restrict__ beta,
                                                     float* __restrict__ out)
{
    const int b = blockIdx.x;
    __shared__ float sal[NT];
    __shared__ float redc[10][304];
    __shared__ float red[2][10];
    const int tid = threadIdx.x;
    const int w = tid >> 5, lane = tid & 31;

    for (int t = tid; t < NT; t += 320)
        sal[t] = g_alpha2[(b * 2) * NT + t] + g_alpha2[(b * 2 + 1) * NT + t];
    __syncthreads();

    float acc10[10];
#pragma unroll
    for (int q = 0; q < 10; ++q) acc10[q] = 0.f;
    const __half* H = g_hid_h + (size_t)b * NT * KH_PAD;
    for (int t = w; t < NT; t += 10) {
        const float a = sal[t];
        const __half* row = H + (size_t)t * KH_PAD;
#pragma unroll
        for (int q = 0; q < 10; ++q) {
            const int c = lane + 32 * q;
            if (c < 300) acc10[q] = fmaf(a, __half2float(row[c]), acc10[q]);
        }
    }
#pragma unroll
    for (int q = 0; q < 10; ++q) {
        const int c = lane + 32 * q;
        if (c < 304) redc[w][c] = acc10[q];
    }
    __syncthreads();

    float acc = 0.f;
    if (tid < D_HID) {
#pragma unroll
        for (int w2 = 0; w2 < 10; ++w2) acc += redc[w2][tid];
    }
    float v1 = (tid < D_HID) ? acc : 0.f;
    float v2 = (tid < D_HID) ? acc * acc : 0.f;
#pragma unroll
    for (int o = 16; o; o >>= 1) {
        v1 += __shfl_xor_sync(0xffffffffu, v1, o);
        v2 += __shfl_xor_sync(0xffffffffu, v2, o);
    }
    if (lane == 0) { red[0][w] = v1; red[1][w] = v2; }
    __syncthreads();
    if (tid == 0) {
        float s1 = 0.f, s2 = 0.f;
        for (int w2 = 0; w2 < 10; ++w2) { s1 += red[0][w2]; s2 += red[1][w2]; }
        red[0][0] = s1 / (float)D_HID;
        red[1][0] = s2 / (float)D_HID;
    }
    __syncthreads();
    if (tid < D_HID) {
        float mu = red[0][0];
        float var = red[1][0] - mu * mu;
        out[b * D_HID + tid] = (acc - mu) * rsqrtf(var + 1e-5f) * gamma[tid] + beta[tid];
    }
}

__global__ void zero_tail_kernel(float* __restrict__ out, long start, long end)
{
    long i = start + (long)blockIdx.x * blockDim.x + threadIdx.x;
    if (i < end) out[i] = 0.f;
}

// ---------------- launch ----------------
extern "C" void kernel_launch(void* const* d_in, const int* in_sizes, int n_in,
                              void* d_out, int out_size)
{
    const int o = (in_sizes[3] == 1) ? 1 : 0;

    const float* nodes  = (const float*)d_in[0];
    const float* ctx    = (const float*)d_in[1];
    const int*   tri    = (const int*)d_in[2];
    const float* W_mean = (const float*)d_in[3 + o];
    const float* b_mean = (const float*)d_in[4 + o];
    const float* W_ih_f = (const float*)d_in[5 + o];
    const float* b_ih_f = (const float*)d_in[6 + o];
    const float* b_hh_f = (const float*)d_in[7 + o];
    const float* W_ih_b = (const float*)d_in[8 + o];
    const float* b_ih_b = (const float*)d_in[9 + o];
    const float* b_hh_b = (const float*)d_in[10 + o];
    const float* W_out  = (const float*)d_in[11 + o];
    const float* b_out  = (const float*)d_in[12 + o];
    const float* W_node = (const float*)d_in[13 + o];
    const float* b_node = (const float*)d_in[14 + o];
    const float* gamma  = (const float*)d_in[15 + o];
    const float* beta   = (const float*)d_in[16 + o];
    float* out = (float*)d_out;

    __half *pNodesH, *pWnodeH, *pWoutH, *pHiddenH, *pHidH;
    cudaGetSymbolAddress((void**)&pNodesH,  g_nodes_h);
    cudaGetSymbolAddress((void**)&pWnodeH,  g_Wnode_h);
    cudaGetSymbolAddress((void**)&pWoutH,   g_Wout_h);
    cudaGetSymbolAddress((void**)&pHiddenH, g_hidden_h);
    cudaGetSymbolAddress((void**)&pHidH,    g_hid_h);

    cudaFuncSetAttribute(combine_kernel, cudaFuncAttributeMaxDynamicSharedMemorySize, COMBINE_SMEM);
    cudaFuncSetAttribute(gemm_gates,     cudaFuncAttributeMaxDynamicSharedMemorySize, GATES_SMEM);
    cudaFuncSetAttribute(attn_kernel,    cudaFuncAttributeMaxDynamicSharedMemorySize, ATTN_SMEM);

    convert_all<<<8192, 256>>>(nodes, ctx, W_node, W_out);

    combine_kernel<<<NCOLS / CBJ, 256, COMBINE_SMEM>>>(
        W_ih_f, b_ih_f, b_hh_f, W_ih_b, b_ih_b, b_hh_b, W_mean, b_mean);

    tri_avg<<<ROWS_BT / 8, 224>>>(tri);

    gemm_gates<<<ROWS_BT / 128, 256, GATES_SMEM>>>();

    {
        dim3 grid((D_HID + BN - 1) / BN, ROWS_BN / BM, 1);
        gemm_f16<false><<<grid, 256>>>(pNodesH, 0, pWnodeH, 0, out + OUT_PATH, 0,
                                       ROWS_BN, D_HID, D_HID, KN_PAD, b_node, 0);
    }
    {
        dim3 grid((KH_PAD + BN - 1) / BN, ROWS_BT / BM, 1);
        gemm_f16<true><<<grid, 256>>>(pHiddenH, 0, pWoutH, 0, pHidH, 0,
                                      ROWS_BT, D_HID, KH_PAD, HPAD, b_out, 1);
    }
    attn_kernel<<<dim3(NB, 2), 256, ATTN_SMEM>>>();

    rep_ln_kernel<<<NB, 320>>>(gamma, beta, out);

    {
        long start = OUT_TAIL_START;
        long end = (long)out_size;
        if (end > start) {
            long n = end - start;
            int blocks = (int)((n + 255) / 256);
            zero_tail_kernel<<<blocks, 256>>>(out, start, end);
        }
    }
}

// round 12
// speedup vs baseline: 2.2305x; 1.0223x over previous
#include <cuda_runtime.h>
#include <cuda_fp16.h>
#include <math.h>
#include <stdint.h>

// ---------------- problem constants ----------------
#define D_NODE 100
#define D_HID  300
#define NB     128
#define NT     512
#define NNODE  256
#define NLQ    256
#define ROWS_BT (NB*NT)     // 65536
#define ROWS_BN (NB*NNODE)  // 32768

#define KN_PAD 112
#define KH_PAD 304
#define HPAD   608          // hidden padded: [fwd 304 | bwd 304]
#define NCOLS  1824         // reordered gate cols

#define OUT_PATH   (NB*D_HID)
#define OUT_NODEF  ((long)ROWS_BN*D_HID)
#define OUT_TAIL_START (OUT_PATH + OUT_NODEF)

// ---------------- device scratch ----------------
__device__ __half g_nodes_h[(size_t)ROWS_BN * KN_PAD];
__device__ __half g_ctx_h[(size_t)NB * NLQ * KH_PAD];
__device__ __half g_T_h[(size_t)ROWS_BT * KN_PAD];
__device__ __half g_Wc_h[NCOLS * KN_PAD];
__device__ float  g_c_r[NCOLS];
__device__ float  g_bhn[HPAD];
__device__ __half g_Wnode_h[300 * KN_PAD];
__device__ __half g_Wout_h[300 * HPAD];
__device__ __half g_hidden_h[(size_t)ROWS_BT * HPAD];
__device__ __half g_hid_h[(size_t)ROWS_BT * KH_PAD];
__device__ float  g_alpha2[NB * 2 * NT];

// ---------------- PTX helpers ----------------
__device__ __forceinline__ uint32_t smem_to_u32(const void* p) {
    uint32_t a;
    asm("{ .reg .u64 t; cvta.to.shared.u64 t, %1; cvt.u32.u64 %0, t; }" : "=r"(a) : "l"(p));
    return a;
}
__device__ __forceinline__ void mma_f16(float* d, const uint32_t* a, const uint32_t* b) {
    asm volatile(
        "mma.sync.aligned.m16n8k16.row.col.f32.f16.f16.f32 "
        "{%0,%1,%2,%3}, {%4,%5,%6,%7}, {%8,%9}, {%0,%1,%2,%3};"
        : "+f"(d[0]), "+f"(d[1]), "+f"(d[2]), "+f"(d[3])
        : "r"(a[0]), "r"(a[1]), "r"(a[2]), "r"(a[3]), "r"(b[0]), "r"(b[1]));
}
__device__ __forceinline__ void cp_async16(uint32_t dst, const void* src, int src_size) {
    asm volatile("cp.async.cg.shared.global [%0], [%1], 16, %2;"
        :: "r"(dst), "l"(src), "r"(src_size) : "memory");
}
#define CP_COMMIT() asm volatile("cp.async.commit_group;" ::: "memory")
#define CP_WAIT(n)  asm volatile("cp.async.wait_group %0;" :: "n"(n) : "memory")

__device__ __forceinline__ float fexp2(float x) {
    float y; asm("ex2.approx.f32 %0, %1;" : "=f"(y) : "f"(x)); return y;
}
__device__ __forceinline__ float frcp(float x) {
    float y; asm("rcp.approx.f32 %0, %1;" : "=f"(y) : "f"(x)); return y;
}
#define LOG2E 1.4426950408889634f
__device__ __forceinline__ float fsigmoid(float x) { return frcp(1.f + fexp2(-LOG2E * x)); }
__device__ __forceinline__ float ftanh(float x)    { return 2.f * frcp(1.f + fexp2(-2.f * LOG2E * x)) - 1.f; }

// ================= generic fp16 mma GEMM (compile-time warp-width TNW) =================
// Block covers TNW*16 cols starting at nbase + blockIdx.x * (TNW*16).
// TNW=8: identical to the proven R9 kernel. TNW=3: 48-col tail block.
#define BM 128
#define ASTR 40

template <bool OUT_HALF, int TNW>
__global__ void __launch_bounds__(256, 2)
gemm_f16(const __half* __restrict__ A, long aBatch,
         const __half* __restrict__ W, long wBatch,
         void* __restrict__ Cv, long cBatch,
         int M, int N, int Npad, int K,
         const float* __restrict__ bias, int act_tanh, int nbase)
{
    constexpr int BNE = TNW * 16;           // block n-extent
    __shared__ __half sA[2][BM * ASTR];
    __shared__ __half sB[2][BM * ASTR];     // (over-sized for TNW<8; fine)

    const int bz = blockIdx.z;
    A += (long)bz * aBatch; W += (long)bz * wBatch;

    const int tid  = threadIdx.x;
    const int warp = tid >> 5, lane = tid & 31;
    const int wm = warp & 3, wn = warp >> 2;
    const int g = lane >> 2, t = lane & 3;

    const int m0 = blockIdx.y * BM;
    const int n0 = nbase + blockIdx.x * BNE;
    const int CH = (K + 31) >> 5;

    const uint32_t sA32 = smem_to_u32(sA);
    const uint32_t sB32 = smem_to_u32(sB);

    float acc[2][TNW][4];
#pragma unroll
    for (int i = 0; i < 2; ++i)
#pragma unroll
        for (int j = 0; j < TNW; ++j)
#pragma unroll
            for (int q = 0; q < 4; ++q) acc[i][j][q] = 0.f;

    auto issue = [&](int c) {
        const int s = c & 1;
        const int kb = c << 5;
        const uint32_t aB = sA32 + (uint32_t)s * (BM * ASTR * 2);
        const uint32_t bB = sB32 + (uint32_t)s * (BM * ASTR * 2);
#pragma unroll
        for (int i = 0; i < 2; ++i) {
            const int seg = tid + i * 256;
            const int row = seg >> 2, q = seg & 3;
            const int k = kb + q * 8;
            const int va = (k + 8 <= K);
            cp_async16(aB + (uint32_t)(row * (ASTR * 2) + q * 16),
                       va ? (const void*)(A + (long)(m0 + row) * K + k) : (const void*)A,
                       va ? 16 : 0);
            const int vb = va && (row < BNE) && (n0 + row < N);
            cp_async16(bB + (uint32_t)(row * (ASTR * 2) + q * 16),
                       vb ? (const void*)(W + (long)(n0 + row) * K + k) : (const void*)W,
                       vb ? 16 : 0);
        }
        CP_COMMIT();
    };

    issue(0);
    for (int c = 0; c < CH; ++c) {
        if (c + 1 < CH) { issue(c + 1); CP_WAIT(1); }
        else            { CP_WAIT(0); }
        __syncthreads();

        const __half* a_ = sA[c & 1];
        const __half* b_ = sB[c & 1];

#pragma unroll
        for (int kk = 0; kk < 2; ++kk) {
            const int col = kk * 16 + 2 * t;
            uint32_t af[2][4], bf[TNW][2];
#pragma unroll
            for (int tm = 0; tm < 2; ++tm) {
                const int r = wm * 32 + tm * 16 + g;
                af[tm][0] = *(const uint32_t*)(a_ + r * ASTR + col);
                af[tm][1] = *(const uint32_t*)(a_ + (r + 8) * ASTR + col);
                af[tm][2] = *(const uint32_t*)(a_ + r * ASTR + col + 8);
                af[tm][3] = *(const uint32_t*)(a_ + (r + 8) * ASTR + col + 8);
            }
#pragma unroll
            for (int tn = 0; tn < TNW; ++tn) {
                const int n = wn * (TNW * 8) + tn * 8 + g;
                bf[tn][0] = *(const uint32_t*)(b_ + n * ASTR + col);
                bf[tn][1] = *(const uint32_t*)(b_ + n * ASTR + col + 8);
            }
#pragma unroll
            for (int tm = 0; tm < 2; ++tm)
#pragma unroll
                for (int tn = 0; tn < TNW; ++tn)
                    mma_f16(acc[tm][tn], af[tm], bf[tn]);
        }
        __syncthreads();
    }

#pragma unroll
    for (int tm = 0; tm < 2; ++tm) {
        const int row = m0 + wm * 32 + tm * 16 + g;
#pragma unroll
        for (int tn = 0; tn < TNW; ++tn) {
            const int n = n0 + wn * (TNW * 8) + tn * 8 + 2 * t;
            if (OUT_HALF ? (n < Npad) : (n < N)) {
                float v0 = 0.f, v1 = 0.f, v2 = 0.f, v3 = 0.f;
                if (n < N) {
                    float b0 = 0.f, b1 = 0.f;
                    if (bias) { b0 = bias[n]; b1 = bias[n + 1]; }
                    v0 = acc[tm][tn][0] + b0;
                    v1 = acc[tm][tn][1] + b1;
                    v2 = acc[tm][tn][2] + b0;
                    v3 = acc[tm][tn][3] + b1;
                    if (act_tanh) { v0 = ftanh(v0); v1 = ftanh(v1); v2 = ftanh(v2); v3 = ftanh(v3); }
                }
                if constexpr (OUT_HALF) {
                    __half* C = (__half*)Cv + (long)bz * cBatch;
                    *(__half2*)(C + (size_t)row * Npad + n)       = __floats2half2_rn(v0, v1);
                    *(__half2*)(C + (size_t)(row + 8) * Npad + n) = __floats2half2_rn(v2, v3);
                } else {
                    float* C = (float*)Cv + (long)bz * cBatch;
                    *(float2*)(C + (size_t)row * N + n)       = make_float2(v0, v1);
                    *(float2*)(C + (size_t)(row + 8) * N + n) = make_float2(v2, v3);
                }
            }
        }
    }
}

// ================= gi-GEMM with fused GRU gates epilogue =================
#define GSTR 120
#define GA_HALVES (128 * GSTR)
#define GB_HALVES (96 * GSTR)
#define GATES_SMEM ((GA_HALVES + 2 * GB_HALVES) * 2)
#define GNT 19

__global__ void __launch_bounds__(256, 2) gemm_gates()
{
    extern __shared__ __half gsm[];
    __half* sA = gsm;
    __half* sB = gsm + GA_HALVES;

    const int tid  = threadIdx.x;
    const int warp = tid >> 5, lane = tid & 31;
    const int wm = warp & 3, wn = warp >> 2;
    const int g = lane >> 2, t = lane & 3;
    const int m0 = blockIdx.x * 128;

    const uint32_t sA32 = smem_to_u32(sA);
    const uint32_t sB32 = smem_to_u32(sB);

    auto issueB = [&](int nt) {
        const uint32_t bB = sB32 + (uint32_t)((nt & 1) * GB_HALVES * 2);
#pragma unroll
        for (int i = 0; i < 6; ++i) {
            const int seg = tid + i * 256;
            if (seg < 1344) {
                const int row = seg / 14, q = seg % 14;
                cp_async16(bB + (uint32_t)(row * (GSTR * 2) + q * 16),
                           g_Wc_h + (size_t)(nt * 96 + row) * KN_PAD + q * 8, 16);
            }
        }
        CP_COMMIT();
    };

#pragma unroll
    for (int i = 0; i < 7; ++i) {
        const int seg = tid + i * 256;
        const int row = seg / 14, q = seg % 14;
        cp_async16(sA32 + (uint32_t)(row * (GSTR * 2) + q * 16),
                   g_T_h + (size_t)(m0 + row) * KN_PAD + q * 8, 16);
    }
    {
        const uint32_t bB = sB32;
#pragma unroll
        for (int i = 0; i < 6; ++i) {
            const int seg = tid + i * 256;
            if (seg < 1344) {
                const int row = seg / 14, q = seg % 14;
                cp_async16(bB + (uint32_t)(row * (GSTR * 2) + q * 16),
                           g_Wc_h + (size_t)row * KN_PAD + q * 8, 16);
            }
        }
        CP_COMMIT();
    }
    issueB(1);

#pragma unroll 1
    for (int nt = 0; nt < GNT; ++nt) {
        CP_WAIT(1);
        __syncthreads();

        const __half* a_ = sA;
        const __half* b_ = sB + (nt & 1) * GB_HALVES;

        float acc[2][6][4];
#pragma unroll
        for (int i = 0; i < 2; ++i)
#pragma unroll
            for (int j = 0; j < 6; ++j)
#pragma unroll
                for (int q = 0; q < 4; ++q) acc[i][j][q] = 0.f;

#pragma unroll
        for (int kk = 0; kk < 7; ++kk) {
            const int col = kk * 16 + 2 * t;
            uint32_t af[2][4], bf[6][2];
#pragma unroll
            for (int tm = 0; tm < 2; ++tm) {
                const int r = wm * 32 + tm * 16 + g;
                af[tm][0] = *(const uint32_t*)(a_ + r * GSTR + col);
                af[tm][1] = *(const uint32_t*)(a_ + (r + 8) * GSTR + col);
                af[tm][2] = *(const uint32_t*)(a_ + r * GSTR + col + 8);
                af[tm][3] = *(const uint32_t*)(a_ + (r + 8) * GSTR + col + 8);
            }
#pragma unroll
            for (int tn = 0; tn < 6; ++tn) {
                const int n = wn * 48 + tn * 8 + g;
                bf[tn][0] = *(const uint32_t*)(b_ + n * GSTR + col);
                bf[tn][1] = *(const uint32_t*)(b_ + n * GSTR + col + 8);
            }
#pragma unroll
            for (int tm = 0; tm < 2; ++tm)
#pragma unroll
                for (int tn = 0; tn < 6; ++tn)
                    mma_f16(acc[tm][tn], af[tm], bf[tn]);
        }
        __syncthreads();
        if (nt + 2 < GNT) issueB(nt + 2);
        else              CP_COMMIT();

        const int n0 = nt * 96;
#pragma unroll
        for (int G = 0; G < 2; ++G) {
            const int colbase = n0 + wn * 48 + G * 24;
            const int d = (colbase >= 912);
            const int grp = (colbase - d * 912) / 24;
            const int j0 = grp * 8 + 2 * t;
            const float bh0 = g_bhn[d * 304 + j0];
            const float bh1 = g_bhn[d * 304 + j0 + 1];
            const float cr0 = g_c_r[colbase + 2 * t];
            const float cr1 = g_c_r[colbase + 2 * t + 1];
            const float cz0 = g_c_r[colbase + 8 + 2 * t];
            const float cz1 = g_c_r[colbase + 8 + 2 * t + 1];
            const float cn0 = g_c_r[colbase + 16 + 2 * t];
            const float cn1 = g_c_r[colbase + 16 + 2 * t + 1];
            const bool valid = (j0 < 300);
#pragma unroll
            for (int tm = 0; tm < 2; ++tm) {
#pragma unroll
                for (int rr = 0; rr < 2; ++rr) {
                    const int bt = m0 + wm * 32 + tm * 16 + g + rr * 8;
                    float h0 = 0.f, h1 = 0.f;
                    if (valid) {
                        const int q0 = rr * 2;
                        const float r0 = fsigmoid(acc[tm][3 * G + 0][q0]     + cr0);
                        const float r1 = fsigmoid(acc[tm][3 * G + 0][q0 + 1] + cr1);
                        const float z0 = fsigmoid(acc[tm][3 * G + 1][q0]     + cz0);
                        const float z1 = fsigmoid(acc[tm][3 * G + 1][q0 + 1] + cz1);
                        const float n0_ = acc[tm][3 * G + 2][q0]     + cn0;
                        const float n1_ = acc[tm][3 * G + 2][q0 + 1] + cn1;
                        h0 = (1.f - z0) * ftanh(n0_ + r0 * bh0);
                        h1 = (1.f - z1) * ftanh(n1_ + r1 * bh1);
                    }
                    *(__half2*)(g_hidden_h + (size_t)bt * HPAD + d * 304 + j0) =
                        __floats2half2_rn(h0, h1);
                }
            }
        }
    }
}

// ================= fused scores GEMM + softmax + alpha =================
#define SC_STR 520
#define ATTN_PIPE_HALVES (2 * (128 + 128) * ASTR)
#define ATTN_SC_HALVES   (128 * SC_STR)
#define ATTN_SMEM ((ATTN_PIPE_HALVES + ATTN_SC_HALVES) * 2 + 8 * NT * 4)

__global__ void __launch_bounds__(256, 1) attn_kernel()
{
    extern __shared__ __half asm_[];
    __half* sPipe = asm_;
    __half* ssc   = asm_ + ATTN_PIPE_HALVES;
    float*  part  = (float*)(asm_ + ATTN_PIPE_HALVES + ATTN_SC_HALVES);

    const int b  = blockIdx.x;
    const int lb = blockIdx.y;
    const __half* A = g_ctx_h + (size_t)(b * NLQ + lb * 128) * KH_PAD;
    const __half* B = g_hid_h + (size_t)b * NT * KH_PAD;

    const int tid  = threadIdx.x;
    const int warp = tid >> 5, lane = tid & 31;
    const int wm = warp & 3, wn = warp >> 2;
    const int g = lane >> 2, t = lane & 3;

    const uint32_t p32 = smem_to_u32(sPipe);
    const int CH = (KH_PAD + 31) >> 5;

#pragma unroll 1
    for (int nt = 0; nt < 4; ++nt) {
        const __half* Bt = B + (size_t)(nt * 128) * KH_PAD;

        auto issue = [&](int c) {
            const int s = c & 1;
            const int kb = c << 5;
            const uint32_t aB = p32 + (uint32_t)s * ((128 + 128) * ASTR * 2);
            const uint32_t bB = aB + (uint32_t)(128 * ASTR * 2);
#pragma unroll
            for (int i = 0; i < 2; ++i) {
                const int seg = tid + i * 256;
                const int row = seg >> 2, q = seg & 3;
                const int k = kb + q * 8;
                const int va = (k + 8 <= KH_PAD);
                cp_async16(aB + (uint32_t)(row * (ASTR * 2) + q * 16),
                           va ? (const void*)(A + (size_t)row * KH_PAD + k) : (const void*)A,
                           va ? 16 : 0);
                cp_async16(bB + (uint32_t)(row * (ASTR * 2) + q * 16),
                           va ? (const void*)(Bt + (size_t)row * KH_PAD + k) : (const void*)Bt,
                           va ? 16 : 0);
            }
            CP_COMMIT();
        };

        float acc[2][8][4];
#pragma unroll
        for (int i = 0; i < 2; ++i)
#pragma unroll
            for (int j = 0; j < 8; ++j)
#pragma unroll
                for (int q = 0; q < 4; ++q) acc[i][j][q] = 0.f;

        issue(0);
        for (int c = 0; c < CH; ++c) {
            if (c + 1 < CH) { issue(c + 1); CP_WAIT(1); }
            else            { CP_WAIT(0); }
            __syncthreads();

            const __half* a_ = sPipe + (size_t)(c & 1) * ((128 + 128) * ASTR);
            const __half* b_ = a_ + 128 * ASTR;

#pragma unroll
            for (int kk = 0; kk < 2; ++kk) {
                const int col = kk * 16 + 2 * t;
                uint32_t af[2][4], bf[8][2];
#pragma unroll
                for (int tm = 0; tm < 2; ++tm) {
                    const int r = wm * 32 + tm * 16 + g;
                    af[tm][0] = *(const uint32_t*)(a_ + r * ASTR + col);
                    af[tm][1] = *(const uint32_t*)(a_ + (r + 8) * ASTR + col);
                    af[tm][2] = *(const uint32_t*)(a_ + r * ASTR + col + 8);
                    af[tm][3] = *(const uint32_t*)(a_ + (r + 8) * ASTR + col + 8);
                }
#pragma unroll
                for (int tn = 0; tn < 8; ++tn) {
                    const int n = wn * 64 + tn * 8 + g;
                    bf[tn][0] = *(const uint32_t*)(b_ + n * ASTR + col);
                    bf[tn][1] = *(const uint32_t*)(b_ + n * ASTR + col + 8);
                }
#pragma unroll
                for (int tm = 0; tm < 2; ++tm)
#pragma unroll
                    for (int tn = 0; tn < 8; ++tn)
                        mma_f16(acc[tm][tn], af[tm], bf[tn]);
            }
            __syncthreads();
        }

#pragma unroll
        for (int tm = 0; tm < 2; ++tm) {
            const int row = wm * 32 + tm * 16 + g;
#pragma unroll
            for (int tn = 0; tn < 8; ++tn) {
                const int n = nt * 128 + wn * 64 + tn * 8 + 2 * t;
                *(__half2*)(ssc + (size_t)row * SC_STR + n) =
                    __floats2half2_rn(acc[tm][tn][0], acc[tm][tn][1]);
                *(__half2*)(ssc + (size_t)(row + 8) * SC_STR + n) =
                    __floats2half2_rn(acc[tm][tn][2], acc[tm][tn][3]);
            }
        }
        __syncthreads();
    }

    float pacc[16];
#pragma unroll
    for (int q = 0; q < 16; ++q) pacc[q] = 0.f;

#pragma unroll 1
    for (int i = 0; i < 16; ++i) {
        const int l = warp * 16 + i;
        const __half2* row2 = (const __half2*)(ssc + (size_t)l * SC_STR);
        float v[16], m = -1e30f;
#pragma unroll
        for (int q = 0; q < 8; ++q) {
            float2 f = __half22float2(row2[lane + 32 * q]);
            v[2 * q] = f.x; v[2 * q + 1] = f.y;
            m = fmaxf(m, fmaxf(f.x, f.y));
        }
#pragma unroll
        for (int o = 16; o; o >>= 1) m = fmaxf(m, __shfl_xor_sync(0xffffffffu, m, o));
        float e[16], s = 0.f;
#pragma unroll
        for (int q = 0; q < 16; ++q) { e[q] = fexp2(LOG2E * (v[q] - m)); s += e[q]; }
#pragma unroll
        for (int o = 16; o; o >>= 1) s += __shfl_xor_sync(0xffffffffu, s, o);
        const float rinv = frcp(s);
#pragma unroll
        for (int q = 0; q < 16; ++q) pacc[q] += e[q] * rinv;
    }
#pragma unroll
    for (int q = 0; q < 8; ++q) {
        const int c = 2 * (lane + 32 * q);
        part[warp * NT + c]     = pacc[2 * q];
        part[warp * NT + c + 1] = pacc[2 * q + 1];
    }
    __syncthreads();

#pragma unroll
    for (int h = 0; h < 2; ++h) {
        const int c = tid + h * 256;
        float s = 0.f;
#pragma unroll
        for (int w2 = 0; w2 < 8; ++w2) s += part[w2 * NT + c];
        g_alpha2[(b * 2 + lb) * NT + c] = s;
    }
}

// ---------------- unified fp32 -> fp16 conversions ----------------
#define CVT_N0 ((long)ROWS_BN * KN_PAD)
#define CVT_N1 ((long)NB * NLQ * KH_PAD)
#define CVT_N2 ((long)300 * KN_PAD)
#define CVT_N3 ((long)300 * HPAD)
#define CVT_TOTAL (CVT_N0 + CVT_N1 + CVT_N2 + CVT_N3)

__global__ void convert_all(const float* __restrict__ nodes,
                            const float* __restrict__ ctx,
                            const float* __restrict__ Wnode,
                            const float* __restrict__ Wout)
{
    for (long i = blockIdx.x * (long)blockDim.x + threadIdx.x; i < CVT_TOTAL;
         i += (long)gridDim.x * blockDim.x) {
        if (i < CVT_N0) {
            const long r = i / KN_PAD, k = i - r * KN_PAD;
            g_nodes_h[i] = __float2half((k < D_NODE) ? nodes[r * D_NODE + k] : 0.f);
        } else if (i < CVT_N0 + CVT_N1) {
            const long j = i - CVT_N0;
            const long r = j / KH_PAD, k = j - r * KH_PAD;
            g_ctx_h[j] = __float2half((k < D_HID) ? ctx[r * D_HID + k] : 0.f);
        } else if (i < CVT_N0 + CVT_N1 + CVT_N2) {
            const long j = i - CVT_N0 - CVT_N1;
            const long r = j / KN_PAD, k = j - r * KN_PAD;
            g_Wnode_h[j] = __float2half((k < D_NODE) ? Wnode[r * D_NODE + k] : 0.f);
        } else {
            const long j = i - CVT_N0 - CVT_N1 - CVT_N2;
            const long n = j / HPAD, k = j - n * HPAD;
            float v = 0.f;
            if (k < 300)                  v = Wout[n * 600 + k];
            else if (k >= 304 && k < 604) v = Wout[n * 600 + (k - 4)];
            g_Wout_h[j] = __float2half(v);
        }
    }
}

// ---------------- weight combine -> reordered Wc_h / c_r / bhn ----------------
#define CBJ 16
#define COMBINE_SMEM ((30000 + CBJ * 300) * 4)

__global__ void __launch_bounds__(256)
combine_kernel(const float* __restrict__ Wf, const float* __restrict__ bif,
               const float* __restrict__ bhf,
               const float* __restrict__ Wb, const float* __restrict__ bib,
               const float* __restrict__ bhb,
               const float* __restrict__ Wmean, const float* __restrict__ bmean)
{
    extern __shared__ float csm[];
    float* sW   = csm;
    float* srow = csm + 30000;

    const int j0 = blockIdx.x * CBJ;
    const int tid = threadIdx.x;

    for (int i = tid; i < 30000; i += 256) sW[i] = Wmean[i];
    for (int i = tid; i < CBJ * 300; i += 256) {
        const int jj = i / 300, dcol = i % 300;
        const int cnew = j0 + jj;
        const int d = (cnew >= 912);
        const int rem = cnew - d * 912;
        const int grp = rem / 24, gate = (rem % 24) >> 3, pos = rem & 7;
        const int h = grp * 8 + pos;
        float v = 0.f;
        if (h < 300) {
            const int src = gate * 300 + h;
            v = d ? Wb[src * 300 + dcol] : Wf[src * 300 + dcol];
        }
        srow[i] = v;
    }
    __syncthreads();

    for (int idx = tid; idx < CBJ * KN_PAD; idx += 256) {
        const int jj = idx / KN_PAD, k = idx % KN_PAD;
        const int cnew = j0 + jj;
        float s = 0.f;
        if (k < 100) {
            const float* wr = srow + jj * 300;
#pragma unroll 4
            for (int dd = 0; dd < 300; ++dd) s = fmaf(wr[dd], sW[dd * 100 + k], s);
        }
        g_Wc_h[(size_t)cnew * KN_PAD + k] = __float2half(s);
    }
    if (tid < CBJ) {
        const int cnew = j0 + tid;
        const int d = (cnew >= 912);
        const int rem = cnew - d * 912;
        const int grp = rem / 24, gate = (rem % 24) >> 3, pos = rem & 7;
        const int h = grp * 8 + pos;
        float s = 0.f;
        if (h < 300) {
            const int src = gate * 300 + h;
            const float* bih = d ? bib : bif;
            const float* bhh = d ? bhb : bhf;
            s = bih[src];
            const float* wr = srow + tid * 300;
            for (int dd = 0; dd < 300; ++dd) s = fmaf(wr[dd], bmean[dd], s);
            if (gate < 2) s += bhh[src];
            if (gate == 2) g_bhn[d * 304 + h] = bhh[600 + h];
        } else {
            if (gate == 2) g_bhn[d * 304 + h] = 0.f;
        }
        g_c_r[cnew] = s;
    }
}

// ---------------- per-triple averaged node vectors ----------------
__global__ void __launch_bounds__(224) tri_avg(const int* __restrict__ tri)
{
    const int r = threadIdx.x / 28, c = threadIdx.x % 28;
    const int bt = blockIdx.x * 8 + r;
    const int b = bt >> 9;
    const int hN = tri[bt * 3 + 0];
    const int tN = tri[bt * 3 + 2];
    const uint2 vh = ((const uint2*)(g_nodes_h + (size_t)(b * NNODE + hN) * KN_PAD))[c];
    const uint2 vt = ((const uint2*)(g_nodes_h + (size_t)(b * NNODE + tN) * KN_PAD))[c];
    const float2 hx = __half22float2(*(const __half2*)&vh.x);
    const float2 hy = __half22float2(*(const __half2*)&vh.y);
    const float2 tx = __half22float2(*(const __half2*)&vt.x);
    const float2 ty = __half22float2(*(const __half2*)&vt.y);
    __half2 o0 = __floats2half2_rn(0.5f * (hx.x + tx.x), 0.5f * (hx.y + tx.y));
    __half2 o1 = __floats2half2_rn(0.5f * (hy.x + ty.x), 0.5f * (hy.y + ty.y));
    uint2 o;
    o.x = *(uint32_t*)&o0;
    o.y = *(uint32_t*)&o1;
    ((uint2*)(g_T_h + (size_t)bt * KN_PAD))[c] = o;
}

// ---------------- rep = alpha @ hid_ ; layernorm (R9 proven version) ----------------
__global__ void __launch_bounds__(320) rep_ln_kernel(const float* __restrict__ gamma,
                                                     const float* __restrict__ beta,
                                                     float* __restrict__ out)
{
    const int b = blockIdx.x;
    __shared__ float sal[NT];
    __shared__ float red[2][10];
    const int tid = threadIdx.x;

    for (int t = tid; t < NT; t += 320)
        sal[t] = g_alpha2[(b * 2) * NT + t] + g_alpha2[(b * 2 + 1) * NT + t];
    __syncthreads();

    float acc = 0.f;
    const __half* H = g_hid_h + (size_t)b * NT * KH_PAD;
    if (tid < D_HID) {
        for (int t = 0; t < NT; ++t)
            acc = fmaf(sal[t], __half2float(H[(size_t)t * KH_PAD + tid]), acc);
    }
    float v1 = (tid < D_HID) ? acc : 0.f;
    float v2 = (tid < D_HID) ? acc * acc : 0.f;
#pragma unroll
    for (int o = 16; o; o >>= 1) {
        v1 += __shfl_xor_sync(0xffffffffu, v1, o);
        v2 += __shfl_xor_sync(0xffffffffu, v2, o);
    }
    const int wid = tid >> 5, lane = tid & 31;
    if (lane == 0) { red[0][wid] = v1; red[1][wid] = v2; }
    __syncthreads();
    if (tid == 0) {
        float s1 = 0.f, s2 = 0.f;
        for (int w = 0; w < 10; ++w) { s1 += red[0][w]; s2 += red[1][w]; }
        red[0][0] = s1 / (float)D_HID;
        red[1][0] = s2 / (float)D_HID;
    }
    __syncthreads();
    if (tid < D_HID) {
        float mu = red[0][0];
        float var = red[1][0] - mu * mu;
        out[b * D_HID + tid] = (acc - mu) * rsqrtf(var + 1e-5f) * gamma[tid] + beta[tid];
    }
}

__global__ void zero_tail_kernel(float* __restrict__ out, long start, long end)
{
    long i = start + (long)blockIdx.x * blockDim.x + threadIdx.x;
    if (i < end) out[i] = 0.f;
}

// ---------------- launch ----------------
extern "C" void kernel_launch(void* const* d_in, const int* in_sizes, int n_in,
                              void* d_out, int out_size)
{
    const int o = (in_sizes[3] == 1) ? 1 : 0;

    const float* nodes  = (const float*)d_in[0];
    const float* ctx    = (const float*)d_in[1];
    const int*   tri    = (const int*)d_in[2];
    const float* W_mean = (const float*)d_in[3 + o];
    const float* b_mean = (const float*)d_in[4 + o];
    const float* W_ih_f = (const float*)d_in[5 + o];
    const float* b_ih_f = (const float*)d_in[6 + o];
    const float* b_hh_f = (const float*)d_in[7 + o];
    const float* W_ih_b = (const float*)d_in[8 + o];
    const float* b_ih_b = (const float*)d_in[9 + o];
    const float* b_hh_b = (const float*)d_in[10 + o];
    const float* W_out  = (const float*)d_in[11 + o];
    const float* b_out  = (const float*)d_in[12 + o];
    const float* W_node = (const float*)d_in[13 + o];
    const float* b_node = (const float*)d_in[14 + o];
    const float* gamma  = (const float*)d_in[15 + o];
    const float* beta   = (const float*)d_in[16 + o];
    float* out = (float*)d_out;

    __half *pNodesH, *pWnodeH, *pWoutH, *pHiddenH, *pHidH;
    cudaGetSymbolAddress((void**)&pNodesH,  g_nodes_h);
    cudaGetSymbolAddress((void**)&pWnodeH,  g_Wnode_h);
    cudaGetSymbolAddress((void**)&pWoutH,   g_Wout_h);
    cudaGetSymbolAddress((void**)&pHiddenH, g_hidden_h);
    cudaGetSymbolAddress((void**)&pHidH,    g_hid_h);

    cudaFuncSetAttribute(combine_kernel, cudaFuncAttributeMaxDynamicSharedMemorySize, COMBINE_SMEM);
    cudaFuncSetAttribute(gemm_gates,     cudaFuncAttributeMaxDynamicSharedMemorySize, GATES_SMEM);
    cudaFuncSetAttribute(attn_kernel,    cudaFuncAttributeMaxDynamicSharedMemorySize, ATTN_SMEM);

    convert_all<<<8192, 256>>>(nodes, ctx, W_node, W_out);

    combine_kernel<<<NCOLS / CBJ, 256, COMBINE_SMEM>>>(
        W_ih_f, b_ih_f, b_hh_f, W_ih_b, b_ih_b, b_hh_b, W_mean, b_mean);

    tri_avg<<<ROWS_BT / 8, 224>>>(tri);

    gemm_gates<<<ROWS_BT / 128, 256, GATES_SMEM>>>();

    // node_feature: cols 0-255 (TNW=8) + tail 256-303 (TNW=3, covers 48 cols)
    {
        dim3 grid(2, ROWS_BN / BM, 1);
        gemm_f16<false, 8><<<grid, 256>>>(pNodesH, 0, pWnodeH, 0, out + OUT_PATH, 0,
                                          ROWS_BN, D_HID, D_HID, KN_PAD, b_node, 0, 0);
        dim3 gridT(1, ROWS_BN / BM, 1);
        gemm_f16<false, 3><<<gridT, 256>>>(pNodesH, 0, pWnodeH, 0, out + OUT_PATH, 0,
                                           ROWS_BN, D_HID, D_HID, KN_PAD, b_node, 0, 256);
    }
    // hid_: cols 0-255 (TNW=8) + tail 256-303 (TNW=3)
    {
        dim3 grid(2, ROWS_BT / BM, 1);
        gemm_f16<true, 8><<<grid, 256>>>(pHiddenH, 0, pWoutH, 0, pHidH, 0,
                                         ROWS_BT, D_HID, KH_PAD, HPAD, b_out, 1, 0);
        dim3 gridT(1, ROWS_BT / BM, 1);
        gemm_f16<true, 3><<<gridT, 256>>>(pHiddenH, 0, pWoutH, 0, pHidH, 0,
                                          ROWS_BT, D_HID, KH_PAD, HPAD, b_out, 1, 256);
    }
    attn_kernel<<<dim3(NB, 2), 256, ATTN_SMEM>>>();

    rep_ln_kernel<<<NB, 320>>>(gamma, beta, out);

    {
        long start = OUT_TAIL_START;
        long end = (long)out_size;
        if (end > start) {
            long n = end - start;
            int blocks = (int)((n + 255) / 256);
            zero_tail_kernel<<<blocks, 256>>>(out, start, end);
        }
    }
}

// round 13
// speedup vs baseline: 2.2520x; 1.0096x over previous
#include <cuda_runtime.h>
#include <cuda_fp16.h>
#include <math.h>
#include <stdint.h>

// ---------------- problem constants ----------------
#define D_NODE 100
#define D_HID  300
#define NB     128
#define NT     512
#define NNODE  256
#define NLQ    256
#define ROWS_BT (NB*NT)     // 65536
#define ROWS_BN (NB*NNODE)  // 32768

#define KN_PAD 112
#define KH_PAD 304
#define HPAD   608          // hidden padded: [fwd 304 | bwd 304]
#define NCOLS  1824         // reordered gate cols

#define OUT_PATH   (NB*D_HID)
#define OUT_NODEF  ((long)ROWS_BN*D_HID)
#define OUT_TAIL_START (OUT_PATH + OUT_NODEF)

// ---------------- device scratch ----------------
__device__ __half g_nodes_h[(size_t)ROWS_BN * KN_PAD];
__device__ __half g_ctx_h[(size_t)NB * NLQ * KH_PAD];
__device__ __half g_T_h[(size_t)ROWS_BT * KN_PAD];
__device__ __half g_Wc_h[NCOLS * KN_PAD];
__device__ float  g_c_r[NCOLS];
__device__ float  g_bhn[HPAD];
__device__ __half g_Wnode_h[300 * KN_PAD];
__device__ __half g_Wout_h[300 * HPAD];
__device__ __half g_hidden_h[(size_t)ROWS_BT * HPAD];
__device__ __half g_hid_h[(size_t)ROWS_BT * KH_PAD];
__device__ float  g_alpha4[NB * 4 * NT];

// ---------------- PTX helpers ----------------
__device__ __forceinline__ uint32_t smem_to_u32(const void* p) {
    uint32_t a;
    asm("{ .reg .u64 t; cvta.to.shared.u64 t, %1; cvt.u32.u64 %0, t; }" : "=r"(a) : "l"(p));
    return a;
}
__device__ __forceinline__ void mma_f16(float* d, const uint32_t* a, const uint32_t* b) {
    asm volatile(
        "mma.sync.aligned.m16n8k16.row.col.f32.f16.f16.f32 "
        "{%0,%1,%2,%3}, {%4,%5,%6,%7}, {%8,%9}, {%0,%1,%2,%3};"
        : "+f"(d[0]), "+f"(d[1]), "+f"(d[2]), "+f"(d[3])
        : "r"(a[0]), "r"(a[1]), "r"(a[2]), "r"(a[3]), "r"(b[0]), "r"(b[1]));
}
__device__ __forceinline__ void cp_async16(uint32_t dst, const void* src, int src_size) {
    asm volatile("cp.async.cg.shared.global [%0], [%1], 16, %2;"
        :: "r"(dst), "l"(src), "r"(src_size) : "memory");
}
#define CP_COMMIT() asm volatile("cp.async.commit_group;" ::: "memory")
#define CP_WAIT(n)  asm volatile("cp.async.wait_group %0;" :: "n"(n) : "memory")

__device__ __forceinline__ float fexp2(float x) {
    float y; asm("ex2.approx.f32 %0, %1;" : "=f"(y) : "f"(x)); return y;
}
__device__ __forceinline__ float frcp(float x) {
    float y; asm("rcp.approx.f32 %0, %1;" : "=f"(y) : "f"(x)); return y;
}
#define LOG2E 1.4426950408889634f
__device__ __forceinline__ float fsigmoid(float x) { return frcp(1.f + fexp2(-LOG2E * x)); }
__device__ __forceinline__ float ftanh(float x)    { return 2.f * frcp(1.f + fexp2(-2.f * LOG2E * x)) - 1.f; }

// ================= generic fp16 mma GEMM (compile-time warp-width TNW) =================
#define BM 128
#define ASTR 40

template <bool OUT_HALF, int TNW>
__global__ void __launch_bounds__(256, 2)
gemm_f16(const __half* __restrict__ A, long aBatch,
         const __half* __restrict__ W, long wBatch,
         void* __restrict__ Cv, long cBatch,
         int M, int N, int Npad, int K,
         const float* __restrict__ bias, int act_tanh, int nbase)
{
    constexpr int BNE = TNW * 16;
    __shared__ __half sA[2][BM * ASTR];
    __shared__ __half sB[2][BM * ASTR];

    const int bz = blockIdx.z;
    A += (long)bz * aBatch; W += (long)bz * wBatch;

    const int tid  = threadIdx.x;
    const int warp = tid >> 5, lane = tid & 31;
    const int wm = warp & 3, wn = warp >> 2;
    const int g = lane >> 2, t = lane & 3;

    const int m0 = blockIdx.y * BM;
    const int n0 = nbase + blockIdx.x * BNE;
    const int CH = (K + 31) >> 5;

    const uint32_t sA32 = smem_to_u32(sA);
    const uint32_t sB32 = smem_to_u32(sB);

    float acc[2][TNW][4];
#pragma unroll
    for (int i = 0; i < 2; ++i)
#pragma unroll
        for (int j = 0; j < TNW; ++j)
#pragma unroll
            for (int q = 0; q < 4; ++q) acc[i][j][q] = 0.f;

    auto issue = [&](int c) {
        const int s = c & 1;
        const int kb = c << 5;
        const uint32_t aB = sA32 + (uint32_t)s * (BM * ASTR * 2);
        const uint32_t bB = sB32 + (uint32_t)s * (BM * ASTR * 2);
#pragma unroll
        for (int i = 0; i < 2; ++i) {
            const int seg = tid + i * 256;
            const int row = seg >> 2, q = seg & 3;
            const int k = kb + q * 8;
            const int va = (k + 8 <= K);
            cp_async16(aB + (uint32_t)(row * (ASTR * 2) + q * 16),
                       va ? (const void*)(A + (long)(m0 + row) * K + k) : (const void*)A,
                       va ? 16 : 0);
            const int vb = va && (row < BNE) && (n0 + row < N);
            cp_async16(bB + (uint32_t)(row * (ASTR * 2) + q * 16),
                       vb ? (const void*)(W + (long)(n0 + row) * K + k) : (const void*)W,
                       vb ? 16 : 0);
        }
        CP_COMMIT();
    };

    issue(0);
    for (int c = 0; c < CH; ++c) {
        if (c + 1 < CH) { issue(c + 1); CP_WAIT(1); }
        else            { CP_WAIT(0); }
        __syncthreads();

        const __half* a_ = sA[c & 1];
        const __half* b_ = sB[c & 1];

#pragma unroll
        for (int kk = 0; kk < 2; ++kk) {
            const int col = kk * 16 + 2 * t;
            uint32_t af[2][4], bf[TNW][2];
#pragma unroll
            for (int tm = 0; tm < 2; ++tm) {
                const int r = wm * 32 + tm * 16 + g;
                af[tm][0] = *(const uint32_t*)(a_ + r * ASTR + col);
                af[tm][1] = *(const uint32_t*)(a_ + (r + 8) * ASTR + col);
                af[tm][2] = *(const uint32_t*)(a_ + r * ASTR + col + 8);
                af[tm][3] = *(const uint32_t*)(a_ + (r + 8) * ASTR + col + 8);
            }
#pragma unroll
            for (int tn = 0; tn < TNW; ++tn) {
                const int n = wn * (TNW * 8) + tn * 8 + g;
                bf[tn][0] = *(const uint32_t*)(b_ + n * ASTR + col);
                bf[tn][1] = *(const uint32_t*)(b_ + n * ASTR + col + 8);
            }
#pragma unroll
            for (int tm = 0; tm < 2; ++tm)
#pragma unroll
                for (int tn = 0; tn < TNW; ++tn)
                    mma_f16(acc[tm][tn], af[tm], bf[tn]);
        }
        __syncthreads();
    }

#pragma unroll
    for (int tm = 0; tm < 2; ++tm) {
        const int row = m0 + wm * 32 + tm * 16 + g;
#pragma unroll
        for (int tn = 0; tn < TNW; ++tn) {
            const int n = n0 + wn * (TNW * 8) + tn * 8 + 2 * t;
            if (OUT_HALF ? (n < Npad) : (n < N)) {
                float v0 = 0.f, v1 = 0.f, v2 = 0.f, v3 = 0.f;
                if (n < N) {
                    float b0 = 0.f, b1 = 0.f;
                    if (bias) { b0 = bias[n]; b1 = bias[n + 1]; }
                    v0 = acc[tm][tn][0] + b0;
                    v1 = acc[tm][tn][1] + b1;
                    v2 = acc[tm][tn][2] + b0;
                    v3 = acc[tm][tn][3] + b1;
                    if (act_tanh) { v0 = ftanh(v0); v1 = ftanh(v1); v2 = ftanh(v2); v3 = ftanh(v3); }
                }
                if constexpr (OUT_HALF) {
                    __half* C = (__half*)Cv + (long)bz * cBatch;
                    *(__half2*)(C + (size_t)row * Npad + n)       = __floats2half2_rn(v0, v1);
                    *(__half2*)(C + (size_t)(row + 8) * Npad + n) = __floats2half2_rn(v2, v3);
                } else {
                    float* C = (float*)Cv + (long)bz * cBatch;
                    *(float2*)(C + (size_t)row * N + n)       = make_float2(v0, v1);
                    *(float2*)(C + (size_t)(row + 8) * N + n) = make_float2(v2, v3);
                }
            }
        }
    }
}

// ================= gi-GEMM with fused GRU gates epilogue =================
#define GSTR 120
#define GA_HALVES (128 * GSTR)
#define GB_HALVES (96 * GSTR)
#define GATES_SMEM ((GA_HALVES + 2 * GB_HALVES) * 2)
#define GNT 19

__global__ void __launch_bounds__(256, 2) gemm_gates()
{
    extern __shared__ __half gsm[];
    __half* sA = gsm;
    __half* sB = gsm + GA_HALVES;

    const int tid  = threadIdx.x;
    const int warp = tid >> 5, lane = tid & 31;
    const int wm = warp & 3, wn = warp >> 2;
    const int g = lane >> 2, t = lane & 3;
    const int m0 = blockIdx.x * 128;

    const uint32_t sA32 = smem_to_u32(sA);
    const uint32_t sB32 = smem_to_u32(sB);

    auto issueB = [&](int nt) {
        const uint32_t bB = sB32 + (uint32_t)((nt & 1) * GB_HALVES * 2);
#pragma unroll
        for (int i = 0; i < 6; ++i) {
            const int seg = tid + i * 256;
            if (seg < 1344) {
                const int row = seg / 14, q = seg % 14;
                cp_async16(bB + (uint32_t)(row * (GSTR * 2) + q * 16),
                           g_Wc_h + (size_t)(nt * 96 + row) * KN_PAD + q * 8, 16);
            }
        }
        CP_COMMIT();
    };

#pragma unroll
    for (int i = 0; i < 7; ++i) {
        const int seg = tid + i * 256;
        const int row = seg / 14, q = seg % 14;
        cp_async16(sA32 + (uint32_t)(row * (GSTR * 2) + q * 16),
                   g_T_h + (size_t)(m0 + row) * KN_PAD + q * 8, 16);
    }
    {
        const uint32_t bB = sB32;
#pragma unroll
        for (int i = 0; i < 6; ++i) {
            const int seg = tid + i * 256;
            if (seg < 1344) {
                const int row = seg / 14, q = seg % 14;
                cp_async16(bB + (uint32_t)(row * (GSTR * 2) + q * 16),
                           g_Wc_h + (size_t)row * KN_PAD + q * 8, 16);
            }
        }
        CP_COMMIT();
    }
    issueB(1);

#pragma unroll 1
    for (int nt = 0; nt < GNT; ++nt) {
        CP_WAIT(1);
        __syncthreads();

        const __half* a_ = sA;
        const __half* b_ = sB + (nt & 1) * GB_HALVES;

        float acc[2][6][4];
#pragma unroll
        for (int i = 0; i < 2; ++i)
#pragma unroll
            for (int j = 0; j < 6; ++j)
#pragma unroll
                for (int q = 0; q < 4; ++q) acc[i][j][q] = 0.f;

#pragma unroll
        for (int kk = 0; kk < 7; ++kk) {
            const int col = kk * 16 + 2 * t;
            uint32_t af[2][4], bf[6][2];
#pragma unroll
            for (int tm = 0; tm < 2; ++tm) {
                const int r = wm * 32 + tm * 16 + g;
                af[tm][0] = *(const uint32_t*)(a_ + r * GSTR + col);
                af[tm][1] = *(const uint32_t*)(a_ + (r + 8) * GSTR + col);
                af[tm][2] = *(const uint32_t*)(a_ + r * GSTR + col + 8);
                af[tm][3] = *(const uint32_t*)(a_ + (r + 8) * GSTR + col + 8);
            }
#pragma unroll
            for (int tn = 0; tn < 6; ++tn) {
                const int n = wn * 48 + tn * 8 + g;
                bf[tn][0] = *(const uint32_t*)(b_ + n * GSTR + col);
                bf[tn][1] = *(const uint32_t*)(b_ + n * GSTR + col + 8);
            }
#pragma unroll
            for (int tm = 0; tm < 2; ++tm)
#pragma unroll
                for (int tn = 0; tn < 6; ++tn)
                    mma_f16(acc[tm][tn], af[tm], bf[tn]);
        }
        __syncthreads();
        if (nt + 2 < GNT) issueB(nt + 2);
        else              CP_COMMIT();

        const int n0 = nt * 96;
#pragma unroll
        for (int G = 0; G < 2; ++G) {
            const int colbase = n0 + wn * 48 + G * 24;
            const int d = (colbase >= 912);
            const int grp = (colbase - d * 912) / 24;
            const int j0 = grp * 8 + 2 * t;
            const float bh0 = g_bhn[d * 304 + j0];
            const float bh1 = g_bhn[d * 304 + j0 + 1];
            const float cr0 = g_c_r[colbase + 2 * t];
            const float cr1 = g_c_r[colbase + 2 * t + 1];
            const float cz0 = g_c_r[colbase + 8 + 2 * t];
            const float cz1 = g_c_r[colbase + 8 + 2 * t + 1];
            const float cn0 = g_c_r[colbase + 16 + 2 * t];
            const float cn1 = g_c_r[colbase + 16 + 2 * t + 1];
            const bool valid = (j0 < 300);
#pragma unroll
            for (int tm = 0; tm < 2; ++tm) {
#pragma unroll
                for (int rr = 0; rr < 2; ++rr) {
                    const int bt = m0 + wm * 32 + tm * 16 + g + rr * 8;
                    float h0 = 0.f, h1 = 0.f;
                    if (valid) {
                        const int q0 = rr * 2;
                        const float r0 = fsigmoid(acc[tm][3 * G + 0][q0]     + cr0);
                        const float r1 = fsigmoid(acc[tm][3 * G + 0][q0 + 1] + cr1);
                        const float z0 = fsigmoid(acc[tm][3 * G + 1][q0]     + cz0);
                        const float z1 = fsigmoid(acc[tm][3 * G + 1][q0 + 1] + cz1);
                        const float n0_ = acc[tm][3 * G + 2][q0]     + cn0;
                        const float n1_ = acc[tm][3 * G + 2][q0 + 1] + cn1;
                        h0 = (1.f - z0) * ftanh(n0_ + r0 * bh0);
                        h1 = (1.f - z1) * ftanh(n1_ + r1 * bh1);
                    }
                    *(__half2*)(g_hidden_h + (size_t)bt * HPAD + d * 304 + j0) =
                        __floats2half2_rn(h0, h1);
                }
            }
        }
    }
}

// ================= fused scores GEMM + softmax + alpha (64-row l-blocks, 2 CTA/SM) ========
#define SC_STR 520
#define AT_BM 64
#define AT_PIPE_HALVES (2 * (AT_BM + 128) * ASTR)     // 15360 halves = 30720 B
#define AT_SC_HALVES   (AT_BM * SC_STR)               // 33280 halves = 66560 B
#define ATTN_SMEM ((AT_PIPE_HALVES + AT_SC_HALVES) * 2)   // 97280 B

__global__ void __launch_bounds__(256, 2) attn_kernel()
{
    extern __shared__ __half asm_[];
    __half* sPipe = asm_;
    __half* ssc   = asm_ + AT_PIPE_HALVES;
    float*  part  = (float*)sPipe;                    // aliased: pipe dead after GEMM phase

    const int b  = blockIdx.x;
    const int lb = blockIdx.y;                        // 0..3
    const __half* A = g_ctx_h + (size_t)(b * NLQ + lb * AT_BM) * KH_PAD;
    const __half* B = g_hid_h + (size_t)b * NT * KH_PAD;

    const int tid  = threadIdx.x;
    const int warp = tid >> 5, lane = tid & 31;
    const int wm = warp & 1, wn = warp >> 1;          // 2 x 4 warp grid (32x32 per warp)
    const int g = lane >> 2, t = lane & 3;

    const uint32_t p32 = smem_to_u32(sPipe);
    const int CH = (KH_PAD + 31) >> 5;                // 10

#pragma unroll 1
    for (int nt = 0; nt < 4; ++nt) {
        const __half* Bt = B + (size_t)(nt * 128) * KH_PAD;

        auto issue = [&](int c) {
            const int s = c & 1;
            const int kb = c << 5;
            const uint32_t aB = p32 + (uint32_t)s * ((AT_BM + 128) * ASTR * 2);
            const uint32_t bB = aB + (uint32_t)(AT_BM * ASTR * 2);
            // A: 64 rows x 4 segs = 256 loads (1/thread)
            {
                const int row = tid >> 2, q = tid & 3;
                const int k = kb + q * 8;
                const int va = (k + 8 <= KH_PAD);
                cp_async16(aB + (uint32_t)(row * (ASTR * 2) + q * 16),
                           va ? (const void*)(A + (size_t)row * KH_PAD + k) : (const void*)A,
                           va ? 16 : 0);
            }
            // B: 128 rows x 4 segs = 512 loads (2/thread)
#pragma unroll
            for (int i = 0; i < 2; ++i) {
                const int seg = tid + i * 256;
                const int row = seg >> 2, q = seg & 3;
                const int k = kb + q * 8;
                const int va = (k + 8 <= KH_PAD);
                cp_async16(bB + (uint32_t)(row * (ASTR * 2) + q * 16),
                           va ? (const void*)(Bt + (size_t)row * KH_PAD + k) : (const void*)Bt,
                           va ? 16 : 0);
            }
            CP_COMMIT();
        };

        float acc[2][4][4];
#pragma unroll
        for (int i = 0; i < 2; ++i)
#pragma unroll
            for (int j = 0; j < 4; ++j)
#pragma unroll
                for (int q = 0; q < 4; ++q) acc[i][j][q] = 0.f;

        issue(0);
        for (int c = 0; c < CH; ++c) {
            if (c + 1 < CH) { issue(c + 1); CP_WAIT(1); }
            else            { CP_WAIT(0); }
            __syncthreads();

            const __half* a_ = sPipe + (size_t)(c & 1) * ((AT_BM + 128) * ASTR);
            const __half* b_ = a_ + AT_BM * ASTR;

#pragma unroll
            for (int kk = 0; kk < 2; ++kk) {
                const int col = kk * 16 + 2 * t;
                uint32_t af[2][4], bf[4][2];
#pragma unroll
                for (int tm = 0; tm < 2; ++tm) {
                    const int r = wm * 32 + tm * 16 + g;
                    af[tm][0] = *(const uint32_t*)(a_ + r * ASTR + col);
                    af[tm][1] = *(const uint32_t*)(a_ + (r + 8) * ASTR + col);
                    af[tm][2] = *(const uint32_t*)(a_ + r * ASTR + col + 8);
                    af[tm][3] = *(const uint32_t*)(a_ + (r + 8) * ASTR + col + 8);
                }
#pragma unroll
                for (int tn = 0; tn < 4; ++tn) {
                    const int n = wn * 32 + tn * 8 + g;
                    bf[tn][0] = *(const uint32_t*)(b_ + n * ASTR + col);
                    bf[tn][1] = *(const uint32_t*)(b_ + n * ASTR + col + 8);
                }
#pragma unroll
                for (int tm = 0; tm < 2; ++tm)
#pragma unroll
                    for (int tn = 0; tn < 4; ++tn)
                        mma_f16(acc[tm][tn], af[tm], bf[tn]);
            }
            __syncthreads();
        }

        // write fp16 scores to smem (same per-element rounding as before)
#pragma unroll
        for (int tm = 0; tm < 2; ++tm) {
            const int row = wm * 32 + tm * 16 + g;
#pragma unroll
            for (int tn = 0; tn < 4; ++tn) {
                const int n = nt * 128 + wn * 32 + tn * 8 + 2 * t;
                *(__half2*)(ssc + (size_t)row * SC_STR + n) =
                    __floats2half2_rn(acc[tm][tn][0], acc[tm][tn][1]);
                *(__half2*)(ssc + (size_t)(row + 8) * SC_STR + n) =
                    __floats2half2_rn(acc[tm][tn][2], acc[tm][tn][3]);
            }
        }
        __syncthreads();   // also orders last pipe reads before part aliasing below
    }

    // ---- softmax over t per row (8 rows per warp), accumulate column partials ----
    float pacc[16];
#pragma unroll
    for (int q = 0; q < 16; ++q) pacc[q] = 0.f;

#pragma unroll 1
    for (int i = 0; i < 8; ++i) {
        const int l = warp * 8 + i;
        const __half2* row2 = (const __half2*)(ssc + (size_t)l * SC_STR);
        float v[16], m = -1e30f;
#pragma unroll
        for (int q = 0; q < 8; ++q) {
            float2 f = __half22float2(row2[lane + 32 * q]);
            v[2 * q] = f.x; v[2 * q + 1] = f.y;
            m = fmaxf(m, fmaxf(f.x, f.y));
        }
#pragma unroll
        for (int o = 16; o; o >>= 1) m = fmaxf(m, __shfl_xor_sync(0xffffffffu, m, o));
        float e[16], s = 0.f;
#pragma unroll
        for (int q = 0; q < 16; ++q) { e[q] = fexp2(LOG2E * (v[q] - m)); s += e[q]; }
#pragma unroll
        for (int o = 16; o; o >>= 1) s += __shfl_xor_sync(0xffffffffu, s, o);
        const float rinv = frcp(s);
#pragma unroll
        for (int q = 0; q < 16; ++q) pacc[q] += e[q] * rinv;
    }
#pragma unroll
    for (int q = 0; q < 8; ++q) {
        const int c = 2 * (lane + 32 * q);
        part[warp * NT + c]     = pacc[2 * q];
        part[warp * NT + c + 1] = pacc[2 * q + 1];
    }
    __syncthreads();

#pragma unroll
    for (int h = 0; h < 2; ++h) {
        const int c = tid + h * 256;
        float s = 0.f;
#pragma unroll
        for (int w2 = 0; w2 < 8; ++w2) s += part[w2 * NT + c];
        g_alpha4[(b * 4 + lb) * NT + c] = s;
    }
}

// ---------------- unified fp32 -> fp16 conversions ----------------
#define CVT_N0 ((long)ROWS_BN * KN_PAD)
#define CVT_N1 ((long)NB * NLQ * KH_PAD)
#define CVT_N2 ((long)300 * KN_PAD)
#define CVT_N3 ((long)300 * HPAD)
#define CVT_TOTAL (CVT_N0 + CVT_N1 + CVT_N2 + CVT_N3)

__global__ void convert_all(const float* __restrict__ nodes,
                            const float* __restrict__ ctx,
                            const float* __restrict__ Wnode,
                            const float* __restrict__ Wout)
{
    for (long i = blockIdx.x * (long)blockDim.x + threadIdx.x; i < CVT_TOTAL;
         i += (long)gridDim.x * blockDim.x) {
        if (i < CVT_N0) {
            const long r = i / KN_PAD, k = i - r * KN_PAD;
            g_nodes_h[i] = __float2half((k < D_NODE) ? nodes[r * D_NODE + k] : 0.f);
        } else if (i < CVT_N0 + CVT_N1) {
            const long j = i - CVT_N0;
            const long r = j / KH_PAD, k = j - r * KH_PAD;
            g_ctx_h[j] = __float2half((k < D_HID) ? ctx[r * D_HID + k] : 0.f);
        } else if (i < CVT_N0 + CVT_N1 + CVT_N2) {
            const long j = i - CVT_N0 - CVT_N1;
            const long r = j / KN_PAD, k = j - r * KN_PAD;
            g_Wnode_h[j] = __float2half((k < D_NODE) ? Wnode[r * D_NODE + k] : 0.f);
        } else {
            const long j = i - CVT_N0 - CVT_N1 - CVT_N2;
            const long n = j / HPAD, k = j - n * HPAD;
            float v = 0.f;
            if (k < 300)                  v = Wout[n * 600 + k];
            else if (k >= 304 && k < 604) v = Wout[n * 600 + (k - 4)];
            g_Wout_h[j] = __float2half(v);
        }
    }
}

// ---------------- weight combine -> reordered Wc_h / c_r / bhn ----------------
#define CBJ 16
#define COMBINE_SMEM ((30000 + CBJ * 300) * 4)

__global__ void __launch_bounds__(256)
combine_kernel(const float* __restrict__ Wf, const float* __restrict__ bif,
               const float* __restrict__ bhf,
               const float* __restrict__ Wb, const float* __restrict__ bib,
               const float* __restrict__ bhb,
               const float* __restrict__ Wmean, const float* __restrict__ bmean)
{
    extern __shared__ float csm[];
    float* sW   = csm;
    float* srow = csm + 30000;

    const int j0 = blockIdx.x * CBJ;
    const int tid = threadIdx.x;

    for (int i = tid; i < 30000; i += 256) sW[i] = Wmean[i];
    for (int i = tid; i < CBJ * 300; i += 256) {
        const int jj = i / 300, dcol = i % 300;
        const int cnew = j0 + jj;
        const int d = (cnew >= 912);
        const int rem = cnew - d * 912;
        const int grp = rem / 24, gate = (rem % 24) >> 3, pos = rem & 7;
        const int h = grp * 8 + pos;
        float v = 0.f;
        if (h < 300) {
            const int src = gate * 300 + h;
            v = d ? Wb[src * 300 + dcol] : Wf[src * 300 + dcol];
        }
        srow[i] = v;
    }
    __syncthreads();

    for (int idx = tid; idx < CBJ * KN_PAD; idx += 256) {
        const int jj = idx / KN_PAD, k = idx % KN_PAD;
        const int cnew = j0 + jj;
        float s = 0.f;
        if (k < 100) {
            const float* wr = srow + jj * 300;
#pragma unroll 4
            for (int dd = 0; dd < 300; ++dd) s = fmaf(wr[dd], sW[dd * 100 + k], s);
        }
        g_Wc_h[(size_t)cnew * KN_PAD + k] = __float2half(s);
    }
    if (tid < CBJ) {
        const int cnew = j0 + tid;
        const int d = (cnew >= 912);
        const int rem = cnew - d * 912;
        const int grp = rem / 24, gate = (rem % 24) >> 3, pos = rem & 7;
        const int h = grp * 8 + pos;
        float s = 0.f;
        if (h < 300) {
            const int src = gate * 300 + h;
            const float* bih = d ? bib : bif;
            const float* bhh = d ? bhb : bhf;
            s = bih[src];
            const float* wr = srow + tid * 300;
            for (int dd = 0; dd < 300; ++dd) s = fmaf(wr[dd], bmean[dd], s);
            if (gate < 2) s += bhh[src];
            if (gate == 2) g_bhn[d * 304 + h] = bhh[600 + h];
        } else {
            if (gate == 2) g_bhn[d * 304 + h] = 0.f;
        }
        g_c_r[cnew] = s;
    }
}

// ---------------- per-triple averaged node vectors ----------------
__global__ void __launch_bounds__(224) tri_avg(const int* __restrict__ tri)
{
    const int r = threadIdx.x / 28, c = threadIdx.x % 28;
    const int bt = blockIdx.x * 8 + r;
    const int b = bt >> 9;
    const int hN = tri[bt * 3 + 0];
    const int tN = tri[bt * 3 + 2];
    const uint2 vh = ((const uint2*)(g_nodes_h + (size_t)(b * NNODE + hN) * KN_PAD))[c];
    const uint2 vt = ((const uint2*)(g_nodes_h + (size_t)(b * NNODE + tN) * KN_PAD))[c];
    const float2 hx = __half22float2(*(const __half2*)&vh.x);
    const float2 hy = __half22float2(*(const __half2*)&vh.y);
    const float2 tx = __half22float2(*(const __half2*)&vt.x);
    const float2 ty = __half22float2(*(const __half2*)&vt.y);
    __half2 o0 = __floats2half2_rn(0.5f * (hx.x + tx.x), 0.5f * (hx.y + tx.y));
    __half2 o1 = __floats2half2_rn(0.5f * (hy.x + ty.x), 0.5f * (hy.y + ty.y));
    uint2 o;
    o.x = *(uint32_t*)&o0;
    o.y = *(uint32_t*)&o1;
    ((uint2*)(g_T_h + (size_t)bt * KN_PAD))[c] = o;
}

// ---------------- rep = alpha @ hid_ ; layernorm ----------------
__global__ void __launch_bounds__(320) rep_ln_kernel(const float* __restrict__ gamma,
                                                     const float* __restrict__ beta,
                                                     float* __restrict__ out)
{
    const int b = blockIdx.x;
    __shared__ float sal[NT];
    __shared__ float red[2][10];
    const int tid = threadIdx.x;

    for (int t = tid; t < NT; t += 320)
        sal[t] = g_alpha4[(b * 4 + 0) * NT + t] + g_alpha4[(b * 4 + 1) * NT + t]
               + g_alpha4[(b * 4 + 2) * NT + t] + g_alpha4[(b * 4 + 3) * NT + t];
    __syncthreads();

    float acc = 0.f;
    const __half* H = g_hid_h + (size_t)b * NT * KH_PAD;
    if (tid < D_HID) {
        for (int t = 0; t < NT; ++t)
            acc = fmaf(sal[t], __half2float(H[(size_t)t * KH_PAD + tid]), acc);
    }
    float v1 = (tid < D_HID) ? acc : 0.f;
    float v2 = (tid < D_HID) ? acc * acc : 0.f;
#pragma unroll
    for (int o = 16; o; o >>= 1) {
        v1 += __shfl_xor_sync(0xffffffffu, v1, o);
        v2 += __shfl_xor_sync(0xffffffffu, v2, o);
    }
    const int wid = tid >> 5, lane = tid & 31;
    if (lane == 0) { red[0][wid] = v1; red[1][wid] = v2; }
    __syncthreads();
    if (tid == 0) {
        float s1 = 0.f, s2 = 0.f;
        for (int w = 0; w < 10; ++w) { s1 += red[0][w]; s2 += red[1][w]; }
        red[0][0] = s1 / (float)D_HID;
        red[1][0] = s2 / (float)D_HID;
    }
    __syncthreads();
    if (tid < D_HID) {
        float mu = red[0][0];
        float var = red[1][0] - mu * mu;
        out[b * D_HID + tid] = (acc - mu) * rsqrtf(var + 1e-5f) * gamma[tid] + beta[tid];
    }
}

__global__ void zero_tail_kernel(float* __restrict__ out, long start, long end)
{
    long i = start + (long)blockIdx.x * blockDim.x + threadIdx.x;
    if (i < end) out[i] = 0.f;
}

// ---------------- launch ----------------
extern "C" void kernel_launch(void* const* d_in, const int* in_sizes, int n_in,
                              void* d_out, int out_size)
{
    const int o = (in_sizes[3] == 1) ? 1 : 0;

    const float* nodes  = (const float*)d_in[0];
    const float* ctx    = (const float*)d_in[1];
    const int*   tri    = (const int*)d_in[2];
    const float* W_mean = (const float*)d_in[3 + o];
    const float* b_mean = (const float*)d_in[4 + o];
    const float* W_ih_f = (const float*)d_in[5 + o];
    const float* b_ih_f = (const float*)d_in[6 + o];
    const float* b_hh_f = (const float*)d_in[7 + o];
    const float* W_ih_b = (const float*)d_in[8 + o];
    const float* b_ih_b = (const float*)d_in[9 + o];
    const float* b_hh_b = (const float*)d_in[10 + o];
    const float* W_out  = (const float*)d_in[11 + o];
    const float* b_out  = (const float*)d_in[12 + o];
    const float* W_node = (const float*)d_in[13 + o];
    const float* b_node = (const float*)d_in[14 + o];
    const float* gamma  = (const float*)d_in[15 + o];
    const float* beta   = (const float*)d_in[16 + o];
    float* out = (float*)d_out;

    __half *pNodesH, *pWnodeH, *pWoutH, *pHiddenH, *pHidH;
    cudaGetSymbolAddress((void**)&pNodesH,  g_nodes_h);
    cudaGetSymbolAddress((void**)&pWnodeH,  g_Wnode_h);
    cudaGetSymbolAddress((void**)&pWoutH,   g_Wout_h);
    cudaGetSymbolAddress((void**)&pHiddenH, g_hidden_h);
    cudaGetSymbolAddress((void**)&pHidH,    g_hid_h);

    cudaFuncSetAttribute(combine_kernel, cudaFuncAttributeMaxDynamicSharedMemorySize, COMBINE_SMEM);
    cudaFuncSetAttribute(gemm_gates,     cudaFuncAttributeMaxDynamicSharedMemorySize, GATES_SMEM);
    cudaFuncSetAttribute(attn_kernel,    cudaFuncAttributeMaxDynamicSharedMemorySize, ATTN_SMEM);

    convert_all<<<8192, 256>>>(nodes, ctx, W_node, W_out);

    combine_kernel<<<NCOLS / CBJ, 256, COMBINE_SMEM>>>(
        W_ih_f, b_ih_f, b_hh_f, W_ih_b, b_ih_b, b_hh_b, W_mean, b_mean);

    tri_avg<<<ROWS_BT / 8, 224>>>(tri);

    gemm_gates<<<ROWS_BT / 128, 256, GATES_SMEM>>>();

    // node_feature: cols 0-255 (TNW=8) + tail 256-303 (TNW=3)
    {
        dim3 grid(2, ROWS_BN / BM, 1);
        gemm_f16<false, 8><<<grid, 256>>>(pNodesH, 0, pWnodeH, 0, out + OUT_PATH, 0,
                                          ROWS_BN, D_HID, D_HID, KN_PAD, b_node, 0, 0);
        dim3 gridT(1, ROWS_BN / BM, 1);
        gemm_f16<false, 3><<<gridT, 256>>>(pNodesH, 0, pWnodeH, 0, out + OUT_PATH, 0,
                                           ROWS_BN, D_HID, D_HID, KN_PAD, b_node, 0, 256);
    }
    // hid_: cols 0-255 (TNW=8) + tail 256-303 (TNW=3)
    {
        dim3 grid(2, ROWS_BT / BM, 1);
        gemm_f16<true, 8><<<grid, 256>>>(pHiddenH, 0, pWoutH, 0, pHidH, 0,
                                         ROWS_BT, D_HID, KH_PAD, HPAD, b_out, 1, 0);
        dim3 gridT(1, ROWS_BT / BM, 1);
        gemm_f16<true, 3><<<gridT, 256>>>(pHiddenH, 0, pWoutH, 0, pHidH, 0,
                                          ROWS_BT, D_HID, KH_PAD, HPAD, b_out, 1, 256);
    }
    attn_kernel<<<dim3(NB, 4), 256, ATTN_SMEM>>>();

    rep_ln_kernel<<<NB, 320>>>(gamma, beta, out);

    {
        long start = OUT_TAIL_START;
        long end = (long)out_size;
        if (end > start) {
            long n = end - start;
            int blocks = (int)((n + 255) / 256);
            zero_tail_kernel<<<blocks, 256>>>(out, start, end);
        }
    }
}

// round 14
// speedup vs baseline: 2.2582x; 1.0028x over previous
#include <cuda_runtime.h>
#include <cuda_fp16.h>
#include <math.h>
#include <stdint.h>

// ---------------- problem constants ----------------
#define D_NODE 100
#define D_HID  300
#define NB     128
#define NT     512
#define NNODE  256
#define NLQ    256
#define ROWS_BT (NB*NT)     // 65536
#define ROWS_BN (NB*NNODE)  // 32768

#define KN_PAD 112
#define KH_PAD 304
#define HPAD   608          // hidden padded: [fwd 304 | bwd 304]
#define NCOLS  1824         // reordered gate cols

#define OUT_PATH   (NB*D_HID)
#define OUT_NODEF  ((long)ROWS_BN*D_HID)
#define OUT_TAIL_START (OUT_PATH + OUT_NODEF)

// ---------------- device scratch ----------------
__device__ __half g_nodes_h[(size_t)ROWS_BN * KN_PAD];
__device__ __half g_ctx_h[(size_t)NB * NLQ * KH_PAD];
__device__ __half g_T_h[(size_t)ROWS_BT * KN_PAD];
__device__ __half g_Wc_h[NCOLS * KN_PAD];
__device__ float  g_c_r[NCOLS];
__device__ float  g_bhn[HPAD];
__device__ __half g_Wnode_h[300 * KN_PAD];
__device__ __half g_Wout_h[300 * HPAD];
__device__ __half g_hidden_h[(size_t)ROWS_BT * HPAD];
__device__ __half g_hid_h[(size_t)ROWS_BT * KH_PAD];
__device__ float  g_alpha4[NB * 4 * NT];

// ---------------- PTX helpers ----------------
__device__ __forceinline__ uint32_t smem_to_u32(const void* p) {
    uint32_t a;
    asm("{ .reg .u64 t; cvta.to.shared.u64 t, %1; cvt.u32.u64 %0, t; }" : "=r"(a) : "l"(p));
    return a;
}
__device__ __forceinline__ void mma_f16(float* d, const uint32_t* a, const uint32_t* b) {
    asm volatile(
        "mma.sync.aligned.m16n8k16.row.col.f32.f16.f16.f32 "
        "{%0,%1,%2,%3}, {%4,%5,%6,%7}, {%8,%9}, {%0,%1,%2,%3};"
        : "+f"(d[0]), "+f"(d[1]), "+f"(d[2]), "+f"(d[3])
        : "r"(a[0]), "r"(a[1]), "r"(a[2]), "r"(a[3]), "r"(b[0]), "r"(b[1]));
}
__device__ __forceinline__ void cp_async16(uint32_t dst, const void* src, int src_size) {
    asm volatile("cp.async.cg.shared.global [%0], [%1], 16, %2;"
        :: "r"(dst), "l"(src), "r"(src_size) : "memory");
}
#define CP_COMMIT() asm volatile("cp.async.commit_group;" ::: "memory")
#define CP_WAIT(n)  asm volatile("cp.async.wait_group %0;" :: "n"(n) : "memory")

__device__ __forceinline__ float fexp2(float x) {
    float y; asm("ex2.approx.f32 %0, %1;" : "=f"(y) : "f"(x)); return y;
}
__device__ __forceinline__ float frcp(float x) {
    float y; asm("rcp.approx.f32 %0, %1;" : "=f"(y) : "f"(x)); return y;
}
#define LOG2E 1.4426950408889634f
__device__ __forceinline__ float fsigmoid(float x) { return frcp(1.f + fexp2(-LOG2E * x)); }
__device__ __forceinline__ float ftanh(float x)    { return 2.f * frcp(1.f + fexp2(-2.f * LOG2E * x)) - 1.f; }

// ================= generic fp16 mma GEMM (compile-time warp-width TNW) =================
#define BM 128
#define ASTR 40

template <bool OUT_HALF, int TNW>
__global__ void __launch_bounds__(256, 2)
gemm_f16(const __half* __restrict__ A, long aBatch,
         const __half* __restrict__ W, long wBatch,
         void* __restrict__ Cv, long cBatch,
         int M, int N, int Npad, int K,
         const float* __restrict__ bias, int act_tanh, int nbase)
{
    constexpr int BNE = TNW * 16;
    __shared__ __half sA[2][BM * ASTR];
    __shared__ __half sB[2][BM * ASTR];

    const int bz = blockIdx.z;
    A += (long)bz * aBatch; W += (long)bz * wBatch;

    const int tid  = threadIdx.x;
    const int warp = tid >> 5, lane = tid & 31;
    const int wm = warp & 3, wn = warp >> 2;
    const int g = lane >> 2, t = lane & 3;

    const int m0 = blockIdx.y * BM;
    const int n0 = nbase + blockIdx.x * BNE;
    const int CH = (K + 31) >> 5;

    const uint32_t sA32 = smem_to_u32(sA);
    const uint32_t sB32 = smem_to_u32(sB);

    float acc[2][TNW][4];
#pragma unroll
    for (int i = 0; i < 2; ++i)
#pragma unroll
        for (int j = 0; j < TNW; ++j)
#pragma unroll
            for (int q = 0; q < 4; ++q) acc[i][j][q] = 0.f;

    auto issue = [&](int c) {
        const int s = c & 1;
        const int kb = c << 5;
        const uint32_t aB = sA32 + (uint32_t)s * (BM * ASTR * 2);
        const uint32_t bB = sB32 + (uint32_t)s * (BM * ASTR * 2);
#pragma unroll
        for (int i = 0; i < 2; ++i) {
            const int seg = tid + i * 256;
            const int row = seg >> 2, q = seg & 3;
            const int k = kb + q * 8;
            const int va = (k + 8 <= K);
            cp_async16(aB + (uint32_t)(row * (ASTR * 2) + q * 16),
                       va ? (const void*)(A + (long)(m0 + row) * K + k) : (const void*)A,
                       va ? 16 : 0);
            const int vb = va && (row < BNE) && (n0 + row < N);
            cp_async16(bB + (uint32_t)(row * (ASTR * 2) + q * 16),
                       vb ? (const void*)(W + (long)(n0 + row) * K + k) : (const void*)W,
                       vb ? 16 : 0);
        }
        CP_COMMIT();
    };

    issue(0);
    for (int c = 0; c < CH; ++c) {
        if (c + 1 < CH) { issue(c + 1); CP_WAIT(1); }
        else            { CP_WAIT(0); }
        __syncthreads();

        const __half* a_ = sA[c & 1];
        const __half* b_ = sB[c & 1];

#pragma unroll
        for (int kk = 0; kk < 2; ++kk) {
            const int col = kk * 16 + 2 * t;
            uint32_t af[2][4], bf[TNW][2];
#pragma unroll
            for (int tm = 0; tm < 2; ++tm) {
                const int r = wm * 32 + tm * 16 + g;
                af[tm][0] = *(const uint32_t*)(a_ + r * ASTR + col);
                af[tm][1] = *(const uint32_t*)(a_ + (r + 8) * ASTR + col);
                af[tm][2] = *(const uint32_t*)(a_ + r * ASTR + col + 8);
                af[tm][3] = *(const uint32_t*)(a_ + (r + 8) * ASTR + col + 8);
            }
#pragma unroll
            for (int tn = 0; tn < TNW; ++tn) {
                const int n = wn * (TNW * 8) + tn * 8 + g;
                bf[tn][0] = *(const uint32_t*)(b_ + n * ASTR + col);
                bf[tn][1] = *(const uint32_t*)(b_ + n * ASTR + col + 8);
            }
#pragma unroll
            for (int tm = 0; tm < 2; ++tm)
#pragma unroll
                for (int tn = 0; tn < TNW; ++tn)
                    mma_f16(acc[tm][tn], af[tm], bf[tn]);
        }
        __syncthreads();
    }

#pragma unroll
    for (int tm = 0; tm < 2; ++tm) {
        const int row = m0 + wm * 32 + tm * 16 + g;
#pragma unroll
        for (int tn = 0; tn < TNW; ++tn) {
            const int n = n0 + wn * (TNW * 8) + tn * 8 + 2 * t;
            if (OUT_HALF ? (n < Npad) : (n < N)) {
                float v0 = 0.f, v1 = 0.f, v2 = 0.f, v3 = 0.f;
                if (n < N) {
                    float b0 = 0.f, b1 = 0.f;
                    if (bias) { b0 = bias[n]; b1 = bias[n + 1]; }
                    v0 = acc[tm][tn][0] + b0;
                    v1 = acc[tm][tn][1] + b1;
                    v2 = acc[tm][tn][2] + b0;
                    v3 = acc[tm][tn][3] + b1;
                    if (act_tanh) { v0 = ftanh(v0); v1 = ftanh(v1); v2 = ftanh(v2); v3 = ftanh(v3); }
                }
                if constexpr (OUT_HALF) {
                    __half* C = (__half*)Cv + (long)bz * cBatch;
                    *(__half2*)(C + (size_t)row * Npad + n)       = __floats2half2_rn(v0, v1);
                    *(__half2*)(C + (size_t)(row + 8) * Npad + n) = __floats2half2_rn(v2, v3);
                } else {
                    float* C = (float*)Cv + (long)bz * cBatch;
                    *(float2*)(C + (size_t)row * N + n)       = make_float2(v0, v1);
                    *(float2*)(C + (size_t)(row + 8) * N + n) = make_float2(v2, v3);
                }
            }
        }
    }
}

// ================= gi-GEMM with fused GRU gates epilogue (48-col tiles, 3 CTA/SM) ========
#define GSTR 120
#define GA_HALVES (128 * GSTR)
#define GB2_HALVES (48 * GSTR)                         // 5760 halves
#define GNT2 38                                        // 1824 / 48
#define GATES_SMEM (GA_HALVES * 2 + 2 * GB2_HALVES * 2 + (NCOLS + HPAD) * 4)  // 63488 B

__global__ void __launch_bounds__(256, 3) gemm_gates()
{
    extern __shared__ char gsm_raw[];
    __half* sA = (__half*)gsm_raw;                     // [128*120]
    __half* sB = sA + GA_HALVES;                       // [2][48*120]
    float* s_cr  = (float*)(sB + 2 * GB2_HALVES);      // [1824]
    float* s_bhn = s_cr + NCOLS;                       // [608]

    const int tid  = threadIdx.x;
    const int warp = tid >> 5, lane = tid & 31;
    const int wm = warp & 3, wn = warp >> 2;           // 4 x 2 warps; wn covers 24 cols
    const int g = lane >> 2, t = lane & 3;
    const int m0 = blockIdx.x * 128;

    const uint32_t sA32 = smem_to_u32(sA);
    const uint32_t sB32 = smem_to_u32(sB);

    // stage biases into smem (visible after first __syncthreads in the loop)
    for (int i = tid; i < NCOLS; i += 256) s_cr[i]  = g_c_r[i];
    for (int i = tid; i < HPAD;  i += 256) s_bhn[i] = g_bhn[i];

    auto issueB = [&](int nt) {
        const uint32_t bB = sB32 + (uint32_t)((nt & 1) * GB2_HALVES * 2);
#pragma unroll
        for (int i = 0; i < 3; ++i) {
            const int seg = tid + i * 256;             // 48*14 = 672
            if (seg < 672) {
                const int row = seg / 14, q = seg % 14;
                cp_async16(bB + (uint32_t)(row * (GSTR * 2) + q * 16),
                           g_Wc_h + (size_t)(nt * 48 + row) * KN_PAD + q * 8, 16);
            }
        }
        CP_COMMIT();
    };

    // prologue: A + B0 in group0, B1 in group1
#pragma unroll
    for (int i = 0; i < 7; ++i) {
        const int seg = tid + i * 256;                 // 128*14 = 1792
        const int row = seg / 14, q = seg % 14;
        cp_async16(sA32 + (uint32_t)(row * (GSTR * 2) + q * 16),
                   g_T_h + (size_t)(m0 + row) * KN_PAD + q * 8, 16);
    }
    {
#pragma unroll
        for (int i = 0; i < 3; ++i) {
            const int seg = tid + i * 256;
            if (seg < 672) {
                const int row = seg / 14, q = seg % 14;
                cp_async16(sB32 + (uint32_t)(row * (GSTR * 2) + q * 16),
                           g_Wc_h + (size_t)row * KN_PAD + q * 8, 16);
            }
        }
        CP_COMMIT();
    }
    issueB(1);

#pragma unroll 1
    for (int nt = 0; nt < GNT2; ++nt) {
        CP_WAIT(1);
        __syncthreads();

        const __half* a_ = sA;
        const __half* b_ = sB + (nt & 1) * GB2_HALVES;

        float acc[2][3][4];
#pragma unroll
        for (int i = 0; i < 2; ++i)
#pragma unroll
            for (int j = 0; j < 3; ++j)
#pragma unroll
                for (int q = 0; q < 4; ++q) acc[i][j][q] = 0.f;

#pragma unroll
        for (int kk = 0; kk < 7; ++kk) {
            const int col = kk * 16 + 2 * t;
            uint32_t af[2][4], bf[3][2];
#pragma unroll
            for (int tm = 0; tm < 2; ++tm) {
                const int r = wm * 32 + tm * 16 + g;
                af[tm][0] = *(const uint32_t*)(a_ + r * GSTR + col);
                af[tm][1] = *(const uint32_t*)(a_ + (r + 8) * GSTR + col);
                af[tm][2] = *(const uint32_t*)(a_ + r * GSTR + col + 8);
                af[tm][3] = *(const uint32_t*)(a_ + (r + 8) * GSTR + col + 8);
            }
#pragma unroll
            for (int tn = 0; tn < 3; ++tn) {
                const int n = wn * 24 + tn * 8 + g;
                bf[tn][0] = *(const uint32_t*)(b_ + n * GSTR + col);
                bf[tn][1] = *(const uint32_t*)(b_ + n * GSTR + col + 8);
            }
#pragma unroll
            for (int tm = 0; tm < 2; ++tm)
#pragma unroll
                for (int tn = 0; tn < 3; ++tn)
                    mma_f16(acc[tm][tn], af[tm], bf[tn]);
        }
        __syncthreads();
        if (nt + 2 < GNT2) issueB(nt + 2);
        else               CP_COMMIT();

        // ---- fused GRU gate epilogue: one 24-col group per warp ----
        {
            const int colbase = nt * 48 + wn * 24;     // multiple of 24; never straddles 912
            const int d = (colbase >= 912);
            const int grp = (colbase - d * 912) / 24;
            const int j0 = grp * 8 + 2 * t;
            const float bh0 = s_bhn[d * 304 + j0];
            const float bh1 = s_bhn[d * 304 + j0 + 1];
            const float cr0 = s_cr[colbase + 2 * t];
            const float cr1 = s_cr[colbase + 2 * t + 1];
            const float cz0 = s_cr[colbase + 8 + 2 * t];
            const float cz1 = s_cr[colbase + 8 + 2 * t + 1];
            const float cn0 = s_cr[colbase + 16 + 2 * t];
            const float cn1 = s_cr[colbase + 16 + 2 * t + 1];
            const bool valid = (j0 < 300);
#pragma unroll
            for (int tm = 0; tm < 2; ++tm) {
#pragma unroll
                for (int rr = 0; rr < 2; ++rr) {
                    const int bt = m0 + wm * 32 + tm * 16 + g + rr * 8;
                    float h0 = 0.f, h1 = 0.f;
                    if (valid) {
                        const int q0 = rr * 2;
                        const float r0 = fsigmoid(acc[tm][0][q0]     + cr0);
                        const float r1 = fsigmoid(acc[tm][0][q0 + 1] + cr1);
                        const float z0 = fsigmoid(acc[tm][1][q0]     + cz0);
                        const float z1 = fsigmoid(acc[tm][1][q0 + 1] + cz1);
                        const float n0_ = acc[tm][2][q0]     + cn0;
                        const float n1_ = acc[tm][2][q0 + 1] + cn1;
                        h0 = (1.f - z0) * ftanh(n0_ + r0 * bh0);
                        h1 = (1.f - z1) * ftanh(n1_ + r1 * bh1);
                    }
                    *(__half2*)(g_hidden_h + (size_t)bt * HPAD + d * 304 + j0) =
                        __floats2half2_rn(h0, h1);
                }
            }
        }
    }
}

// ================= fused scores GEMM + softmax + alpha (64-row l-blocks, 2 CTA/SM) ========
#define SC_STR 520
#define AT_BM 64
#define AT_PIPE_HALVES (2 * (AT_BM + 128) * ASTR)
#define AT_SC_HALVES   (AT_BM * SC_STR)
#define ATTN_SMEM ((AT_PIPE_HALVES + AT_SC_HALVES) * 2)

__global__ void __launch_bounds__(256, 2) attn_kernel()
{
    extern __shared__ __half asm_[];
    __half* sPipe = asm_;
    __half* ssc   = asm_ + AT_PIPE_HALVES;
    float*  part  = (float*)sPipe;                     // aliased after GEMM phase

    const int b  = blockIdx.x;
    const int lb = blockIdx.y;
    const __half* A = g_ctx_h + (size_t)(b * NLQ + lb * AT_BM) * KH_PAD;
    const __half* B = g_hid_h + (size_t)b * NT * KH_PAD;

    const int tid  = threadIdx.x;
    const int warp = tid >> 5, lane = tid & 31;
    const int wm = warp & 1, wn = warp >> 1;
    const int g = lane >> 2, t = lane & 3;

    const uint32_t p32 = smem_to_u32(sPipe);
    const int CH = (KH_PAD + 31) >> 5;

#pragma unroll 1
    for (int nt = 0; nt < 4; ++nt) {
        const __half* Bt = B + (size_t)(nt * 128) * KH_PAD;

        auto issue = [&](int c) {
            const int s = c & 1;
            const int kb = c << 5;
            const uint32_t aB = p32 + (uint32_t)s * ((AT_BM + 128) * ASTR * 2);
            const uint32_t bB = aB + (uint32_t)(AT_BM * ASTR * 2);
            {
                const int row = tid >> 2, q = tid & 3;
                const int k = kb + q * 8;
                const int va = (k + 8 <= KH_PAD);
                cp_async16(aB + (uint32_t)(row * (ASTR * 2) + q * 16),
                           va ? (const void*)(A + (size_t)row * KH_PAD + k) : (const void*)A,
                           va ? 16 : 0);
            }
#pragma unroll
            for (int i = 0; i < 2; ++i) {
                const int seg = tid + i * 256;
                const int row = seg >> 2, q = seg & 3;
                const int k = kb + q * 8;
                const int va = (k + 8 <= KH_PAD);
                cp_async16(bB + (uint32_t)(row * (ASTR * 2) + q * 16),
                           va ? (const void*)(Bt + (size_t)row * KH_PAD + k) : (const void*)Bt,
                           va ? 16 : 0);
            }
            CP_COMMIT();
        };

        float acc[2][4][4];
#pragma unroll
        for (int i = 0; i < 2; ++i)
#pragma unroll
            for (int j = 0; j < 4; ++j)
#pragma unroll
                for (int q = 0; q < 4; ++q) acc[i][j][q] = 0.f;

        issue(0);
        for (int c = 0; c < CH; ++c) {
            if (c + 1 < CH) { issue(c + 1); CP_WAIT(1); }
            else            { CP_WAIT(0); }
            __syncthreads();

            const __half* a_ = sPipe + (size_t)(c & 1) * ((AT_BM + 128) * ASTR);
            const __half* b_ = a_ + AT_BM * ASTR;

#pragma unroll
            for (int kk = 0; kk < 2; ++kk) {
                const int col = kk * 16 + 2 * t;
                uint32_t af[2][4], bf[4][2];
#pragma unroll
                for (int tm = 0; tm < 2; ++tm) {
                    const int r = wm * 32 + tm * 16 + g;
                    af[tm][0] = *(const uint32_t*)(a_ + r * ASTR + col);
                    af[tm][1] = *(const uint32_t*)(a_ + (r + 8) * ASTR + col);
                    af[tm][2] = *(const uint32_t*)(a_ + r * ASTR + col + 8);
                    af[tm][3] = *(const uint32_t*)(a_ + (r + 8) * ASTR + col + 8);
                }
#pragma unroll
                for (int tn = 0; tn < 4; ++tn) {
                    const int n = wn * 32 + tn * 8 + g;
                    bf[tn][0] = *(const uint32_t*)(b_ + n * ASTR + col);
                    bf[tn][1] = *(const uint32_t*)(b_ + n * ASTR + col + 8);
                }
#pragma unroll
                for (int tm = 0; tm < 2; ++tm)
#pragma unroll
                    for (int tn = 0; tn < 4; ++tn)
                        mma_f16(acc[tm][tn], af[tm], bf[tn]);
            }
            __syncthreads();
        }

#pragma unroll
        for (int tm = 0; tm < 2; ++tm) {
            const int row = wm * 32 + tm * 16 + g;
#pragma unroll
            for (int tn = 0; tn < 4; ++tn) {
                const int n = nt * 128 + wn * 32 + tn * 8 + 2 * t;
                *(__half2*)(ssc + (size_t)row * SC_STR + n) =
                    __floats2half2_rn(acc[tm][tn][0], acc[tm][tn][1]);
                *(__half2*)(ssc + (size_t)(row + 8) * SC_STR + n) =
                    __floats2half2_rn(acc[tm][tn][2], acc[tm][tn][3]);
            }
        }
        __syncthreads();
    }

    float pacc[16];
#pragma unroll
    for (int q = 0; q < 16; ++q) pacc[q] = 0.f;

#pragma unroll 1
    for (int i = 0; i < 8; ++i) {
        const int l = warp * 8 + i;
        const __half2* row2 = (const __half2*)(ssc + (size_t)l * SC_STR);
        float v[16], m = -1e30f;
#pragma unroll
        for (int q = 0; q < 8; ++q) {
            float2 f = __half22float2(row2[lane + 32 * q]);
            v[2 * q] = f.x; v[2 * q + 1] = f.y;
            m = fmaxf(m, fmaxf(f.x, f.y));
        }
#pragma unroll
        for (int o = 16; o; o >>= 1) m = fmaxf(m, __shfl_xor_sync(0xffffffffu, m, o));
        float e[16], s = 0.f;
#pragma unroll
        for (int q = 0; q < 16; ++q) { e[q] = fexp2(LOG2E * (v[q] - m)); s += e[q]; }
#pragma unroll
        for (int o = 16; o; o >>= 1) s += __shfl_xor_sync(0xffffffffu, s, o);
        const float rinv = frcp(s);
#pragma unroll
        for (int q = 0; q < 16; ++q) pacc[q] += e[q] * rinv;
    }
#pragma unroll
    for (int q = 0; q < 8; ++q) {
        const int c = 2 * (lane + 32 * q);
        part[warp * NT + c]     = pacc[2 * q];
        part[warp * NT + c + 1] = pacc[2 * q + 1];
    }
    __syncthreads();

#pragma unroll
    for (int h = 0; h < 2; ++h) {
        const int c = tid + h * 256;
        float s = 0.f;
#pragma unroll
        for (int w2 = 0; w2 < 8; ++w2) s += part[w2 * NT + c];
        g_alpha4[(b * 4 + lb) * NT + c] = s;
    }
}

// ---------------- unified fp32 -> fp16 conversions ----------------
#define CVT_N0 ((long)ROWS_BN * KN_PAD)
#define CVT_N1 ((long)NB * NLQ * KH_PAD)
#define CVT_N2 ((long)300 * KN_PAD)
#define CVT_N3 ((long)300 * HPAD)
#define CVT_TOTAL (CVT_N0 + CVT_N1 + CVT_N2 + CVT_N3)

__global__ void convert_all(const float* __restrict__ nodes,
                            const float* __restrict__ ctx,
                            const float* __restrict__ Wnode,
                            const float* __restrict__ Wout)
{
    for (long i = blockIdx.x * (long)blockDim.x + threadIdx.x; i < CVT_TOTAL;
         i += (long)gridDim.x * blockDim.x) {
        if (i < CVT_N0) {
            const long r = i / KN_PAD, k = i - r * KN_PAD;
            g_nodes_h[i] = __float2half((k < D_NODE) ? nodes[r * D_NODE + k] : 0.f);
        } else if (i < CVT_N0 + CVT_N1) {
            const long j = i - CVT_N0;
            const long r = j / KH_PAD, k = j - r * KH_PAD;
            g_ctx_h[j] = __float2half((k < D_HID) ? ctx[r * D_HID + k] : 0.f);
        } else if (i < CVT_N0 + CVT_N1 + CVT_N2) {
            const long j = i - CVT_N0 - CVT_N1;
            const long r = j / KN_PAD, k = j - r * KN_PAD;
            g_Wnode_h[j] = __float2half((k < D_NODE) ? Wnode[r * D_NODE + k] : 0.f);
        } else {
            const long j = i - CVT_N0 - CVT_N1 - CVT_N2;
            const long n = j / HPAD, k = j - n * HPAD;
            float v = 0.f;
            if (k < 300)                  v = Wout[n * 600 + k];
            else if (k >= 304 && k < 604) v = Wout[n * 600 + (k - 4)];
            g_Wout_h[j] = __float2half(v);
        }
    }
}

// ---------------- weight combine -> reordered Wc_h / c_r / bhn ----------------
#define CBJ 16
#define COMBINE_SMEM ((30000 + CBJ * 300) * 4)

__global__ void __launch_bounds__(256)
combine_kernel(const float* __restrict__ Wf, const float* __restrict__ bif,
               const float* __restrict__ bhf,
               const float* __restrict__ Wb, const float* __restrict__ bib,
               const float* __restrict__ bhb,
               const float* __restrict__ Wmean, const float* __restrict__ bmean)
{
    extern __shared__ float csm[];
    float* sW   = csm;
    float* srow = csm + 30000;

    const int j0 = blockIdx.x * CBJ;
    const int tid = threadIdx.x;

    for (int i = tid; i < 30000; i += 256) sW[i] = Wmean[i];
    for (int i = tid; i < CBJ * 300; i += 256) {
        const int jj = i / 300, dcol = i % 300;
        const int cnew = j0 + jj;
        const int d = (cnew >= 912);
        const int rem = cnew - d * 912;
        const int grp = rem / 24, gate = (rem % 24) >> 3, pos = rem & 7;
        const int h = grp * 8 + pos;
        float v = 0.f;
        if (h < 300) {
            const int src = gate * 300 + h;
            v = d ? Wb[src * 300 + dcol] : Wf[src * 300 + dcol];
        }
        srow[i] = v;
    }
    __syncthreads();

    for (int idx = tid; idx < CBJ * KN_PAD; idx += 256) {
        const int jj = idx / KN_PAD, k = idx % KN_PAD;
        const int cnew = j0 + jj;
        float s = 0.f;
        if (k < 100) {
            const float* wr = srow + jj * 300;
#pragma unroll 4
            for (int dd = 0; dd < 300; ++dd) s = fmaf(wr[dd], sW[dd * 100 + k], s);
        }
        g_Wc_h[(size_t)cnew * KN_PAD + k] = __float2half(s);
    }
    if (tid < CBJ) {
        const int cnew = j0 + tid;
        const int d = (cnew >= 912);
        const int rem = cnew - d * 912;
        const int grp = rem / 24, gate = (rem % 24) >> 3, pos = rem & 7;
        const int h = grp * 8 + pos;
        float s = 0.f;
        if (h < 300) {
            const int src = gate * 300 + h;
            const float* bih = d ? bib : bif;
            const float* bhh = d ? bhb : bhf;
            s = bih[src];
            const float* wr = srow + tid * 300;
            for (int dd = 0; dd < 300; ++dd) s = fmaf(wr[dd], bmean[dd], s);
            if (gate < 2) s += bhh[src];
            if (gate == 2) g_bhn[d * 304 + h] = bhh[600 + h];
        } else {
            if (gate == 2) g_bhn[d * 304 + h] = 0.f;
        }
        g_c_r[cnew] = s;
    }
}

// ---------------- per-triple averaged node vectors ----------------
__global__ void __launch_bounds__(224) tri_avg(const int* __restrict__ tri)
{
    const int r = threadIdx.x / 28, c = threadIdx.x % 28;
    const int bt = blockIdx.x * 8 + r;
    const int b = bt >> 9;
    const int hN = tri[bt * 3 + 0];
    const int tN = tri[bt * 3 + 2];
    const uint2 vh = ((const uint2*)(g_nodes_h + (size_t)(b * NNODE + hN) * KN_PAD))[c];
    const uint2 vt = ((const uint2*)(g_nodes_h + (size_t)(b * NNODE + tN) * KN_PAD))[c];
    const float2 hx = __half22float2(*(const __half2*)&vh.x);
    const float2 hy = __half22float2(*(const __half2*)&vh.y);
    const float2 tx = __half22float2(*(const __half2*)&vt.x);
    const float2 ty = __half22float2(*(const __half2*)&vt.y);
    __half2 o0 = __floats2half2_rn(0.5f * (hx.x + tx.x), 0.5f * (hx.y + tx.y));
    __half2 o1 = __floats2half2_rn(0.5f * (hy.x + ty.x), 0.5f * (hy.y + ty.y));
    uint2 o;
    o.x = *(uint32_t*)&o0;
    o.y = *(uint32_t*)&o1;
    ((uint2*)(g_T_h + (size_t)bt * KN_PAD))[c] = o;
}

// ---------------- rep = alpha @ hid_ ; layernorm ----------------
__global__ void __launch_bounds__(320) rep_ln_kernel(const float* __restrict__ gamma,
                                                     const float* __restrict__ beta,
                                                     float* __restrict__ out)
{
    const int b = blockIdx.x;
    __shared__ float sal[NT];
    __shared__ float red[2][10];
    const int tid = threadIdx.x;

    for (int t = tid; t < NT; t += 320)
        sal[t] = g_alpha4[(b * 4 + 0) * NT + t] + g_alpha4[(b * 4 + 1) * NT + t]
               + g_alpha4[(b * 4 + 2) * NT + t] + g_alpha4[(b * 4 + 3) * NT + t];
    __syncthreads();

    float acc = 0.f;
    const __half* H = g_hid_h + (size_t)b * NT * KH_PAD;
    if (tid < D_HID) {
        for (int t = 0; t < NT; ++t)
            acc = fmaf(sal[t], __half2float(H[(size_t)t * KH_PAD + tid]), acc);
    }
    float v1 = (tid < D_HID) ? acc : 0.f;
    float v2 = (tid < D_HID) ? acc * acc : 0.f;
#pragma unroll
    for (int o = 16; o; o >>= 1) {
        v1 += __shfl_xor_sync(0xffffffffu, v1, o);
        v2 += __shfl_xor_sync(0xffffffffu, v2, o);
    }
    const int wid = tid >> 5, lane = tid & 31;
    if (lane == 0) { red[0][wid] = v1; red[1][wid] = v2; }
    __syncthreads();
    if (tid == 0) {
        float s1 = 0.f, s2 = 0.f;
        for (int w = 0; w < 10; ++w) { s1 += red[0][w]; s2 += red[1][w]; }
        red[0][0] = s1 / (float)D_HID;
        red[1][0] = s2 / (float)D_HID;
    }
    __syncthreads();
    if (tid < D_HID) {
        float mu = red[0][0];
        float var = red[1][0] - mu * mu;
        out[b * D_HID + tid] = (acc - mu) * rsqrtf(var + 1e-5f) * gamma[tid] + beta[tid];
    }
}

__global__ void zero_tail_kernel(float* __restrict__ out, long start, long end)
{
    long i = start + (long)blockIdx.x * blockDim.x + threadIdx.x;
    if (i < end) out[i] = 0.f;
}

// ---------------- launch ----------------
extern "C" void kernel_launch(void* const* d_in, const int* in_sizes, int n_in,
                              void* d_out, int out_size)
{
    const int o = (in_sizes[3] == 1) ? 1 : 0;

    const float* nodes  = (const float*)d_in[0];
    const float* ctx    = (const float*)d_in[1];
    const int*   tri    = (const int*)d_in[2];
    const float* W_mean = (const float*)d_in[3 + o];
    const float* b_mean = (const float*)d_in[4 + o];
    const float* W_ih_f = (const float*)d_in[5 + o];
    const float* b_ih_f = (const float*)d_in[6 + o];
    const float* b_hh_f = (const float*)d_in[7 + o];
    const float* W_ih_b = (const float*)d_in[8 + o];
    const float* b_ih_b = (const float*)d_in[9 + o];
    const float* b_hh_b = (const float*)d_in[10 + o];
    const float* W_out  = (const float*)d_in[11 + o];
    const float* b_out  = (const float*)d_in[12 + o];
    const float* W_node = (const float*)d_in[13 + o];
    const float* b_node = (const float*)d_in[14 + o];
    const float* gamma  = (const float*)d_in[15 + o];
    const float* beta   = (const float*)d_in[16 + o];
    float* out = (float*)d_out;

    __half *pNodesH, *pWnodeH, *pWoutH, *pHiddenH, *pHidH;
    cudaGetSymbolAddress((void**)&pNodesH,  g_nodes_h);
    cudaGetSymbolAddress((void**)&pWnodeH,  g_Wnode_h);
    cudaGetSymbolAddress((void**)&pWoutH,   g_Wout_h);
    cudaGetSymbolAddress((void**)&pHiddenH, g_hidden_h);
    cudaGetSymbolAddress((void**)&pHidH,    g_hid_h);

    cudaFuncSetAttribute(combine_kernel, cudaFuncAttributeMaxDynamicSharedMemorySize, COMBINE_SMEM);
    cudaFuncSetAttribute(gemm_gates,     cudaFuncAttributeMaxDynamicSharedMemorySize, GATES_SMEM);
    cudaFuncSetAttribute(attn_kernel,    cudaFuncAttributeMaxDynamicSharedMemorySize, ATTN_SMEM);

    convert_all<<<8192, 256>>>(nodes, ctx, W_node, W_out);

    combine_kernel<<<NCOLS / CBJ, 256, COMBINE_SMEM>>>(
        W_ih_f, b_ih_f, b_hh_f, W_ih_b, b_ih_b, b_hh_b, W_mean, b_mean);

    tri_avg<<<ROWS_BT / 8, 224>>>(tri);

    gemm_gates<<<ROWS_BT / 128, 256, GATES_SMEM>>>();

    // node_feature: cols 0-255 (TNW=8) + tail 256-303 (TNW=3)
    {
        dim3 grid(2, ROWS_BN / BM, 1);
        gemm_f16<false, 8><<<grid, 256>>>(pNodesH, 0, pWnodeH, 0, out + OUT_PATH, 0,
                                          ROWS_BN, D_HID, D_HID, KN_PAD, b_node, 0, 0);
        dim3 gridT(1, ROWS_BN / BM, 1);
        gemm_f16<false, 3><<<gridT, 256>>>(pNodesH, 0, pWnodeH, 0, out + OUT_PATH, 0,
                                           ROWS_BN, D_HID, D_HID, KN_PAD, b_node, 0, 256);
    }
    // hid_: cols 0-255 (TNW=8) + tail 256-303 (TNW=3)
    {
        dim3 grid(2, ROWS_BT / BM, 1);
        gemm_f16<true, 8><<<grid, 256>>>(pHiddenH, 0, pWoutH, 0, pHidH, 0,
                                         ROWS_BT, D_HID, KH_PAD, HPAD, b_out, 1, 0);
        dim3 gridT(1, ROWS_BT / BM, 1);
        gemm_f16<true, 3><<<gridT, 256>>>(pHiddenH, 0, pWoutH, 0, pHidH, 0,
                                          ROWS_BT, D_HID, KH_PAD, HPAD, b_out, 1, 256);
    }
    attn_kernel<<<dim3(NB, 4), 256, ATTN_SMEM>>>();

    rep_ln_kernel<<<NB, 320>>>(gamma, beta, out);

    {
        long start = OUT_TAIL_START;
        long end = (long)out_size;
        if (end > start) {
            long n = end - start;
            int blocks = (int)((n + 255) / 256);
            zero_tail_kernel<<<blocks, 256>>>(out, start, end);
        }
    }
}

// round 15
// speedup vs baseline: 2.3109x; 1.0233x over previous
#include <cuda_runtime.h>
#include <cuda_fp16.h>
#include <math.h>
#include <stdint.h>

// ---------------- problem constants ----------------
#define D_NODE 100
#define D_HID  300
#define NB     128
#define NT     512
#define NNODE  256
#define NLQ    256
#define ROWS_BT (NB*NT)     // 65536
#define ROWS_BN (NB*NNODE)  // 32768

#define KN_PAD 112
#define KH_PAD 304
#define HPAD   608          // hidden padded: [fwd 304 | bwd 304]
#define NCOLS  1824         // reordered gate cols

#define OUT_PATH   (NB*D_HID)
#define OUT_NODEF  ((long)ROWS_BN*D_HID)
#define OUT_TAIL_START (OUT_PATH + OUT_NODEF)

// ---------------- device scratch ----------------
__device__ __half g_nodes_h[(size_t)ROWS_BN * KN_PAD];
__device__ __half g_ctx_h[(size_t)NB * NLQ * KH_PAD];
__device__ __half g_T_h[(size_t)ROWS_BT * KN_PAD];
__device__ __half g_Wc_h[NCOLS * KN_PAD];
__device__ float  g_c_r[NCOLS];
__device__ float  g_bhn[HPAD];
__device__ __half g_Wnode_h[300 * KN_PAD];
__device__ __half g_Wout_h[300 * HPAD];
__device__ __half g_hidden_h[(size_t)ROWS_BT * HPAD];
__device__ __half g_hid_h[(size_t)ROWS_BT * KH_PAD];
__device__ float  g_alpha4[NB * 4 * NT];

// ---------------- PTX helpers ----------------
__device__ __forceinline__ uint32_t smem_to_u32(const void* p) {
    uint32_t a;
    asm("{ .reg .u64 t; cvta.to.shared.u64 t, %1; cvt.u32.u64 %0, t; }" : "=r"(a) : "l"(p));
    return a;
}
__device__ __forceinline__ void mma_f16(float* d, const uint32_t* a, const uint32_t* b) {
    asm volatile(
        "mma.sync.aligned.m16n8k16.row.col.f32.f16.f16.f32 "
        "{%0,%1,%2,%3}, {%4,%5,%6,%7}, {%8,%9}, {%0,%1,%2,%3};"
        : "+f"(d[0]), "+f"(d[1]), "+f"(d[2]), "+f"(d[3])
        : "r"(a[0]), "r"(a[1]), "r"(a[2]), "r"(a[3]), "r"(b[0]), "r"(b[1]));
}
__device__ __forceinline__ void cp_async16(uint32_t dst, const void* src, int src_size) {
    asm volatile("cp.async.cg.shared.global [%0], [%1], 16, %2;"
        :: "r"(dst), "l"(src), "r"(src_size) : "memory");
}
#define CP_COMMIT() asm volatile("cp.async.commit_group;" ::: "memory")
#define CP_WAIT(n)  asm volatile("cp.async.wait_group %0;" :: "n"(n) : "memory")

__device__ __forceinline__ float fexp2(float x) {
    float y; asm("ex2.approx.f32 %0, %1;" : "=f"(y) : "f"(x)); return y;
}
__device__ __forceinline__ float frcp(float x) {
    float y; asm("rcp.approx.f32 %0, %1;" : "=f"(y) : "f"(x)); return y;
}
#define LOG2E 1.4426950408889634f
__device__ __forceinline__ float fsigmoid(float x) { return frcp(1.f + fexp2(-LOG2E * x)); }
__device__ __forceinline__ float ftanh(float x)    { return 2.f * frcp(1.f + fexp2(-2.f * LOG2E * x)) - 1.f; }

// ================= generic fp16 mma GEMM (compile-time warp-width TNW) =================
#define BM 128
#define ASTR 40

template <bool OUT_HALF, int TNW>
__global__ void __launch_bounds__(256, 2)
gemm_f16(const __half* __restrict__ A, long aBatch,
         const __half* __restrict__ W, long wBatch,
         void* __restrict__ Cv, long cBatch,
         int M, int N, int Npad, int K,
         const float* __restrict__ bias, int act_tanh, int nbase)
{
    constexpr int BNE = TNW * 16;
    __shared__ __half sA[2][BM * ASTR];
    __shared__ __half sB[2][BM * ASTR];

    const int bz = blockIdx.z;
    A += (long)bz * aBatch; W += (long)bz * wBatch;

    const int tid  = threadIdx.x;
    const int warp = tid >> 5, lane = tid & 31;
    const int wm = warp & 3, wn = warp >> 2;
    const int g = lane >> 2, t = lane & 3;

    const int m0 = blockIdx.y * BM;
    const int n0 = nbase + blockIdx.x * BNE;
    const int CH = (K + 31) >> 5;

    const uint32_t sA32 = smem_to_u32(sA);
    const uint32_t sB32 = smem_to_u32(sB);

    float acc[2][TNW][4];
#pragma unroll
    for (int i = 0; i < 2; ++i)
#pragma unroll
        for (int j = 0; j < TNW; ++j)
#pragma unroll
            for (int q = 0; q < 4; ++q) acc[i][j][q] = 0.f;

    auto issue = [&](int c) {
        const int s = c & 1;
        const int kb = c << 5;
        const uint32_t aB = sA32 + (uint32_t)s * (BM * ASTR * 2);
        const uint32_t bB = sB32 + (uint32_t)s * (BM * ASTR * 2);
#pragma unroll
        for (int i = 0; i < 2; ++i) {
            const int seg = tid + i * 256;
            const int row = seg >> 2, q = seg & 3;
            const int k = kb + q * 8;
            const int va = (k + 8 <= K);
            cp_async16(aB + (uint32_t)(row * (ASTR * 2) + q * 16),
                       va ? (const void*)(A + (long)(m0 + row) * K + k) : (const void*)A,
                       va ? 16 : 0);
            const int vb = va && (row < BNE) && (n0 + row < N);
            cp_async16(bB + (uint32_t)(row * (ASTR * 2) + q * 16),
                       vb ? (const void*)(W + (long)(n0 + row) * K + k) : (const void*)W,
                       vb ? 16 : 0);
        }
        CP_COMMIT();
    };

    issue(0);
    for (int c = 0; c < CH; ++c) {
        if (c + 1 < CH) { issue(c + 1); CP_WAIT(1); }
        else            { CP_WAIT(0); }
        __syncthreads();

        const __half* a_ = sA[c & 1];
        const __half* b_ = sB[c & 1];

#pragma unroll
        for (int kk = 0; kk < 2; ++kk) {
            const int col = kk * 16 + 2 * t;
            uint32_t af[2][4], bf[TNW][2];
#pragma unroll
            for (int tm = 0; tm < 2; ++tm) {
                const int r = wm * 32 + tm * 16 + g;
                af[tm][0] = *(const uint32_t*)(a_ + r * ASTR + col);
                af[tm][1] = *(const uint32_t*)(a_ + (r + 8) * ASTR + col);
                af[tm][2] = *(const uint32_t*)(a_ + r * ASTR + col + 8);
                af[tm][3] = *(const uint32_t*)(a_ + (r + 8) * ASTR + col + 8);
            }
#pragma unroll
            for (int tn = 0; tn < TNW; ++tn) {
                const int n = wn * (TNW * 8) + tn * 8 + g;
                bf[tn][0] = *(const uint32_t*)(b_ + n * ASTR + col);
                bf[tn][1] = *(const uint32_t*)(b_ + n * ASTR + col + 8);
            }
#pragma unroll
            for (int tm = 0; tm < 2; ++tm)
#pragma unroll
                for (int tn = 0; tn < TNW; ++tn)
                    mma_f16(acc[tm][tn], af[tm], bf[tn]);
        }
        __syncthreads();
    }

#pragma unroll
    for (int tm = 0; tm < 2; ++tm) {
        const int row = m0 + wm * 32 + tm * 16 + g;
#pragma unroll
        for (int tn = 0; tn < TNW; ++tn) {
            const int n = n0 + wn * (TNW * 8) + tn * 8 + 2 * t;
            if (OUT_HALF ? (n < Npad) : (n < N)) {
                float v0 = 0.f, v1 = 0.f, v2 = 0.f, v3 = 0.f;
                if (n < N) {
                    float b0 = 0.f, b1 = 0.f;
                    if (bias) { b0 = bias[n]; b1 = bias[n + 1]; }
                    v0 = acc[tm][tn][0] + b0;
                    v1 = acc[tm][tn][1] + b1;
                    v2 = acc[tm][tn][2] + b0;
                    v3 = acc[tm][tn][3] + b1;
                    if (act_tanh) { v0 = ftanh(v0); v1 = ftanh(v1); v2 = ftanh(v2); v3 = ftanh(v3); }
                }
                if constexpr (OUT_HALF) {
                    __half* C = (__half*)Cv + (long)bz * cBatch;
                    *(__half2*)(C + (size_t)row * Npad + n)       = __floats2half2_rn(v0, v1);
                    *(__half2*)(C + (size_t)(row + 8) * Npad + n) = __floats2half2_rn(v2, v3);
                } else {
                    float* C = (float*)Cv + (long)bz * cBatch;
                    *(float2*)(C + (size_t)row * N + n)       = make_float2(v0, v1);
                    *(float2*)(C + (size_t)(row + 8) * N + n) = make_float2(v2, v3);
                }
            }
        }
    }
}

// ================= gi-GEMM + fused GRU gates (BM=256, 48-col tiles, 1 wave) =============
#define GSTR 120
#define GBM 256
#define GA_HALVES (GBM * GSTR)                         // 30720 halves = 61440 B
#define GB2_HALVES (48 * GSTR)                         // 5760 halves
#define GNT2 38                                        // 1824 / 48
#define GATES_SMEM (GA_HALVES * 2 + 2 * GB2_HALVES * 2 + (NCOLS + HPAD) * 4)  // 94208 B

__global__ void __launch_bounds__(256, 2) gemm_gates()
{
    extern __shared__ char gsm_raw[];
    __half* sA = (__half*)gsm_raw;                     // [256*120]
    __half* sB = sA + GA_HALVES;                       // [2][48*120]
    float* s_cr  = (float*)(sB + 2 * GB2_HALVES);      // [1824]
    float* s_bhn = s_cr + NCOLS;                       // [608]

    const int tid  = threadIdx.x;
    const int warp = tid >> 5, lane = tid & 31;
    const int wm = warp & 3, wn = warp >> 2;           // wm covers 64 rows; wn covers 24 cols
    const int g = lane >> 2, t = lane & 3;
    const int m0 = blockIdx.x * GBM;

    const uint32_t sA32 = smem_to_u32(sA);
    const uint32_t sB32 = smem_to_u32(sB);

    // stage biases into smem
    for (int i = tid; i < NCOLS; i += 256) s_cr[i]  = g_c_r[i];
    for (int i = tid; i < HPAD;  i += 256) s_bhn[i] = g_bhn[i];

    auto issueB = [&](int nt) {
        const uint32_t bB = sB32 + (uint32_t)((nt & 1) * GB2_HALVES * 2);
#pragma unroll
        for (int i = 0; i < 3; ++i) {
            const int seg = tid + i * 256;             // 48*14 = 672
            if (seg < 672) {
                const int row = seg / 14, q = seg % 14;
                cp_async16(bB + (uint32_t)(row * (GSTR * 2) + q * 16),
                           g_Wc_h + (size_t)(nt * 48 + row) * KN_PAD + q * 8, 16);
            }
        }
        CP_COMMIT();
    };

    // prologue: A (256 rows x 14 chunks = 3584 segs) + B0 in group0, B1 in group1
#pragma unroll
    for (int i = 0; i < 14; ++i) {
        const int seg = tid + i * 256;
        const int row = seg / 14, q = seg % 14;
        cp_async16(sA32 + (uint32_t)(row * (GSTR * 2) + q * 16),
                   g_T_h + (size_t)(m0 + row) * KN_PAD + q * 8, 16);
    }
    {
#pragma unroll
        for (int i = 0; i < 3; ++i) {
            const int seg = tid + i * 256;
            if (seg < 672) {
                const int row = seg / 14, q = seg % 14;
                cp_async16(sB32 + (uint32_t)(row * (GSTR * 2) + q * 16),
                           g_Wc_h + (size_t)row * KN_PAD + q * 8, 16);
            }
        }
        CP_COMMIT();
    }
    issueB(1);

#pragma unroll 1
    for (int nt = 0; nt < GNT2; ++nt) {
        CP_WAIT(1);
        __syncthreads();

        const __half* a_ = sA;
        const __half* b_ = sB + (nt & 1) * GB2_HALVES;

        float acc[4][3][4];
#pragma unroll
        for (int i = 0; i < 4; ++i)
#pragma unroll
            for (int j = 0; j < 3; ++j)
#pragma unroll
                for (int q = 0; q < 4; ++q) acc[i][j][q] = 0.f;

#pragma unroll
        for (int kk = 0; kk < 7; ++kk) {
            const int col = kk * 16 + 2 * t;
            uint32_t af[4][4], bf[3][2];
#pragma unroll
            for (int tm = 0; tm < 4; ++tm) {
                const int r = wm * 64 + tm * 16 + g;
                af[tm][0] = *(const uint32_t*)(a_ + r * GSTR + col);
                af[tm][1] = *(const uint32_t*)(a_ + (r + 8) * GSTR + col);
                af[tm][2] = *(const uint32_t*)(a_ + r * GSTR + col + 8);
                af[tm][3] = *(const uint32_t*)(a_ + (r + 8) * GSTR + col + 8);
            }
#pragma unroll
            for (int tn = 0; tn < 3; ++tn) {
                const int n = wn * 24 + tn * 8 + g;
                bf[tn][0] = *(const uint32_t*)(b_ + n * GSTR + col);
                bf[tn][1] = *(const uint32_t*)(b_ + n * GSTR + col + 8);
            }
#pragma unroll
            for (int tm = 0; tm < 4; ++tm)
#pragma unroll
                for (int tn = 0; tn < 3; ++tn)
                    mma_f16(acc[tm][tn], af[tm], bf[tn]);
        }
        __syncthreads();
        if (nt + 2 < GNT2) issueB(nt + 2);
        else               CP_COMMIT();

        // ---- fused GRU gate epilogue: one 24-col group per warp, 64 rows ----
        {
            const int colbase = nt * 48 + wn * 24;     // multiple of 24; never straddles 912
            const int d = (colbase >= 912);
            const int grp = (colbase - d * 912) / 24;
            const int j0 = grp * 8 + 2 * t;
            const float bh0 = s_bhn[d * 304 + j0];
            const float bh1 = s_bhn[d * 304 + j0 + 1];
            const float cr0 = s_cr[colbase + 2 * t];
            const float cr1 = s_cr[colbase + 2 * t + 1];
            const float cz0 = s_cr[colbase + 8 + 2 * t];
            const float cz1 = s_cr[colbase + 8 + 2 * t + 1];
            const float cn0 = s_cr[colbase + 16 + 2 * t];
            const float cn1 = s_cr[colbase + 16 + 2 * t + 1];
            const bool valid = (j0 < 300);
#pragma unroll
            for (int tm = 0; tm < 4; ++tm) {
#pragma unroll
                for (int rr = 0; rr < 2; ++rr) {
                    const int bt = m0 + wm * 64 + tm * 16 + g + rr * 8;
                    float h0 = 0.f, h1 = 0.f;
                    if (valid) {
                        const int q0 = rr * 2;
                        const float r0 = fsigmoid(acc[tm][0][q0]     + cr0);
                        const float r1 = fsigmoid(acc[tm][0][q0 + 1] + cr1);
                        const float z0 = fsigmoid(acc[tm][1][q0]     + cz0);
                        const float z1 = fsigmoid(acc[tm][1][q0 + 1] + cz1);
                        const float n0_ = acc[tm][2][q0]     + cn0;
                        const float n1_ = acc[tm][2][q0 + 1] + cn1;
                        h0 = (1.f - z0) * ftanh(n0_ + r0 * bh0);
                        h1 = (1.f - z1) * ftanh(n1_ + r1 * bh1);
                    }
                    *(__half2*)(g_hidden_h + (size_t)bt * HPAD + d * 304 + j0) =
                        __floats2half2_rn(h0, h1);
                }
            }
        }
    }
}

// ================= fused scores GEMM + softmax + alpha (64-row l-blocks, 2 CTA/SM) ========
#define SC_STR 520
#define AT_BM 64
#define AT_PIPE_HALVES (2 * (AT_BM + 128) * ASTR)
#define AT_SC_HALVES   (AT_BM * SC_STR)
#define ATTN_SMEM ((AT_PIPE_HALVES + AT_SC_HALVES) * 2)

__global__ void __launch_bounds__(256, 2) attn_kernel()
{
    extern __shared__ __half asm_[];
    __half* sPipe = asm_;
    __half* ssc   = asm_ + AT_PIPE_HALVES;
    float*  part  = (float*)sPipe;                     // aliased after GEMM phase

    const int b  = blockIdx.x;
    const int lb = blockIdx.y;
    const __half* A = g_ctx_h + (size_t)(b * NLQ + lb * AT_BM) * KH_PAD;
    const __half* B = g_hid_h + (size_t)b * NT * KH_PAD;

    const int tid  = threadIdx.x;
    const int warp = tid >> 5, lane = tid & 31;
    const int wm = warp & 1, wn = warp >> 1;
    const int g = lane >> 2, t = lane & 3;

    const uint32_t p32 = smem_to_u32(sPipe);
    const int CH = (KH_PAD + 31) >> 5;

#pragma unroll 1
    for (int nt = 0; nt < 4; ++nt) {
        const __half* Bt = B + (size_t)(nt * 128) * KH_PAD;

        auto issue = [&](int c) {
            const int s = c & 1;
            const int kb = c << 5;
            const uint32_t aB = p32 + (uint32_t)s * ((AT_BM + 128) * ASTR * 2);
            const uint32_t bB = aB + (uint32_t)(AT_BM * ASTR * 2);
            {
                const int row = tid >> 2, q = tid & 3;
                const int k = kb + q * 8;
                const int va = (k + 8 <= KH_PAD);
                cp_async16(aB + (uint32_t)(row * (ASTR * 2) + q * 16),
                           va ? (const void*)(A + (size_t)row * KH_PAD + k) : (const void*)A,
                           va ? 16 : 0);
            }
#pragma unroll
            for (int i = 0; i < 2; ++i) {
                const int seg = tid + i * 256;
                const int row = seg >> 2, q = seg & 3;
                const int k = kb + q * 8;
                const int va = (k + 8 <= KH_PAD);
                cp_async16(bB + (uint32_t)(row * (ASTR * 2) + q * 16),
                           va ? (const void*)(Bt + (size_t)row * KH_PAD + k) : (const void*)Bt,
                           va ? 16 : 0);
            }
            CP_COMMIT();
        };

        float acc[2][4][4];
#pragma unroll
        for (int i = 0; i < 2; ++i)
#pragma unroll
            for (int j = 0; j < 4; ++j)
#pragma unroll
                for (int q = 0; q < 4; ++q) acc[i][j][q] = 0.f;

        issue(0);
        for (int c = 0; c < CH; ++c) {
            if (c + 1 < CH) { issue(c + 1); CP_WAIT(1); }
            else            { CP_WAIT(0); }
            __syncthreads();

            const __half* a_ = sPipe + (size_t)(c & 1) * ((AT_BM + 128) * ASTR);
            const __half* b_ = a_ + AT_BM * ASTR;

#pragma unroll
            for (int kk = 0; kk < 2; ++kk) {
                const int col = kk * 16 + 2 * t;
                uint32_t af[2][4], bf[4][2];
#pragma unroll
                for (int tm = 0; tm < 2; ++tm) {
                    const int r = wm * 32 + tm * 16 + g;
                    af[tm][0] = *(const uint32_t*)(a_ + r * ASTR + col);
                    af[tm][1] = *(const uint32_t*)(a_ + (r + 8) * ASTR + col);
                    af[tm][2] = *(const uint32_t*)(a_ + r * ASTR + col + 8);
                    af[tm][3] = *(const uint32_t*)(a_ + (r + 8) * ASTR + col + 8);
                }
#pragma unroll
                for (int tn = 0; tn < 4; ++tn) {
                    const int n = wn * 32 + tn * 8 + g;
                    bf[tn][0] = *(const uint32_t*)(b_ + n * ASTR + col);
                    bf[tn][1] = *(const uint32_t*)(b_ + n * ASTR + col + 8);
                }
#pragma unroll
                for (int tm = 0; tm < 2; ++tm)
#pragma unroll
                    for (int tn = 0; tn < 4; ++tn)
                        mma_f16(acc[tm][tn], af[tm], bf[tn]);
            }
            __syncthreads();
        }

#pragma unroll
        for (int tm = 0; tm < 2; ++tm) {
            const int row = wm * 32 + tm * 16 + g;
#pragma unroll
            for (int tn = 0; tn < 4; ++tn) {
                const int n = nt * 128 + wn * 32 + tn * 8 + 2 * t;
                *(__half2*)(ssc + (size_t)row * SC_STR + n) =
                    __floats2half2_rn(acc[tm][tn][0], acc[tm][tn][1]);
                *(__half2*)(ssc + (size_t)(row + 8) * SC_STR + n) =
                    __floats2half2_rn(acc[tm][tn][2], acc[tm][tn][3]);
            }
        }
        __syncthreads();
    }

    float pacc[16];
#pragma unroll
    for (int q = 0; q < 16; ++q) pacc[q] = 0.f;

#pragma unroll 1
    for (int i = 0; i < 8; ++i) {
        const int l = warp * 8 + i;
        const __half2* row2 = (const __half2*)(ssc + (size_t)l * SC_STR);
        float v[16], m = -1e30f;
#pragma unroll
        for (int q = 0; q < 8; ++q) {
            float2 f = __half22float2(row2[lane + 32 * q]);
            v[2 * q] = f.x; v[2 * q + 1] = f.y;
            m = fmaxf(m, fmaxf(f.x, f.y));
        }
#pragma unroll
        for (int o = 16; o; o >>= 1) m = fmaxf(m, __shfl_xor_sync(0xffffffffu, m, o));
        float e[16], s = 0.f;
#pragma unroll
        for (int q = 0; q < 16; ++q) { e[q] = fexp2(LOG2E * (v[q] - m)); s += e[q]; }
#pragma unroll
        for (int o = 16; o; o >>= 1) s += __shfl_xor_sync(0xffffffffu, s, o);
        const float rinv = frcp(s);
#pragma unroll
        for (int q = 0; q < 16; ++q) pacc[q] += e[q] * rinv;
    }
#pragma unroll
    for (int q = 0; q < 8; ++q) {
        const int c = 2 * (lane + 32 * q);
        part[warp * NT + c]     = pacc[2 * q];
        part[warp * NT + c + 1] = pacc[2 * q + 1];
    }
    __syncthreads();

#pragma unroll
    for (int h = 0; h < 2; ++h) {
        const int c = tid + h * 256;
        float s = 0.f;
#pragma unroll
        for (int w2 = 0; w2 < 8; ++w2) s += part[w2 * NT + c];
        g_alpha4[(b * 4 + lb) * NT + c] = s;
    }
}

// ---------------- unified fp32 -> fp16 conversions ----------------
#define CVT_N0 ((long)ROWS_BN * KN_PAD)
#define CVT_N1 ((long)NB * NLQ * KH_PAD)
#define CVT_N2 ((long)300 * KN_PAD)
#define CVT_N3 ((long)300 * HPAD)
#define CVT_TOTAL (CVT_N0 + CVT_N1 + CVT_N2 + CVT_N3)

__global__ void convert_all(const float* __restrict__ nodes,
                            const float* __restrict__ ctx,
                            const float* __restrict__ Wnode,
                            const float* __restrict__ Wout)
{
    for (long i = blockIdx.x * (long)blockDim.x + threadIdx.x; i < CVT_TOTAL;
         i += (long)gridDim.x * blockDim.x) {
        if (i < CVT_N0) {
            const long r = i / KN_PAD, k = i - r * KN_PAD;
            g_nodes_h[i] = __float2half((k < D_NODE) ? nodes[r * D_NODE + k] : 0.f);
        } else if (i < CVT_N0 + CVT_N1) {
            const long j = i - CVT_N0;
            const long r = j / KH_PAD, k = j - r * KH_PAD;
            g_ctx_h[j] = __float2half((k < D_HID) ? ctx[r * D_HID + k] : 0.f);
        } else if (i < CVT_N0 + CVT_N1 + CVT_N2) {
            const long j = i - CVT_N0 - CVT_N1;
            const long r = j / KN_PAD, k = j - r * KN_PAD;
            g_Wnode_h[j] = __float2half((k < D_NODE) ? Wnode[r * D_NODE + k] : 0.f);
        } else {
            const long j = i - CVT_N0 - CVT_N1 - CVT_N2;
            const long n = j / HPAD, k = j - n * HPAD;
            float v = 0.f;
            if (k < 300)                  v = Wout[n * 600 + k];
            else if (k >= 304 && k < 604) v = Wout[n * 600 + (k - 4)];
            g_Wout_h[j] = __float2half(v);
        }
    }
}

// ---------------- weight combine -> reordered Wc_h / c_r / bhn ----------------
#define CBJ 16
#define COMBINE_SMEM ((30000 + CBJ * 300) * 4)

__global__ void __launch_bounds__(256)
combine_kernel(const float* __restrict__ Wf, const float* __restrict__ bif,
               const float* __restrict__ bhf,
               const float* __restrict__ Wb, const float* __restrict__ bib,
               const float* __restrict__ bhb,
               const float* __restrict__ Wmean, const float* __restrict__ bmean)
{
    extern __shared__ float csm[];
    float* sW   = csm;
    float* srow = csm + 30000;

    const int j0 = blockIdx.x * CBJ;
    const int tid = threadIdx.x;

    for (int i = tid; i < 30000; i += 256) sW[i] = Wmean[i];
    for (int i = tid; i < CBJ * 300; i += 256) {
        const int jj = i / 300, dcol = i % 300;
        const int cnew = j0 + jj;
        const int d = (cnew >= 912);
        const int rem = cnew - d * 912;
        const int grp = rem / 24, gate = (rem % 24) >> 3, pos = rem & 7;
        const int h = grp * 8 + pos;
        float v = 0.f;
        if (h < 300) {
            const int src = gate * 300 + h;
            v = d ? Wb[src * 300 + dcol] : Wf[src * 300 + dcol];
        }
        srow[i] = v;
    }
    __syncthreads();

    for (int idx = tid; idx < CBJ * KN_PAD; idx += 256) {
        const int jj = idx / KN_PAD, k = idx % KN_PAD;
        const int cnew = j0 + jj;
        float s = 0.f;
        if (k < 100) {
            const float* wr = srow + jj * 300;
#pragma unroll 4
            for (int dd = 0; dd < 300; ++dd) s = fmaf(wr[dd], sW[dd * 100 + k], s);
        }
        g_Wc_h[(size_t)cnew * KN_PAD + k] = __float2half(s);
    }
    if (tid < CBJ) {
        const int cnew = j0 + tid;
        const int d = (cnew >= 912);
        const int rem = cnew - d * 912;
        const int grp = rem / 24, gate = (rem % 24) >> 3, pos = rem & 7;
        const int h = grp * 8 + pos;
        float s = 0.f;
        if (h < 300) {
            const int src = gate * 300 + h;
            const float* bih = d ? bib : bif;
            const float* bhh = d ? bhb : bhf;
            s = bih[src];
            const float* wr = srow + tid * 300;
            for (int dd = 0; dd < 300; ++dd) s = fmaf(wr[dd], bmean[dd], s);
            if (gate < 2) s += bhh[src];
            if (gate == 2) g_bhn[d * 304 + h] = bhh[600 + h];
        } else {
            if (gate == 2) g_bhn[d * 304 + h] = 0.f;
        }
        g_c_r[cnew] = s;
    }
}

// ---------------- per-triple averaged node vectors ----------------
__global__ void __launch_bounds__(224) tri_avg(const int* __restrict__ tri)
{
    const int r = threadIdx.x / 28, c = threadIdx.x % 28;
    const int bt = blockIdx.x * 8 + r;
    const int b = bt >> 9;
    const int hN = tri[bt * 3 + 0];
    const int tN = tri[bt * 3 + 2];
    const uint2 vh = ((const uint2*)(g_nodes_h + (size_t)(b * NNODE + hN) * KN_PAD))[c];
    const uint2 vt = ((const uint2*)(g_nodes_h + (size_t)(b * NNODE + tN) * KN_PAD))[c];
    const float2 hx = __half22float2(*(const __half2*)&vh.x);
    const float2 hy = __half22float2(*(const __half2*)&vh.y);
    const float2 tx = __half22float2(*(const __half2*)&vt.x);
    const float2 ty = __half22float2(*(const __half2*)&vt.y);
    __half2 o0 = __floats2half2_rn(0.5f * (hx.x + tx.x), 0.5f * (hx.y + tx.y));
    __half2 o1 = __floats2half2_rn(0.5f * (hy.x + ty.x), 0.5f * (hy.y + ty.y));
    uint2 o;
    o.x = *(uint32_t*)&o0;
    o.y = *(uint32_t*)&o1;
    ((uint2*)(g_T_h + (size_t)bt * KN_PAD))[c] = o;
}

// ---------------- rep = alpha @ hid_ ; layernorm ----------------
__global__ void __launch_bounds__(320) rep_ln_kernel(const float* __restrict__ gamma,
                                                     const float* __restrict__ beta,
                                                     float* __restrict__ out)
{
    const int b = blockIdx.x;
    __shared__ float sal[NT];
    __shared__ float red[2][10];
    const int tid = threadIdx.x;

    for (int t = tid; t < NT; t += 320)
        sal[t] = g_alpha4[(b * 4 + 0) * NT + t] + g_alpha4[(b * 4 + 1) * NT + t]
               + g_alpha4[(b * 4 + 2) * NT + t] + g_alpha4[(b * 4 + 3) * NT + t];
    __syncthreads();

    float acc = 0.f;
    const __half* H = g_hid_h + (size_t)b * NT * KH_PAD;
    if (tid < D_HID) {
        for (int t = 0; t < NT; ++t)
            acc = fmaf(sal[t], __half2float(H[(size_t)t * KH_PAD + tid]), acc);
    }
    float v1 = (tid < D_HID) ? acc : 0.f;
    float v2 = (tid < D_HID) ? acc * acc : 0.f;
#pragma unroll
    for (int o = 16; o; o >>= 1) {
        v1 += __shfl_xor_sync(0xffffffffu, v1, o);
        v2 += __shfl_xor_sync(0xffffffffu, v2, o);
    }
    const int wid = tid >> 5, lane = tid & 31;
    if (lane == 0) { red[0][wid] = v1; red[1][wid] = v2; }
    __syncthreads();
    if (tid == 0) {
        float s1 = 0.f, s2 = 0.f;
        for (int w = 0; w < 10; ++w) { s1 += red[0][w]; s2 += red[1][w]; }
        red[0][0] = s1 / (float)D_HID;
        red[1][0] = s2 / (float)D_HID;
    }
    __syncthreads();
    if (tid < D_HID) {
        float mu = red[0][0];
        float var = red[1][0] - mu * mu;
        out[b * D_HID + tid] = (acc - mu) * rsqrtf(var + 1e-5f) * gamma[tid] + beta[tid];
    }
}

__global__ void zero_tail_kernel(float* __restrict__ out, long start, long end)
{
    long i = start + (long)blockIdx.x * blockDim.x + threadIdx.x;
    if (i < end) out[i] = 0.f;
}

// ---------------- launch ----------------
extern "C" void kernel_launch(void* const* d_in, const int* in_sizes, int n_in,
                              void* d_out, int out_size)
{
    const int o = (in_sizes[3] == 1) ? 1 : 0;

    const float* nodes  = (const float*)d_in[0];
    const float* ctx    = (const float*)d_in[1];
    const int*   tri    = (const int*)d_in[2];
    const float* W_mean = (const float*)d_in[3 + o];
    const float* b_mean = (const float*)d_in[4 + o];
    const float* W_ih_f = (const float*)d_in[5 + o];
    const float* b_ih_f = (const float*)d_in[6 + o];
    const float* b_hh_f = (const float*)d_in[7 + o];
    const float* W_ih_b = (const float*)d_in[8 + o];
    const float* b_ih_b = (const float*)d_in[9 + o];
    const float* b_hh_b = (const float*)d_in[10 + o];
    const float* W_out  = (const float*)d_in[11 + o];
    const float* b_out  = (const float*)d_in[12 + o];
    const float* W_node = (const float*)d_in[13 + o];
    const float* b_node = (const float*)d_in[14 + o];
    const float* gamma  = (const float*)d_in[15 + o];
    const float* beta   = (const float*)d_in[16 + o];
    float* out = (float*)d_out;

    __half *pNodesH, *pWnodeH, *pWoutH, *pHiddenH, *pHidH;
    cudaGetSymbolAddress((void**)&pNodesH,  g_nodes_h);
    cudaGetSymbolAddress((void**)&pWnodeH,  g_Wnode_h);
    cudaGetSymbolAddress((void**)&pWoutH,   g_Wout_h);
    cudaGetSymbolAddress((void**)&pHiddenH, g_hidden_h);
    cudaGetSymbolAddress((void**)&pHidH,    g_hid_h);

    cudaFuncSetAttribute(combine_kernel, cudaFuncAttributeMaxDynamicSharedMemorySize, COMBINE_SMEM);
    cudaFuncSetAttribute(gemm_gates,     cudaFuncAttributeMaxDynamicSharedMemorySize, GATES_SMEM);
    cudaFuncSetAttribute(attn_kernel,    cudaFuncAttributeMaxDynamicSharedMemorySize, ATTN_SMEM);

    convert_all<<<8192, 256>>>(nodes, ctx, W_node, W_out);

    combine_kernel<<<NCOLS / CBJ, 256, COMBINE_SMEM>>>(
        W_ih_f, b_ih_f, b_hh_f, W_ih_b, b_ih_b, b_hh_b, W_mean, b_mean);

    tri_avg<<<ROWS_BT / 8, 224>>>(tri);

    gemm_gates<<<ROWS_BT / GBM, 256, GATES_SMEM>>>();

    // node_feature: cols 0-255 (TNW=8) + tail 256-303 (TNW=3)
    {
        dim3 grid(2, ROWS_BN / BM, 1);
        gemm_f16<false, 8><<<grid, 256>>>(pNodesH, 0, pWnodeH, 0, out + OUT_PATH, 0,
                                          ROWS_BN, D_HID, D_HID, KN_PAD, b_node, 0, 0);
        dim3 gridT(1, ROWS_BN / BM, 1);
        gemm_f16<false, 3><<<gridT, 256>>>(pNodesH, 0, pWnodeH, 0, out + OUT_PATH, 0,
                                           ROWS_BN, D_HID, D_HID, KN_PAD, b_node, 0, 256);
    }
    // hid_: cols 0-255 (TNW=8) + tail 256-303 (TNW=3)
    {
        dim3 grid(2, ROWS_BT / BM, 1);
        gemm_f16<true, 8><<<grid, 256>>>(pHiddenH, 0, pWoutH, 0, pHidH, 0,
                                         ROWS_BT, D_HID, KH_PAD, HPAD, b_out, 1, 0);
        dim3 gridT(1, ROWS_BT / BM, 1);
        gemm_f16<true, 3><<<gridT, 256>>>(pHiddenH, 0, pWoutH, 0, pHidH, 0,
                                          ROWS_BT, D_HID, KH_PAD, HPAD, b_out, 1, 256);
    }
    attn_kernel<<<dim3(NB, 4), 256, ATTN_SMEM>>>();

    rep_ln_kernel<<<NB, 320>>>(gamma, beta, out);

    {
        long start = OUT_TAIL_START;
        long end = (long)out_size;
        if (end > start) {
            long n = end - start;
            int blocks = (int)((n + 255) / 256);
            zero_tail_kernel<<<blocks, 256>>>(out, start, end);
        }
    }
}